// round 1
// baseline (speedup 1.0000x reference)
#include <cuda_runtime.h>
#include <math.h>

// Problem constants
#define B_   32
#define S_   512
#define D_   1024
#define NH_  16
#define E_   16
#define H_   256
#define DH_  64
#define T_   (B_ * S_)          // 16384

// ---------------- scratch (static device memory; no allocations) -----------
__device__ float g_h[(size_t)T_ * D_];              // LN output (h, later h3)
__device__ float g_qkv[(size_t)T_ * 3 * D_];        // qkv
__device__ float g_scores[(size_t)B_ * NH_ * S_ * S_]; // attention scores/probs
__device__ float g_ctx[(size_t)T_ * D_];            // attention context
__device__ float g_x[(size_t)T_ * D_];              // post-attention residual
__device__ float g_uw[(size_t)T_ * E_ * H_];        // gated expert activations
__device__ float g_gate[(size_t)T_ * E_];           // gate_dense

// ---------------- LayerNorm: one block per token, 256 threads --------------
__global__ void ln_kernel(const float* __restrict__ x, const float* __restrict__ g,
                          const float* __restrict__ b, float* __restrict__ y) {
    long t = blockIdx.x;
    const float* row = x + t * D_;
    float* out = y + t * D_;
    int tid = threadIdx.x;
    float v[4];
    float s = 0.f, sq = 0.f;
#pragma unroll
    for (int i = 0; i < 4; i++) {
        v[i] = row[tid + i * 256];
        s += v[i];
        sq += v[i] * v[i];
    }
#pragma unroll
    for (int o = 16; o; o >>= 1) {
        s  += __shfl_xor_sync(0xffffffffu, s, o);
        sq += __shfl_xor_sync(0xffffffffu, sq, o);
    }
    __shared__ float ws[8], wq[8];
    int w = tid >> 5, l = tid & 31;
    if (l == 0) { ws[w] = s; wq[w] = sq; }
    __syncthreads();
    if (tid == 0) {
        float a = 0.f, c = 0.f;
        for (int i = 0; i < 8; i++) { a += ws[i]; c += wq[i]; }
        ws[0] = a; wq[0] = c;
    }
    __syncthreads();
    float mean = ws[0] * (1.f / D_);
    float var  = wq[0] * (1.f / D_) - mean * mean;
    float inv  = rsqrtf(var + 1e-5f);
#pragma unroll
    for (int i = 0; i < 4; i++) {
        int d = tid + i * 256;
        out[d] = (v[i] - mean) * inv * g[d] + b[d];
    }
}

// ---------------- row softmax over 512 elements ----------------------------
__global__ void softmax512_kernel(float* __restrict__ sc) {
    long r = blockIdx.x;
    float* p = sc + r * 512;
    int tid = threadIdx.x;
    float a = p[tid], b = p[tid + 256];
    float m = fmaxf(a, b);
#pragma unroll
    for (int o = 16; o; o >>= 1) m = fmaxf(m, __shfl_xor_sync(0xffffffffu, m, o));
    __shared__ float sm[8], ss[8];
    int w = tid >> 5, l = tid & 31;
    if (l == 0) sm[w] = m;
    __syncthreads();
    if (tid == 0) {
        float x = sm[0];
        for (int i = 1; i < 8; i++) x = fmaxf(x, sm[i]);
        sm[0] = x;
    }
    __syncthreads();
    m = sm[0];
    a = expf(a - m); b = expf(b - m);
    float sum = a + b;
#pragma unroll
    for (int o = 16; o; o >>= 1) sum += __shfl_xor_sync(0xffffffffu, sum, o);
    if (l == 0) ss[w] = sum;
    __syncthreads();
    if (tid == 0) {
        float x = 0.f;
        for (int i = 0; i < 8; i++) x += ss[i];
        ss[0] = x;
    }
    __syncthreads();
    float inv = 1.f / ss[0];
    p[tid] = a * inv;
    p[tid + 256] = b * inv;
}

// ---------------- generic batched SGEMM 128x128x8, 8x8 per thread ----------
// C = epilogue(alpha * A @ op(B)); batch index z decomposed as (zo, zi).
template <bool TB, bool BI, bool GE, bool GA, bool RE>
__global__ void __launch_bounds__(256) gemm_k(
    const float* __restrict__ A, const float* __restrict__ B,
    float* __restrict__ C, const float* __restrict__ bias,
    const float* __restrict__ gate, const float* __restrict__ resid,
    int M, int N, int Kd, int lda, int ldb, int ldc,
    long sAo, long sAi, long sBo, long sBi, long sCo, long sCi,
    int nInner, long sBias, long sGate, int gateStride, float alpha) {
    int zo = blockIdx.z / nInner, zi = blockIdx.z - zo * nInner;
    A += (long)zo * sAo + (long)zi * sAi;
    B += (long)zo * sBo + (long)zi * sBi;
    long coff = (long)zo * sCo + (long)zi * sCi;

    __shared__ __align__(16) float As[8][128];
    __shared__ __align__(16) float Bs[8][128];
    int bm = blockIdx.y * 128, bn = blockIdx.x * 128;
    int tid = threadIdx.x;
    int rowg = (tid >> 4) << 3;
    int colg = (tid & 15) << 3;
    float acc[8][8];
#pragma unroll
    for (int i = 0; i < 8; i++)
#pragma unroll
        for (int j = 0; j < 8; j++) acc[i][j] = 0.f;

    for (int k0 = 0; k0 < Kd; k0 += 8) {
#pragma unroll
        for (int i = 0; i < 4; i++) {
            int idx = tid + i * 256;
            int m = idx >> 3, k = idx & 7;
            float v = 0.f;
            if (bm + m < M && k0 + k < Kd) v = A[(long)(bm + m) * lda + (k0 + k)];
            As[k][m] = v;
        }
#pragma unroll
        for (int i = 0; i < 4; i++) {
            int idx = tid + i * 256;
            float v = 0.f;
            if (TB) {
                int n = idx >> 3, k = idx & 7;
                if (bn + n < N && k0 + k < Kd) v = B[(long)(bn + n) * ldb + (k0 + k)];
                Bs[k][n] = v;
            } else {
                int k = idx >> 7, n = idx & 127;
                if (k0 + k < Kd && bn + n < N) v = B[(long)(k0 + k) * ldb + (bn + n)];
                Bs[k][n] = v;
            }
        }
        __syncthreads();
#pragma unroll
        for (int k = 0; k < 8; k++) {
            float4 a0 = *(const float4*)&As[k][rowg];
            float4 a1 = *(const float4*)&As[k][rowg + 4];
            float4 b0 = *(const float4*)&Bs[k][colg];
            float4 b1 = *(const float4*)&Bs[k][colg + 4];
            float ra[8] = {a0.x, a0.y, a0.z, a0.w, a1.x, a1.y, a1.z, a1.w};
            float rb[8] = {b0.x, b0.y, b0.z, b0.w, b1.x, b1.y, b1.z, b1.w};
#pragma unroll
            for (int i = 0; i < 8; i++)
#pragma unroll
                for (int j = 0; j < 8; j++) acc[i][j] += ra[i] * rb[j];
        }
        __syncthreads();
    }

    const float* biasp  = BI ? bias  + (long)blockIdx.z * sBias : nullptr;
    const float* gatep  = GA ? gate  + (long)blockIdx.z * sGate : nullptr;
    const float* residp = RE ? resid + coff : nullptr;
    float* Cp = C + coff;
#pragma unroll
    for (int i = 0; i < 8; i++) {
        int m = bm + rowg + i;
        if (m < M) {
            float gv = GA ? gatep[(long)m * gateStride] : 0.f;
#pragma unroll
            for (int j = 0; j < 8; j++) {
                int n = bn + colg + j;
                if (n < N) {
                    float v = acc[i][j] * alpha;
                    if (BI) v += biasp[n];
                    if (GE) v = 0.5f * v * (1.f + erff(v * 0.70710678118654752f));
                    if (GA) v *= gv;
                    if (RE) v += residp[(long)m * ldc + n];
                    Cp[(long)m * ldc + n] = v;
                }
            }
        }
    }
}

// ---------------- gate: logits, softmax, probs, top-8 gates ----------------
__global__ void gate_kernel(const float* __restrict__ h3, const float* __restrict__ gate_w,
                            const int* __restrict__ task_id,
                            float* __restrict__ probs, float* __restrict__ gate_dense) {
    long t = blockIdx.x;
    const float* gw = gate_w + (long)(*task_id) * (D_ * E_);
    const float* row = h3 + t * D_;
    int tid = threadIdx.x;
    float acc[16];
#pragma unroll
    for (int e = 0; e < 16; e++) acc[e] = 0.f;
    for (int d = tid; d < D_; d += 128) {
        float hv = row[d];
        const float* g = gw + (long)d * 16;
#pragma unroll
        for (int e = 0; e < 16; e++) acc[e] += hv * g[e];
    }
    __shared__ float red[128][17];
#pragma unroll
    for (int e = 0; e < 16; e++) red[tid][e] = acc[e];
    __syncthreads();
    for (int s = 64; s; s >>= 1) {
        if (tid < s) {
#pragma unroll
            for (int e = 0; e < 16; e++) red[tid][e] += red[tid + s][e];
        }
        __syncthreads();
    }
    if (tid == 0) {
        float lg[16], mx = -1e30f;
#pragma unroll
        for (int e = 0; e < 16; e++) { lg[e] = red[0][e]; mx = fmaxf(mx, lg[e]); }
        float sum = 0.f;
#pragma unroll
        for (int e = 0; e < 16; e++) { lg[e] = expf(lg[e] - mx); sum += lg[e]; }
        float inv = 1.f / sum;
        float p[16];
#pragma unroll
        for (int e = 0; e < 16; e++) { p[e] = lg[e] * inv; probs[t * 16 + e] = p[e]; }
        // top-8 (ties -> earliest index, matching lax.top_k)
        bool used[16];
#pragma unroll
        for (int e = 0; e < 16; e++) used[e] = false;
        int   tidx[8];
        float tval[8];
        float gsum = 0.f;
        for (int kk = 0; kk < 8; kk++) {
            float best = -1.f; int bi = 0;
            for (int e = 0; e < 16; e++)
                if (!used[e] && p[e] > best) { best = p[e]; bi = e; }
            used[bi] = true; tidx[kk] = bi; tval[kk] = best; gsum += best;
        }
        float ginv = 1.f / (gsum + 1e-6f);
        float gd[16];
#pragma unroll
        for (int e = 0; e < 16; e++) gd[e] = 0.f;
        for (int kk = 0; kk < 8; kk++) gd[tidx[kk]] = tval[kk] * ginv;
#pragma unroll
        for (int e = 0; e < 16; e++) gate_dense[t * 16 + e] = gd[e];
    }
}

// ---------------- aux loss (deterministic single-block reduction) ----------
__global__ void aux_kernel(const float* __restrict__ probs, float* __restrict__ outv) {
    int tid = threadIdx.x;
    float acc[16];
#pragma unroll
    for (int e = 0; e < 16; e++) acc[e] = 0.f;
    for (int t = tid; t < T_; t += 256) {
        const float* p = probs + (long)t * 16;
#pragma unroll
        for (int e = 0; e < 16; e++) acc[e] += p[e];
    }
    __shared__ float red[256][17];
#pragma unroll
    for (int e = 0; e < 16; e++) red[tid][e] = acc[e];
    __syncthreads();
    for (int s = 128; s; s >>= 1) {
        if (tid < s) {
#pragma unroll
            for (int e = 0; e < 16; e++) red[tid][e] += red[tid + s][e];
        }
        __syncthreads();
    }
    if (tid == 0) {
        float aux = 0.f;
#pragma unroll
        for (int e = 0; e < 16; e++) {
            float mp = red[0][e] * (1.f / T_);
            aux += mp * logf(mp + 1e-6f);
        }
        outv[0] = 5e-4f * aux;
    }
}

// ---------------- + gate_dense @ b2 ---------------------------------------
__global__ void b2add_kernel(const float* __restrict__ gd, const float* __restrict__ b2,
                             float* __restrict__ xo) {
    long t = blockIdx.x;
    __shared__ float g[16];
    if (threadIdx.x < 16) g[threadIdx.x] = gd[t * 16 + threadIdx.x];
    __syncthreads();
    float* row = xo + t * D_;
    for (int d = threadIdx.x; d < D_; d += 256) {
        float s = 0.f;
#pragma unroll
        for (int e = 0; e < 16; e++) s += g[e] * b2[(long)e * D_ + d];
        row[d] += s;
    }
}

// ---------------- launch ----------------------------------------------------
extern "C" void kernel_launch(void* const* d_in, const int* in_sizes, int n_in,
                              void* d_out, int out_size) {
    const float* tgt        = (const float*)d_in[0];
    const float* ln1_g      = (const float*)d_in[2];
    const float* ln1_b      = (const float*)d_in[3];
    const float* ln3_g      = (const float*)d_in[4];
    const float* ln3_b      = (const float*)d_in[5];
    const float* in_proj_w  = (const float*)d_in[6];
    const float* in_proj_b  = (const float*)d_in[7];
    const float* out_proj_w = (const float*)d_in[8];
    const float* out_proj_b = (const float*)d_in[9];
    const float* gate_w     = (const float*)d_in[10];
    const float* w1         = (const float*)d_in[11];
    const float* b1         = (const float*)d_in[12];
    const float* w2         = (const float*)d_in[13];
    const float* b2         = (const float*)d_in[14];
    const int*   task_id    = (const int*)d_in[15];

    float* out       = (float*)d_out;
    float* out_x     = out;                          // [B,S,D]
    float* out_aux   = out + (size_t)T_ * D_;        // scalar
    float* out_probs = out_aux + 1;                  // [B,S,E]

    float *h, *qkv, *sc, *ctx, *x, *uw, *gd;
    cudaGetSymbolAddress((void**)&h,   g_h);
    cudaGetSymbolAddress((void**)&qkv, g_qkv);
    cudaGetSymbolAddress((void**)&sc,  g_scores);
    cudaGetSymbolAddress((void**)&ctx, g_ctx);
    cudaGetSymbolAddress((void**)&x,   g_x);
    cudaGetSymbolAddress((void**)&uw,  g_uw);
    cudaGetSymbolAddress((void**)&gd,  g_gate);

    // 1. h = LN1(tgt)
    ln_kernel<<<T_, 256>>>(tgt, ln1_g, ln1_b, h);

    // 2. qkv = h @ in_proj_w^T + in_proj_b    [16384 x 3072 x 1024]
    gemm_k<true, true, false, false, false><<<dim3(24, 128, 1), 256>>>(
        h, in_proj_w, qkv, in_proj_b, nullptr, nullptr,
        T_, 3 * D_, D_, D_, D_, 3 * D_,
        0, 0, 0, 0, 0, 0, 1, 0, 0, 0, 1.f);

    // 3. scores = (q @ k^T) / 8  — batched over (b,h), z = b*16+h
    gemm_k<true, false, false, false, false><<<dim3(4, 4, B_ * NH_), 256>>>(
        qkv, qkv + D_, sc, nullptr, nullptr, nullptr,
        S_, S_, DH_, 3 * D_, 3 * D_, S_,
        (long)S_ * 3 * D_, DH_, (long)S_ * 3 * D_, DH_,
        (long)NH_ * S_ * S_, (long)S_ * S_,
        NH_, 0, 0, 0, 0.125f);

    // 4. softmax over keys
    softmax512_kernel<<<(unsigned)((long)B_ * NH_ * S_), 256>>>(sc);

    // 5. ctx = attn @ v  — batched, written back interleaved [T, D]
    gemm_k<false, false, false, false, false><<<dim3(1, 4, B_ * NH_), 256>>>(
        sc, qkv + 2 * D_, ctx, nullptr, nullptr, nullptr,
        S_, DH_, S_, S_, 3 * D_, D_,
        (long)NH_ * S_ * S_, (long)S_ * S_, (long)S_ * 3 * D_, DH_,
        (long)S_ * D_, DH_,
        NH_, 0, 0, 0, 1.f);

    // 6. x = tgt + ctx @ out_proj_w^T + out_proj_b
    gemm_k<true, true, false, false, true><<<dim3(8, 128, 1), 256>>>(
        ctx, out_proj_w, x, out_proj_b, nullptr, tgt,
        T_, D_, D_, D_, D_, D_,
        0, 0, 0, 0, 0, 0, 1, 0, 0, 0, 1.f);

    // 7. h3 = LN3(x)  (reuse g_h)
    ln_kernel<<<T_, 256>>>(x, ln3_g, ln3_b, h);

    // 8. gate: logits/softmax/top8 → probs (to d_out), gate_dense
    gate_kernel<<<T_, 128>>>(h, gate_w, task_id, out_probs, gd);

    // 9. aux loss scalar
    aux_kernel<<<1, 256>>>(out_probs, out_aux);

    // 10. uw[t, e*H+h'] = gelu(h3 @ w1[e] + b1[e]) * gate_dense[t,e]  (z = expert)
    gemm_k<false, true, true, true, false><<<dim3(2, 128, E_), 256>>>(
        h, w1, uw, b1, gd, nullptr,
        T_, H_, D_, D_, H_, E_ * H_,
        0, 0, (long)D_ * H_, 0, (long)H_, 0,
        1, (long)H_, 1, E_, 1.f);

    // 11. out_x = x + uw @ w2_flat   [16384 x 1024 x 4096]
    gemm_k<false, false, false, false, true><<<dim3(8, 128, 1), 256>>>(
        uw, w2, out_x, nullptr, nullptr, x,
        T_, D_, E_ * H_, E_ * H_, D_, D_,
        0, 0, 0, 0, 0, 0, 1, 0, 0, 0, 1.f);

    // 12. out_x += gate_dense @ b2
    b2add_kernel<<<T_, 256>>>(gd, b2, out_x);

    (void)in_sizes; (void)n_in; (void)out_size;
}

// round 2
// speedup vs baseline: 3.0082x; 3.0082x over previous
#include <cuda_runtime.h>
#include <math.h>

// Problem constants
#define B_   32
#define S_   512
#define D_   1024
#define NH_  16
#define E_   16
#define H_   256
#define DH_  64
#define T_   (B_ * S_)          // 16384

// ---------------- scratch (static device memory; padded for unguarded vector reads)
__device__ float g_h[(size_t)T_ * D_ + 4096];
__device__ float g_qkv[(size_t)T_ * 3 * D_ + 4096];
__device__ float g_scores[(size_t)B_ * NH_ * S_ * S_ + 4096];
__device__ float g_ctx[(size_t)T_ * D_ + 4096];
__device__ float g_x[(size_t)T_ * D_ + 4096];
__device__ float g_uw[(size_t)T_ * E_ * H_ + 4096];
__device__ float g_gate[(size_t)T_ * E_];

__device__ __forceinline__ float f2tf(float x) {
    unsigned u;
    asm("cvt.rna.tf32.f32 %0, %1;" : "=r"(u) : "f"(x));
    return __uint_as_float(u);
}

__device__ __forceinline__ void mma8(float* d, const float* a, const float* b) {
    asm volatile(
        "mma.sync.aligned.m16n8k8.row.col.f32.tf32.tf32.f32 "
        "{%0,%1,%2,%3},{%4,%5,%6,%7},{%8,%9},{%0,%1,%2,%3};"
        : "+f"(d[0]), "+f"(d[1]), "+f"(d[2]), "+f"(d[3])
        : "r"(__float_as_uint(a[0])), "r"(__float_as_uint(a[1])),
          "r"(__float_as_uint(a[2])), "r"(__float_as_uint(a[3])),
          "r"(__float_as_uint(b[0])), "r"(__float_as_uint(b[1])));
}

// ---------------- LayerNorm: one block per token, 256 threads --------------
__global__ void ln_kernel(const float* __restrict__ x, const float* __restrict__ g,
                          const float* __restrict__ b, float* __restrict__ y) {
    long t = blockIdx.x;
    const float* row = x + t * D_;
    float* out = y + t * D_;
    int tid = threadIdx.x;
    float v[4];
    float s = 0.f, sq = 0.f;
#pragma unroll
    for (int i = 0; i < 4; i++) {
        v[i] = row[tid + i * 256];
        s += v[i];
        sq += v[i] * v[i];
    }
#pragma unroll
    for (int o = 16; o; o >>= 1) {
        s  += __shfl_xor_sync(0xffffffffu, s, o);
        sq += __shfl_xor_sync(0xffffffffu, sq, o);
    }
    __shared__ float ws[8], wq[8];
    int w = tid >> 5, l = tid & 31;
    if (l == 0) { ws[w] = s; wq[w] = sq; }
    __syncthreads();
    if (tid == 0) {
        float a = 0.f, c = 0.f;
        for (int i = 0; i < 8; i++) { a += ws[i]; c += wq[i]; }
        ws[0] = a; wq[0] = c;
    }
    __syncthreads();
    float mean = ws[0] * (1.f / D_);
    float var  = wq[0] * (1.f / D_) - mean * mean;
    float inv  = rsqrtf(var + 1e-5f);
#pragma unroll
    for (int i = 0; i < 4; i++) {
        int d = tid + i * 256;
        out[d] = (v[i] - mean) * inv * g[d] + b[d];
    }
}

// ---------------- row softmax over 512 elements ----------------------------
__global__ void softmax512_kernel(float* __restrict__ sc) {
    long r = blockIdx.x;
    float* p = sc + r * 512;
    int tid = threadIdx.x;
    float a = p[tid], b = p[tid + 256];
    float m = fmaxf(a, b);
#pragma unroll
    for (int o = 16; o; o >>= 1) m = fmaxf(m, __shfl_xor_sync(0xffffffffu, m, o));
    __shared__ float sm[8], ss[8];
    int w = tid >> 5, l = tid & 31;
    if (l == 0) sm[w] = m;
    __syncthreads();
    if (tid == 0) {
        float x = sm[0];
        for (int i = 1; i < 8; i++) x = fmaxf(x, sm[i]);
        sm[0] = x;
    }
    __syncthreads();
    m = sm[0];
    a = expf(a - m); b = expf(b - m);
    float sum = a + b;
#pragma unroll
    for (int o = 16; o; o >>= 1) sum += __shfl_xor_sync(0xffffffffu, sum, o);
    if (l == 0) ss[w] = sum;
    __syncthreads();
    if (tid == 0) {
        float x = 0.f;
        for (int i = 0; i < 8; i++) x += ss[i];
        ss[0] = x;
    }
    __syncthreads();
    float inv = 1.f / ss[0];
    p[tid] = a * inv;
    p[tid + 256] = b * inv;
}

// ---------------- TF32 tensor-core batched GEMM ----------------------------
// C = epilogue(alpha * A @ op(B)); 128x128 CTA tile, BK=16.
// 8 warps: 2 (m) x 4 (n), warp tile 64x32, mma m16n8k8.tf32.
// Requirements: M % 128 == 0, K % 16 == 0, input buffers padded so unguarded
// vector loads past N stay in-bounds. N guarded at epilogue only.
// smem layout: idx(k,m) = k*136 + (m ^ (((k>>2)&3)<<3))  -> conflict-free
// fragment loads, conflict-free B(non-TB) stores, A stores conflict-free too
// (per-thread constant xor; verified lane bank math).
template <bool TB, bool BI, bool GE, bool GA, bool RE>
__global__ void __launch_bounds__(256, 2) gemm_tc(
    const float* __restrict__ A, const float* __restrict__ Bm,
    float* __restrict__ C, const float* __restrict__ bias,
    const float* __restrict__ gate, const float* __restrict__ resid,
    int M, int N, int Kd, int lda, int ldb, int ldc,
    long sAo, long sAi, long sBo, long sBi, long sCo, long sCi,
    int nInner, long sBias, long sGate, int gateStride, float alpha) {
    int zo = blockIdx.z / nInner, zi = blockIdx.z - zo * nInner;
    A  += (long)zo * sAo + (long)zi * sAi;
    Bm += (long)zo * sBo + (long)zi * sBi;
    long coff = (long)zo * sCo + (long)zi * sCi;

    __shared__ __align__(16) float As[16 * 136];
    __shared__ __align__(16) float Bs[16 * 136];

    int bm = blockIdx.y * 128, bn = blockIdx.x * 128;
    int tid  = threadIdx.x;
    int lane = tid & 31, warp = tid >> 5;
    int wm = (warp & 1) * 64, wn = (warp >> 1) * 32;
    int gid = lane >> 2, tig = lane & 3;

    float acc[4][4][4];
#pragma unroll
    for (int mi = 0; mi < 4; mi++)
#pragma unroll
        for (int ni = 0; ni < 4; ni++)
#pragma unroll
            for (int r = 0; r < 4; r++) acc[mi][ni][r] = 0.f;

    // fill-slot precompute (2 slots per thread for each of A, B)
    float4 stA[2], stB[2];
    int aM[2], aKq[2];       // A (and B when TB): m/n row, k-quad
    int bK[2], bNq[2];       // B non-TB: k row, n-quad
#pragma unroll
    for (int j = 0; j < 2; j++) {
        int slot = tid + 256 * j;
        aM[j]  = slot >> 2;
        aKq[j] = slot & 3;
        bK[j]  = slot >> 5;
        bNq[j] = slot & 31;
    }

    // preload k0 = 0
#pragma unroll
    for (int j = 0; j < 2; j++) {
        stA[j] = *(const float4*)(A + (long)(bm + aM[j]) * lda + aKq[j] * 4);
        if (TB)
            stB[j] = *(const float4*)(Bm + (long)(bn + aM[j]) * ldb + aKq[j] * 4);
        else
            stB[j] = *(const float4*)(Bm + (long)bK[j] * ldb + bn + bNq[j] * 4);
    }

    for (int k0 = 0; k0 < Kd; k0 += 16) {
        // store staged tile to smem (convert to tf32 at fill time)
#pragma unroll
        for (int j = 0; j < 2; j++) {
            int base = aKq[j] * 4 * 136 + (aM[j] ^ (aKq[j] << 3));
            As[base]           = f2tf(stA[j].x);
            As[base + 136]     = f2tf(stA[j].y);
            As[base + 272]     = f2tf(stA[j].z);
            As[base + 408]     = f2tf(stA[j].w);
            if (TB) {
                Bs[base]           = f2tf(stB[j].x);
                Bs[base + 136]     = f2tf(stB[j].y);
                Bs[base + 272]     = f2tf(stB[j].z);
                Bs[base + 408]     = f2tf(stB[j].w);
            } else {
                int c = ((bK[j] >> 2) & 3) << 3;
                int idx = bK[j] * 136 + ((bNq[j] * 4) ^ c);
                float4 v;
                v.x = f2tf(stB[j].x); v.y = f2tf(stB[j].y);
                v.z = f2tf(stB[j].z); v.w = f2tf(stB[j].w);
                *(float4*)&Bs[idx] = v;
            }
        }
        __syncthreads();

        // prefetch next tile while computing
        if (k0 + 16 < Kd) {
            int kn = k0 + 16;
#pragma unroll
            for (int j = 0; j < 2; j++) {
                stA[j] = *(const float4*)(A + (long)(bm + aM[j]) * lda + kn + aKq[j] * 4);
                if (TB)
                    stB[j] = *(const float4*)(Bm + (long)(bn + aM[j]) * ldb + kn + aKq[j] * 4);
                else
                    stB[j] = *(const float4*)(Bm + (long)(kn + bK[j]) * ldb + bn + bNq[j] * 4);
            }
        }

#pragma unroll
        for (int s = 0; s < 2; s++) {
            int ka0 = 8 * s + tig;          // kq = 2s
            int ka2 = 8 * s + tig + 4;      // kq = 2s+1
            int ca0 = (2 * s) << 3;
            int ca2 = ((2 * s + 1) & 3) << 3;
            float a[4][4], b[4][2];
#pragma unroll
            for (int mi = 0; mi < 4; mi++) {
                int mb = wm + mi * 16;
                a[mi][0] = As[ka0 * 136 + ((mb + gid) ^ ca0)];
                a[mi][1] = As[ka0 * 136 + ((mb + 8 + gid) ^ ca0)];
                a[mi][2] = As[ka2 * 136 + ((mb + gid) ^ ca2)];
                a[mi][3] = As[ka2 * 136 + ((mb + 8 + gid) ^ ca2)];
            }
#pragma unroll
            for (int ni = 0; ni < 4; ni++) {
                int nb = wn + ni * 8;
                b[ni][0] = Bs[ka0 * 136 + ((nb + gid) ^ ca0)];
                b[ni][1] = Bs[ka2 * 136 + ((nb + gid) ^ ca2)];
            }
#pragma unroll
            for (int mi = 0; mi < 4; mi++)
#pragma unroll
                for (int ni = 0; ni < 4; ni++)
                    mma8(acc[mi][ni], a[mi], b[ni]);
        }
        __syncthreads();
    }

    // epilogue
    const float* biasp  = BI ? bias  + (long)blockIdx.z * sBias : nullptr;
    const float* gatep  = GA ? gate  + (long)blockIdx.z * sGate : nullptr;
    const float* residp = RE ? resid + coff : nullptr;
    float* Cp = C + coff;
#pragma unroll
    for (int mi = 0; mi < 4; mi++) {
#pragma unroll
        for (int rh = 0; rh < 2; rh++) {
            int m = bm + wm + mi * 16 + gid + rh * 8;
            float gv = GA ? gatep[(long)m * gateStride] : 0.f;
            float* crow = Cp + (long)m * ldc;
            const float* rrow = RE ? residp + (long)m * ldc : nullptr;
#pragma unroll
            for (int ni = 0; ni < 4; ni++) {
#pragma unroll
                for (int cc = 0; cc < 2; cc++) {
                    int n = bn + wn + ni * 8 + tig * 2 + cc;
                    if (n < N) {
                        float v = acc[mi][ni][rh * 2 + cc] * alpha;
                        if (BI) v += biasp[n];
                        if (GE) v = 0.5f * v * (1.f + erff(v * 0.70710678118654752f));
                        if (GA) v *= gv;
                        if (RE) v += rrow[n];
                        crow[n] = v;
                    }
                }
            }
        }
    }
}

// ---------------- gate: logits, softmax, probs, top-8 gates ----------------
__global__ void gate_kernel(const float* __restrict__ h3, const float* __restrict__ gate_w,
                            const int* __restrict__ task_id,
                            float* __restrict__ probs, float* __restrict__ gate_dense) {
    long t = blockIdx.x;
    const float* gw = gate_w + (long)(*task_id) * (D_ * E_);
    const float* row = h3 + t * D_;
    int tid = threadIdx.x;
    float acc[16];
#pragma unroll
    for (int e = 0; e < 16; e++) acc[e] = 0.f;
    for (int d = tid; d < D_; d += 128) {
        float hv = row[d];
        const float* g = gw + (long)d * 16;
#pragma unroll
        for (int e = 0; e < 16; e++) acc[e] += hv * g[e];
    }
    __shared__ float red[128][17];
#pragma unroll
    for (int e = 0; e < 16; e++) red[tid][e] = acc[e];
    __syncthreads();
    for (int s = 64; s; s >>= 1) {
        if (tid < s) {
#pragma unroll
            for (int e = 0; e < 16; e++) red[tid][e] += red[tid + s][e];
        }
        __syncthreads();
    }
    if (tid == 0) {
        float lg[16], mx = -1e30f;
#pragma unroll
        for (int e = 0; e < 16; e++) { lg[e] = red[0][e]; mx = fmaxf(mx, lg[e]); }
        float sum = 0.f;
#pragma unroll
        for (int e = 0; e < 16; e++) { lg[e] = expf(lg[e] - mx); sum += lg[e]; }
        float inv = 1.f / sum;
        float p[16];
#pragma unroll
        for (int e = 0; e < 16; e++) { p[e] = lg[e] * inv; probs[t * 16 + e] = p[e]; }
        bool used[16];
#pragma unroll
        for (int e = 0; e < 16; e++) used[e] = false;
        int   tidx[8];
        float tval[8];
        float gsum = 0.f;
        for (int kk = 0; kk < 8; kk++) {
            float best = -1.f; int bi = 0;
            for (int e = 0; e < 16; e++)
                if (!used[e] && p[e] > best) { best = p[e]; bi = e; }
            used[bi] = true; tidx[kk] = bi; tval[kk] = best; gsum += best;
        }
        float ginv = 1.f / (gsum + 1e-6f);
        float gd[16];
#pragma unroll
        for (int e = 0; e < 16; e++) gd[e] = 0.f;
        for (int kk = 0; kk < 8; kk++) gd[tidx[kk]] = tval[kk] * ginv;
#pragma unroll
        for (int e = 0; e < 16; e++) gate_dense[t * 16 + e] = gd[e];
    }
}

// ---------------- aux loss (deterministic single-block reduction) ----------
__global__ void aux_kernel(const float* __restrict__ probs, float* __restrict__ outv) {
    int tid = threadIdx.x;
    float acc[16];
#pragma unroll
    for (int e = 0; e < 16; e++) acc[e] = 0.f;
    for (int t = tid; t < T_; t += 256) {
        const float* p = probs + (long)t * 16;
#pragma unroll
        for (int e = 0; e < 16; e++) acc[e] += p[e];
    }
    __shared__ float red[256][17];
#pragma unroll
    for (int e = 0; e < 16; e++) red[tid][e] = acc[e];
    __syncthreads();
    for (int s = 128; s; s >>= 1) {
        if (tid < s) {
#pragma unroll
            for (int e = 0; e < 16; e++) red[tid][e] += red[tid + s][e];
        }
        __syncthreads();
    }
    if (tid == 0) {
        float aux = 0.f;
#pragma unroll
        for (int e = 0; e < 16; e++) {
            float mp = red[0][e] * (1.f / T_);
            aux += mp * logf(mp + 1e-6f);
        }
        outv[0] = 5e-4f * aux;
    }
}

// ---------------- + gate_dense @ b2 ---------------------------------------
__global__ void b2add_kernel(const float* __restrict__ gd, const float* __restrict__ b2,
                             float* __restrict__ xo) {
    long t = blockIdx.x;
    __shared__ float g[16];
    if (threadIdx.x < 16) g[threadIdx.x] = gd[t * 16 + threadIdx.x];
    __syncthreads();
    float* row = xo + t * D_;
    for (int d = threadIdx.x; d < D_; d += 256) {
        float s = 0.f;
#pragma unroll
        for (int e = 0; e < 16; e++) s += g[e] * b2[(long)e * D_ + d];
        row[d] += s;
    }
}

// ---------------- launch ----------------------------------------------------
extern "C" void kernel_launch(void* const* d_in, const int* in_sizes, int n_in,
                              void* d_out, int out_size) {
    const float* tgt        = (const float*)d_in[0];
    const float* ln1_g      = (const float*)d_in[2];
    const float* ln1_b      = (const float*)d_in[3];
    const float* ln3_g      = (const float*)d_in[4];
    const float* ln3_b      = (const float*)d_in[5];
    const float* in_proj_w  = (const float*)d_in[6];
    const float* in_proj_b  = (const float*)d_in[7];
    const float* out_proj_w = (const float*)d_in[8];
    const float* out_proj_b = (const float*)d_in[9];
    const float* gate_w     = (const float*)d_in[10];
    const float* w1         = (const float*)d_in[11];
    const float* b1         = (const float*)d_in[12];
    const float* w2         = (const float*)d_in[13];
    const float* b2         = (const float*)d_in[14];
    const int*   task_id    = (const int*)d_in[15];

    float* out       = (float*)d_out;
    float* out_x     = out;                          // [B,S,D]
    float* out_aux   = out + (size_t)T_ * D_;        // scalar
    float* out_probs = out_aux + 1;                  // [B,S,E]

    float *h, *qkv, *sc, *ctx, *x, *uw, *gd;
    cudaGetSymbolAddress((void**)&h,   g_h);
    cudaGetSymbolAddress((void**)&qkv, g_qkv);
    cudaGetSymbolAddress((void**)&sc,  g_scores);
    cudaGetSymbolAddress((void**)&ctx, g_ctx);
    cudaGetSymbolAddress((void**)&x,   g_x);
    cudaGetSymbolAddress((void**)&uw,  g_uw);
    cudaGetSymbolAddress((void**)&gd,  g_gate);

    // 1. h = LN1(tgt)
    ln_kernel<<<T_, 256>>>(tgt, ln1_g, ln1_b, h);

    // 2. qkv = h @ in_proj_w^T + in_proj_b    [16384 x 3072 x 1024]
    gemm_tc<true, true, false, false, false><<<dim3(24, 128, 1), 256>>>(
        h, in_proj_w, qkv, in_proj_b, nullptr, nullptr,
        T_, 3 * D_, D_, D_, D_, 3 * D_,
        0, 0, 0, 0, 0, 0, 1, 0, 0, 0, 1.f);

    // 3. scores = (q @ k^T) / 8  — batched over (b,h), z = b*16+h
    gemm_tc<true, false, false, false, false><<<dim3(4, 4, B_ * NH_), 256>>>(
        qkv, qkv + D_, sc, nullptr, nullptr, nullptr,
        S_, S_, DH_, 3 * D_, 3 * D_, S_,
        (long)S_ * 3 * D_, DH_, (long)S_ * 3 * D_, DH_,
        (long)NH_ * S_ * S_, (long)S_ * S_,
        NH_, 0, 0, 0, 0.125f);

    // 4. softmax over keys
    softmax512_kernel<<<(unsigned)((long)B_ * NH_ * S_), 256>>>(sc);

    // 5. ctx = attn @ v  — batched, written back interleaved [T, D]
    gemm_tc<false, false, false, false, false><<<dim3(1, 4, B_ * NH_), 256>>>(
        sc, qkv + 2 * D_, ctx, nullptr, nullptr, nullptr,
        S_, DH_, S_, S_, 3 * D_, D_,
        (long)NH_ * S_ * S_, (long)S_ * S_, (long)S_ * 3 * D_, DH_,
        (long)S_ * D_, DH_,
        NH_, 0, 0, 0, 1.f);

    // 6. x = tgt + ctx @ out_proj_w^T + out_proj_b
    gemm_tc<true, true, false, false, true><<<dim3(8, 128, 1), 256>>>(
        ctx, out_proj_w, x, out_proj_b, nullptr, tgt,
        T_, D_, D_, D_, D_, D_,
        0, 0, 0, 0, 0, 0, 1, 0, 0, 0, 1.f);

    // 7. h3 = LN3(x)  (reuse g_h)
    ln_kernel<<<T_, 256>>>(x, ln3_g, ln3_b, h);

    // 8. gate: logits/softmax/top8 → probs (to d_out), gate_dense
    gate_kernel<<<T_, 128>>>(h, gate_w, task_id, out_probs, gd);

    // 9. aux loss scalar
    aux_kernel<<<1, 256>>>(out_probs, out_aux);

    // 10. uw[t, e*H+h'] = gelu(h3 @ w1[e] + b1[e]) * gate_dense[t,e]  (z = expert)
    gemm_tc<false, true, true, true, false><<<dim3(2, 128, E_), 256>>>(
        h, w1, uw, b1, gd, nullptr,
        T_, H_, D_, D_, H_, E_ * H_,
        0, 0, (long)D_ * H_, 0, (long)H_, 0,
        1, (long)H_, 1, E_, 1.f);

    // 11. out_x = x + uw @ w2_flat   [16384 x 1024 x 4096]
    gemm_tc<false, false, false, false, true><<<dim3(8, 128, 1), 256>>>(
        uw, w2, out_x, nullptr, nullptr, x,
        T_, D_, E_ * H_, E_ * H_, D_, D_,
        0, 0, 0, 0, 0, 0, 1, 0, 0, 0, 1.f);

    // 12. out_x += gate_dense @ b2
    b2add_kernel<<<T_, 256>>>(gd, b2, out_x);

    (void)in_sizes; (void)n_in; (void)out_size;
}

// round 4
// speedup vs baseline: 5.6259x; 1.8702x over previous
#include <cuda_runtime.h>
#include <cuda_fp16.h>
#include <math.h>
#include <stdint.h>

#define B_   32
#define S_   512
#define D_   1024
#define NH_  16
#define E_   16
#define H_   256
#define DH_  64
#define T_   (B_ * S_)          // 16384

// ---------------- scratch (static device memory) ---------------------------
__device__ __half g_h16[(size_t)T_ * D_];
__device__ float  g_hf[(size_t)T_ * D_];
__device__ __half g_qkv16[(size_t)T_ * 3 * D_];
__device__ float  g_sc[(size_t)B_ * NH_ * S_ * S_];
__device__ __half g_p16[(size_t)B_ * NH_ * S_ * S_];
__device__ __half g_vt16[(size_t)B_ * NH_ * DH_ * S_];
__device__ __half g_ctx16[(size_t)T_ * D_];
__device__ float  g_x[(size_t)T_ * D_];
__device__ __half g_uw16[(size_t)T_ * E_ * H_];
__device__ float  g_gate[(size_t)T_ * E_];
__device__ __half g_wi16[(size_t)3 * D_ * D_];
__device__ __half g_wo16[(size_t)D_ * D_];
__device__ __half g_w1t16[(size_t)E_ * H_ * D_];
__device__ __half g_w2t16[(size_t)D_ * E_ * H_];

// ---------------- helpers ---------------------------------------------------
__device__ __forceinline__ uint32_t smem_u32(const void* p) {
    uint32_t a;
    asm("{ .reg .u64 t; cvta.to.shared.u64 t, %1; cvt.u32.u64 %0, t; }" : "=r"(a) : "l"(p));
    return a;
}
#define CP_ASYNC16(dst, src) \
    asm volatile("cp.async.ca.shared.global [%0], [%1], 16;" :: "r"(dst), "l"(src) : "memory")
#define CP_COMMIT() asm volatile("cp.async.commit_group;" ::: "memory")
#define CP_WAIT1()  asm volatile("cp.async.wait_group 1;" ::: "memory")
#define CP_WAIT0()  asm volatile("cp.async.wait_group 0;" ::: "memory")

#define LDSM_X4(r0, r1, r2, r3, addr) \
    asm volatile("ldmatrix.sync.aligned.m8n8.x4.shared.b16 {%0,%1,%2,%3}, [%4];" \
        : "=r"(r0), "=r"(r1), "=r"(r2), "=r"(r3) : "r"(addr))

__device__ __forceinline__ void mma16(float* d, const uint32_t* a, const uint32_t* b) {
    asm volatile(
        "mma.sync.aligned.m16n8k16.row.col.f32.f16.f16.f32 "
        "{%0,%1,%2,%3},{%4,%5,%6,%7},{%8,%9},{%0,%1,%2,%3};"
        : "+f"(d[0]), "+f"(d[1]), "+f"(d[2]), "+f"(d[3])
        : "r"(a[0]), "r"(a[1]), "r"(a[2]), "r"(a[3]), "r"(b[0]), "r"(b[1]));
}

// smem tile byte offset for row m, 16B-chunk c (row = 32 halfs = 64B)
__device__ __forceinline__ uint32_t swoff(int m, int c) {
    return (uint32_t)(m * 64 + ((c ^ ((m >> 1) & 3)) << 4));
}

// ---------------- LayerNorm (fp32 in -> half + fp32 out) --------------------
__global__ void ln_kernel(const float* __restrict__ x, const float* __restrict__ g,
                          const float* __restrict__ b, __half* __restrict__ y16,
                          float* __restrict__ yf) {
    long t = blockIdx.x;
    const float* row = x + t * D_;
    int tid = threadIdx.x;
    float v[4];
    float s = 0.f, sq = 0.f;
#pragma unroll
    for (int i = 0; i < 4; i++) {
        v[i] = row[tid + i * 256];
        s += v[i]; sq += v[i] * v[i];
    }
#pragma unroll
    for (int o = 16; o; o >>= 1) {
        s  += __shfl_xor_sync(0xffffffffu, s, o);
        sq += __shfl_xor_sync(0xffffffffu, sq, o);
    }
    __shared__ float ws[8], wq[8];
    int w = tid >> 5, l = tid & 31;
    if (l == 0) { ws[w] = s; wq[w] = sq; }
    __syncthreads();
    if (tid == 0) {
        float a = 0.f, c = 0.f;
        for (int i = 0; i < 8; i++) { a += ws[i]; c += wq[i]; }
        ws[0] = a; wq[0] = c;
    }
    __syncthreads();
    float mean = ws[0] * (1.f / D_);
    float var  = wq[0] * (1.f / D_) - mean * mean;
    float inv  = rsqrtf(var + 1e-5f);
#pragma unroll
    for (int i = 0; i < 4; i++) {
        int d = tid + i * 256;
        float o = (v[i] - mean) * inv * g[d] + b[d];
        y16[t * D_ + d] = __float2half(o);
        yf[t * D_ + d] = o;
    }
}

// ---------------- softmax: fp32 in, half out --------------------------------
__global__ void softmax512_k(const float* __restrict__ sc, __half* __restrict__ p16) {
    int half_ = threadIdx.x >> 7;
    int t = threadIdx.x & 127;
    long r = (long)blockIdx.x * 2 + half_;
    float4 v = *(const float4*)(sc + r * 512 + t * 4);
    float m = fmaxf(fmaxf(v.x, v.y), fmaxf(v.z, v.w));
#pragma unroll
    for (int o = 16; o; o >>= 1) m = fmaxf(m, __shfl_xor_sync(0xffffffffu, m, o));
    __shared__ float rm[2][4], rs[2][4];
    int w = t >> 5;
    if ((t & 31) == 0) rm[half_][w] = m;
    __syncthreads();
    m = fmaxf(fmaxf(rm[half_][0], rm[half_][1]), fmaxf(rm[half_][2], rm[half_][3]));
    v.x = expf(v.x - m); v.y = expf(v.y - m);
    v.z = expf(v.z - m); v.w = expf(v.w - m);
    float sum = v.x + v.y + v.z + v.w;
#pragma unroll
    for (int o = 16; o; o >>= 1) sum += __shfl_xor_sync(0xffffffffu, sum, o);
    if ((t & 31) == 0) rs[half_][w] = sum;
    __syncthreads();
    float inv = 1.f / (rs[half_][0] + rs[half_][1] + rs[half_][2] + rs[half_][3]);
    __half2 h0 = __floats2half2_rn(v.x * inv, v.y * inv);
    __half2 h1 = __floats2half2_rn(v.z * inv, v.w * inv);
    *(__half2*)(p16 + r * 512 + t * 4)     = h0;
    *(__half2*)(p16 + r * 512 + t * 4 + 2) = h1;
}

// ---------------- fp32 -> fp16 convert --------------------------------------
__global__ void conv_f2h(const float* __restrict__ in, __half* __restrict__ out, long n) {
    long i = (long)blockIdx.x * 1024 + threadIdx.x * 4;
    if (i < n) {
        float4 v = *(const float4*)(in + i);
        __half2 a = __floats2half2_rn(v.x, v.y);
        __half2 b = __floats2half2_rn(v.z, v.w);
        *(__half2*)(out + i) = a;
        *(__half2*)(out + i + 2) = b;
    }
}

// ---------------- batched tiled transpose -> half ---------------------------
template <typename TI>
__global__ void transpose_h(const TI* __restrict__ src, __half* __restrict__ dst,
                            int R, int C, long srcRS,
                            long sSo, long sSi, long sDo, long sDi, int nInner) {
    int zo = blockIdx.z / nInner, zi = blockIdx.z - zo * nInner;
    src += (long)zo * sSo + (long)zi * sSi;
    dst += (long)zo * sDo + (long)zi * sDi;
    __shared__ float tile[32][33];
    int r0 = blockIdx.y * 32, c0 = blockIdx.x * 32;
    int tx = threadIdx.x & 31, ty = threadIdx.x >> 5;
#pragma unroll
    for (int k = 0; k < 4; k++) {
        int r = r0 + ty + 8 * k;
        if (r < R && c0 + tx < C) tile[ty + 8 * k][tx] = (float)src[(long)r * srcRS + c0 + tx];
    }
    __syncthreads();
#pragma unroll
    for (int k = 0; k < 4; k++) {
        int c = c0 + ty + 8 * k;
        if (c < C && r0 + tx < R) dst[(long)c * R + r0 + tx] = __float2half(tile[tx][ty + 8 * k]);
    }
}

// ---------------- fp16 tensor-core GEMM, 128 x NT tile, BK=32 ---------------
// C = epilogue(alpha * A @ B^T); A:[M,K] half row-major, B:[N,K] half row-major.
// 512 threads. NT=256: warps 4m x 4n (32x64 warp tile). NT=64: 8m x 2n (16x32).
template <int NT, bool BI, bool GE, bool GA, bool RE, bool HOUT>
__global__ void __launch_bounds__(512) gemm_h(
    const __half* __restrict__ A, const __half* __restrict__ Bm, void* __restrict__ C,
    const float* __restrict__ bias, const float* __restrict__ gate,
    const float* __restrict__ resid,
    int Kd, int lda, int ldb, int ldc,
    long sAo, long sAi, long sBo, long sBi, long sCo, long sCi,
    int nInner, long sBias, long sGate, int gateStride, float alpha) {
    constexpr int WMG = (NT == 256) ? 4 : 8;   // warp groups along m
    constexpr int WNG = 16 / WMG;
    constexpr int WM  = 128 / WMG;             // 32 or 16
    constexpr int WN  = NT / WNG;              // 64 or 32
    constexpr int MI  = WM / 16;               // 2 or 1
    constexpr int NI  = WN / 8;                // 8 or 4

    __shared__ __align__(16) __half As[2][128 * 32];
    __shared__ __align__(16) __half Bs[2][NT * 32];

    int tid = threadIdx.x, lane = tid & 31, warp = tid >> 5;
    int zo = blockIdx.z / nInner, zi = blockIdx.z - zo * nInner;
    const __half* Ap = A + (long)zo * sAo + (long)zi * sAi;
    const __half* Bp = Bm + (long)zo * sBo + (long)zi * sBi;
    long coff = (long)zo * sCo + (long)zi * sCi;
    int bm = blockIdx.y * 128, bn = blockIdx.x * NT;
    int wm = (warp % WMG) * WM, wn = (warp / WMG) * WN;
    int g = lane >> 2, tq = lane & 3;

    uint32_t aB = smem_u32(As), bB = smem_u32(Bs);

    float acc[MI][NI][4];
#pragma unroll
    for (int mi = 0; mi < MI; mi++)
#pragma unroll
        for (int ni = 0; ni < NI; ni++)
#pragma unroll
            for (int r = 0; r < 4; r++) acc[mi][ni][r] = 0.f;

    // fill slots
    int ar = tid >> 2, ac = tid & 3;      // A: 512 slots
    int NC = Kd >> 5;

    // prologue: chunk 0
    {
        CP_ASYNC16(aB + swoff(ar, ac), Ap + (long)(bm + ar) * lda + ac * 8);
        if (NT == 256) {
#pragma unroll
            for (int j = 0; j < 2; j++) {
                int s = tid + 512 * j;
                int r = s >> 2, c = s & 3;
                CP_ASYNC16(bB + swoff(r, c), Bp + (long)(bn + r) * ldb + c * 8);
            }
        } else {
            if (tid < NT * 4) {
                int r = tid >> 2, c = tid & 3;
                CP_ASYNC16(bB + swoff(r, c), Bp + (long)(bn + r) * ldb + c * 8);
            }
        }
        CP_COMMIT();
    }

    for (int ck = 0; ck < NC; ck++) {
        int buf = ck & 1;
        if (ck + 1 < NC) {
            int k0 = (ck + 1) << 5;
            uint32_t ao = aB + (1 - buf) * (128 * 64);
            uint32_t bo = bB + (1 - buf) * (NT * 64);
            CP_ASYNC16(ao + swoff(ar, ac), Ap + (long)(bm + ar) * lda + k0 + ac * 8);
            if (NT == 256) {
#pragma unroll
                for (int j = 0; j < 2; j++) {
                    int s = tid + 512 * j;
                    int r = s >> 2, c = s & 3;
                    CP_ASYNC16(bo + swoff(r, c), Bp + (long)(bn + r) * ldb + k0 + c * 8);
                }
            } else {
                if (tid < NT * 4) {
                    int r = tid >> 2, c = tid & 3;
                    CP_ASYNC16(bo + swoff(r, c), Bp + (long)(bn + r) * ldb + k0 + c * 8);
                }
            }
            CP_COMMIT();
            CP_WAIT1();
        } else {
            CP_WAIT0();
        }
        __syncthreads();

        uint32_t aBase = aB + buf * (128 * 64);
        uint32_t bBase = bB + buf * (NT * 64);
#pragma unroll
        for (int s = 0; s < 2; s++) {
            uint32_t af[MI][4], bf[NI][2];
            int q = lane >> 3, r7 = lane & 7;
#pragma unroll
            for (int mi = 0; mi < MI; mi++) {
                int m = wm + mi * 16 + (q & 1) * 8 + r7;
                int c = 2 * s + (q >> 1);
                LDSM_X4(af[mi][0], af[mi][1], af[mi][2], af[mi][3], aBase + swoff(m, c));
            }
#pragma unroll
            for (int nj = 0; nj < NI / 2; nj++) {
                int n = wn + nj * 16 + (q >> 1) * 8 + r7;
                int c = 2 * s + (q & 1);
                LDSM_X4(bf[2 * nj][0], bf[2 * nj][1], bf[2 * nj + 1][0], bf[2 * nj + 1][1],
                        bBase + swoff(n, c));
            }
#pragma unroll
            for (int mi = 0; mi < MI; mi++)
#pragma unroll
                for (int ni = 0; ni < NI; ni++)
                    mma16(acc[mi][ni], af[mi], bf[ni]);
        }
        __syncthreads();
    }

    // epilogue
    const float* biasz = BI ? bias + (long)blockIdx.z * sBias : nullptr;
    const float* gatez = GA ? gate + (long)blockIdx.z * sGate : nullptr;
    __half* Ch = (__half*)C + coff;
    float*  Cf = (float*)C + coff;
    const float* Rz = RE ? resid + coff : nullptr;
#pragma unroll
    for (int mi = 0; mi < MI; mi++) {
#pragma unroll
        for (int rh = 0; rh < 2; rh++) {
            int row = bm + wm + mi * 16 + g + rh * 8;
            float gv = GA ? gatez[(long)row * gateStride] : 0.f;
#pragma unroll
            for (int ni = 0; ni < NI; ni++) {
                int n = bn + wn + ni * 8 + tq * 2;
                float v0 = acc[mi][ni][rh * 2]     * alpha;
                float v1 = acc[mi][ni][rh * 2 + 1] * alpha;
                if (BI) { v0 += biasz[n]; v1 += biasz[n + 1]; }
                if (GE) {
                    v0 = 0.5f * v0 * (1.f + erff(v0 * 0.70710678118654752f));
                    v1 = 0.5f * v1 * (1.f + erff(v1 * 0.70710678118654752f));
                }
                if (GA) { v0 *= gv; v1 *= gv; }
                if (HOUT) {
                    *(__half2*)(Ch + (long)row * ldc + n) = __floats2half2_rn(v0, v1);
                } else {
                    if (RE) {
                        float2 rv = *(const float2*)(Rz + (long)row * ldc + n);
                        v0 += rv.x; v1 += rv.y;
                    }
                    float2 ov; ov.x = v0; ov.y = v1;
                    *(float2*)(Cf + (long)row * ldc + n) = ov;
                }
            }
        }
    }
}

// ---------------- gate: logits, softmax, probs, top-8 gates ----------------
__global__ void gate_kernel(const float* __restrict__ h3, const float* __restrict__ gate_w,
                            const int* __restrict__ task_id,
                            float* __restrict__ probs, float* __restrict__ gate_dense) {
    long t = blockIdx.x;
    const float* gw = gate_w + (long)(*task_id) * (D_ * E_);
    const float* row = h3 + t * D_;
    int tid = threadIdx.x;
    float acc[16];
#pragma unroll
    for (int e = 0; e < 16; e++) acc[e] = 0.f;
    for (int d = tid; d < D_; d += 128) {
        float hv = row[d];
        const float* g = gw + (long)d * 16;
#pragma unroll
        for (int e = 0; e < 16; e++) acc[e] += hv * g[e];
    }
    __shared__ float red[128][17];
#pragma unroll
    for (int e = 0; e < 16; e++) red[tid][e] = acc[e];
    __syncthreads();
    for (int s = 64; s; s >>= 1) {
        if (tid < s) {
#pragma unroll
            for (int e = 0; e < 16; e++) red[tid][e] += red[tid + s][e];
        }
        __syncthreads();
    }
    if (tid == 0) {
        float lg[16], mx = -1e30f;
#pragma unroll
        for (int e = 0; e < 16; e++) { lg[e] = red[0][e]; mx = fmaxf(mx, lg[e]); }
        float sum = 0.f;
#pragma unroll
        for (int e = 0; e < 16; e++) { lg[e] = expf(lg[e] - mx); sum += lg[e]; }
        float inv = 1.f / sum;
        float p[16];
#pragma unroll
        for (int e = 0; e < 16; e++) { p[e] = lg[e] * inv; probs[t * 16 + e] = p[e]; }
        bool used[16];
#pragma unroll
        for (int e = 0; e < 16; e++) used[e] = false;
        int tidx[8]; float tval[8]; float gsum = 0.f;
        for (int kk = 0; kk < 8; kk++) {
            float best = -1.f; int bi = 0;
            for (int e = 0; e < 16; e++)
                if (!used[e] && p[e] > best) { best = p[e]; bi = e; }
            used[bi] = true; tidx[kk] = bi; tval[kk] = best; gsum += best;
        }
        float ginv = 1.f / (gsum + 1e-6f);
        float gd[16];
#pragma unroll
        for (int e = 0; e < 16; e++) gd[e] = 0.f;
        for (int kk = 0; kk < 8; kk++) gd[tidx[kk]] = tval[kk] * ginv;
#pragma unroll
        for (int e = 0; e < 16; e++) gate_dense[t * 16 + e] = gd[e];
    }
}

// ---------------- aux loss ---------------------------------------------------
__global__ void aux_kernel(const float* __restrict__ probs, float* __restrict__ outv) {
    int tid = threadIdx.x;
    float acc[16];
#pragma unroll
    for (int e = 0; e < 16; e++) acc[e] = 0.f;
    for (int t = tid; t < T_; t += 256) {
        const float* p = probs + (long)t * 16;
#pragma unroll
        for (int e = 0; e < 16; e++) acc[e] += p[e];
    }
    __shared__ float red[256][17];
#pragma unroll
    for (int e = 0; e < 16; e++) red[tid][e] = acc[e];
    __syncthreads();
    for (int s = 128; s; s >>= 1) {
        if (tid < s) {
#pragma unroll
            for (int e = 0; e < 16; e++) red[tid][e] += red[tid + s][e];
        }
        __syncthreads();
    }
    if (tid == 0) {
        float aux = 0.f;
#pragma unroll
        for (int e = 0; e < 16; e++) {
            float mp = red[0][e] * (1.f / T_);
            aux += mp * logf(mp + 1e-6f);
        }
        outv[0] = 5e-4f * aux;
    }
}

// ---------------- + gate_dense @ b2 -----------------------------------------
__global__ void b2add_kernel(const float* __restrict__ gd, const float* __restrict__ b2,
                             float* __restrict__ xo) {
    long t = blockIdx.x;
    __shared__ float g[16];
    if (threadIdx.x < 16) g[threadIdx.x] = gd[t * 16 + threadIdx.x];
    __syncthreads();
    float* row = xo + t * D_;
    for (int d = threadIdx.x; d < D_; d += 256) {
        float s = 0.f;
#pragma unroll
        for (int e = 0; e < 16; e++) s += g[e] * b2[(long)e * D_ + d];
        row[d] += s;
    }
}

// ---------------- launch -----------------------------------------------------
extern "C" void kernel_launch(void* const* d_in, const int* in_sizes, int n_in,
                              void* d_out, int out_size) {
    const float* tgt        = (const float*)d_in[0];
    const float* ln1_g      = (const float*)d_in[2];
    const float* ln1_b      = (const float*)d_in[3];
    const float* ln3_g      = (const float*)d_in[4];
    const float* ln3_b      = (const float*)d_in[5];
    const float* in_proj_w  = (const float*)d_in[6];
    const float* in_proj_b  = (const float*)d_in[7];
    const float* out_proj_w = (const float*)d_in[8];
    const float* out_proj_b = (const float*)d_in[9];
    const float* gate_w     = (const float*)d_in[10];
    const float* w1         = (const float*)d_in[11];
    const float* b1         = (const float*)d_in[12];
    const float* w2         = (const float*)d_in[13];
    const float* b2         = (const float*)d_in[14];
    const int*   task_id    = (const int*)d_in[15];

    float* out       = (float*)d_out;
    float* out_x     = out;
    float* out_aux   = out + (size_t)T_ * D_;
    float* out_probs = out_aux + 1;

    __half *h16, *qkv16, *p16, *vt16, *ctx16, *uw16, *wi16, *wo16, *w1t16, *w2t16;
    float *hf, *sc, *x, *gd;
    cudaGetSymbolAddress((void**)&h16,   g_h16);
    cudaGetSymbolAddress((void**)&hf,    g_hf);
    cudaGetSymbolAddress((void**)&qkv16, g_qkv16);
    cudaGetSymbolAddress((void**)&sc,    g_sc);
    cudaGetSymbolAddress((void**)&p16,   g_p16);
    cudaGetSymbolAddress((void**)&vt16,  g_vt16);
    cudaGetSymbolAddress((void**)&ctx16, g_ctx16);
    cudaGetSymbolAddress((void**)&x,     g_x);
    cudaGetSymbolAddress((void**)&uw16,  g_uw16);
    cudaGetSymbolAddress((void**)&gd,    g_gate);
    cudaGetSymbolAddress((void**)&wi16,  g_wi16);
    cudaGetSymbolAddress((void**)&wo16,  g_wo16);
    cudaGetSymbolAddress((void**)&w1t16, g_w1t16);
    cudaGetSymbolAddress((void**)&w2t16, g_w2t16);

    // 0. weight preprocessing (half conversions + transposes)
    conv_f2h<<<(unsigned)(3L * D_ * D_ / 1024), 256>>>(in_proj_w, wi16, 3L * D_ * D_);
    conv_f2h<<<(unsigned)(1L * D_ * D_ / 1024), 256>>>(out_proj_w, wo16, 1L * D_ * D_);
    transpose_h<float><<<dim3(8, 32, E_), 256>>>(
        w1, w1t16, D_, H_, H_, (long)D_ * H_, 0, (long)H_ * D_, 0, 1);
    transpose_h<float><<<dim3(32, 128, 1), 256>>>(
        w2, w2t16, E_ * H_, D_, D_, 0, 0, 0, 0, 1);

    // 1. h = LN1(tgt)
    ln_kernel<<<T_, 256>>>(tgt, ln1_g, ln1_b, h16, hf);

    // 2. qkv = h @ in_proj_w^T + b  (half out)
    gemm_h<256, true, false, false, false, true><<<dim3(12, 128, 1), 512>>>(
        h16, wi16, qkv16, in_proj_b, nullptr, nullptr,
        D_, D_, D_, 3 * D_,
        0, 0, 0, 0, 0, 0, 1, 0, 0, 0, 1.f);

    // 3. scores = (Q @ K^T) / 8  (fp32 out), z = b*NH+h
    gemm_h<256, false, false, false, false, false><<<dim3(2, 4, B_ * NH_), 512>>>(
        qkv16, qkv16 + D_, sc, nullptr, nullptr, nullptr,
        DH_, 3 * D_, 3 * D_, S_,
        (long)S_ * 3 * D_, DH_, (long)S_ * 3 * D_, DH_,
        (long)NH_ * S_ * S_, (long)S_ * S_,
        NH_, 0, 0, 0, 0.125f);

    // 4. softmax -> half probs
    softmax512_k<<<(unsigned)((long)B_ * NH_ * S_ / 2), 256>>>(sc, p16);

    // 5. Vt = V^T per (b,h): [512,64] -> [64,512]
    transpose_h<__half><<<dim3(2, 16, B_ * NH_), 256>>>(
        qkv16 + 2 * D_, vt16, S_, DH_, 3 * D_,
        (long)S_ * 3 * D_, DH_, (long)NH_ * DH_ * S_, (long)DH_ * S_, NH_);

    // 6. ctx = probs @ V (half out, interleaved [T,D])
    gemm_h<64, false, false, false, false, true><<<dim3(1, 4, B_ * NH_), 512>>>(
        p16, vt16, ctx16, nullptr, nullptr, nullptr,
        S_, S_, S_, D_,
        (long)NH_ * S_ * S_, (long)S_ * S_,
        (long)NH_ * DH_ * S_, (long)DH_ * S_,
        (long)S_ * D_, DH_,
        NH_, 0, 0, 0, 1.f);

    // 7. x = tgt + ctx @ out_proj_w^T + b  (fp32 out)
    gemm_h<256, true, false, false, true, false><<<dim3(4, 128, 1), 512>>>(
        ctx16, wo16, x, out_proj_b, nullptr, tgt,
        D_, D_, D_, D_,
        0, 0, 0, 0, 0, 0, 1, 0, 0, 0, 1.f);

    // 8. h3 = LN3(x) -> half + fp32
    ln_kernel<<<T_, 256>>>(x, ln3_g, ln3_b, h16, hf);

    // 9. gate / aux
    gate_kernel<<<T_, 128>>>(hf, gate_w, task_id, out_probs, gd);
    aux_kernel<<<1, 256>>>(out_probs, out_aux);

    // 10. uw = gelu(h3 @ w1 + b1) * gate  (half out), z = expert
    gemm_h<256, true, true, true, false, true><<<dim3(1, 128, E_), 512>>>(
        h16, w1t16, uw16, b1, gd, nullptr,
        D_, D_, D_, E_ * H_,
        0, 0, (long)H_ * D_, 0, (long)H_, 0,
        1, (long)H_, 1, E_, 1.f);

    // 11. out_x = x + uw @ w2  (fp32 out)
    gemm_h<256, false, false, false, true, false><<<dim3(4, 128, 1), 512>>>(
        uw16, w2t16, out_x, nullptr, nullptr, x,
        E_ * H_, E_ * H_, E_ * H_, D_,
        0, 0, 0, 0, 0, 0, 1, 0, 0, 0, 1.f);

    // 12. out_x += gate_dense @ b2
    b2add_kernel<<<T_, 256>>>(gd, b2, out_x);

    (void)in_sizes; (void)n_in; (void)out_size;
}

// round 6
// speedup vs baseline: 6.2913x; 1.1183x over previous
#include <cuda_runtime.h>
#include <cuda_fp16.h>
#include <math.h>
#include <stdint.h>

#define B_   32
#define S_   512
#define D_   1024
#define NH_  16
#define E_   16
#define H_   256
#define DH_  64
#define T_   (B_ * S_)          // 16384

// ---------------- scratch (static device memory) ---------------------------
__device__ __half g_h16[(size_t)T_ * D_];
__device__ __half g_qkv16[(size_t)T_ * 3 * D_];
__device__ __half g_vt16[(size_t)B_ * NH_ * DH_ * S_];
__device__ __half g_ctx16[(size_t)T_ * D_];
__device__ float  g_x[(size_t)T_ * D_];
__device__ __half g_uw16[(size_t)T_ * E_ * H_];
__device__ float  g_gate[(size_t)T_ * E_];
__device__ __half g_wi16[(size_t)3 * D_ * D_];
__device__ __half g_wo16[(size_t)D_ * D_];
__device__ __half g_w1t16[(size_t)E_ * H_ * D_];
__device__ __half g_w2t16[(size_t)D_ * E_ * H_];

// ---------------- helpers ---------------------------------------------------
__device__ __forceinline__ uint32_t smem_u32(const void* p) {
    uint32_t a;
    asm("{ .reg .u64 t; cvta.to.shared.u64 t, %1; cvt.u32.u64 %0, t; }" : "=r"(a) : "l"(p));
    return a;
}
__device__ __forceinline__ uint32_t h2_as_u32(__half2 h) {
    return *reinterpret_cast<uint32_t*>(&h);
}
#define CP_ASYNC16(dst, src) \
    asm volatile("cp.async.ca.shared.global [%0], [%1], 16;" :: "r"(dst), "l"(src) : "memory")
#define CP_COMMIT() asm volatile("cp.async.commit_group;" ::: "memory")
#define CP_WAIT1()  asm volatile("cp.async.wait_group 1;" ::: "memory")
#define CP_WAIT0()  asm volatile("cp.async.wait_group 0;" ::: "memory")

#define LDSM_X4(r0, r1, r2, r3, addr) \
    asm volatile("ldmatrix.sync.aligned.m8n8.x4.shared.b16 {%0,%1,%2,%3}, [%4];" \
        : "=r"(r0), "=r"(r1), "=r"(r2), "=r"(r3) : "r"(addr))

__device__ __forceinline__ void mma16(float* d, const uint32_t* a, const uint32_t* b) {
    asm volatile(
        "mma.sync.aligned.m16n8k16.row.col.f32.f16.f16.f32 "
        "{%0,%1,%2,%3},{%4,%5,%6,%7},{%8,%9},{%0,%1,%2,%3};"
        : "+f"(d[0]), "+f"(d[1]), "+f"(d[2]), "+f"(d[3])
        : "r"(a[0]), "r"(a[1]), "r"(a[2]), "r"(a[3]), "r"(b[0]), "r"(b[1]));
}

// GEMM smem tile: 32 halfs (64B) per row
__device__ __forceinline__ uint32_t swoff(int m, int c) {
    return (uint32_t)(m * 64 + ((c ^ ((m >> 1) & 3)) << 4));
}
// flash smem tile: 64 halfs (128B) per row, SW128
__device__ __forceinline__ uint32_t qoff(int m, int c) {
    return (uint32_t)(m * 128 + ((c ^ (m & 7)) << 4));
}

// ---------------- LayerNorm (fp32 in -> half out) ---------------------------
__global__ void ln_kernel(const float* __restrict__ x, const float* __restrict__ g,
                          const float* __restrict__ b, __half* __restrict__ y16) {
    long t = blockIdx.x;
    const float* row = x + t * D_;
    int tid = threadIdx.x;
    float v[4];
    float s = 0.f, sq = 0.f;
#pragma unroll
    for (int i = 0; i < 4; i++) {
        v[i] = row[tid + i * 256];
        s += v[i]; sq += v[i] * v[i];
    }
#pragma unroll
    for (int o = 16; o; o >>= 1) {
        s  += __shfl_xor_sync(0xffffffffu, s, o);
        sq += __shfl_xor_sync(0xffffffffu, sq, o);
    }
    __shared__ float ws[8], wq[8];
    int w = tid >> 5, l = tid & 31;
    if (l == 0) { ws[w] = s; wq[w] = sq; }
    __syncthreads();
    if (tid == 0) {
        float a = 0.f, c = 0.f;
        for (int i = 0; i < 8; i++) { a += ws[i]; c += wq[i]; }
        ws[0] = a; wq[0] = c;
    }
    __syncthreads();
    float mean = ws[0] * (1.f / D_);
    float var  = wq[0] * (1.f / D_) - mean * mean;
    float inv  = rsqrtf(var + 1e-5f);
#pragma unroll
    for (int i = 0; i < 4; i++) {
        int d = tid + i * 256;
        y16[t * D_ + d] = __float2half((v[i] - mean) * inv * g[d] + b[d]);
    }
}

// ---------------- fp32 -> fp16 convert --------------------------------------
__global__ void conv_f2h(const float* __restrict__ in, __half* __restrict__ out, long n) {
    long i = (long)blockIdx.x * 1024 + threadIdx.x * 4;
    if (i < n) {
        float4 v = *(const float4*)(in + i);
        *(__half2*)(out + i)     = __floats2half2_rn(v.x, v.y);
        *(__half2*)(out + i + 2) = __floats2half2_rn(v.z, v.w);
    }
}

// ---------------- batched tiled transpose -> half ---------------------------
template <typename TI>
__global__ void transpose_h(const TI* __restrict__ src, __half* __restrict__ dst,
                            int R, int C, long srcRS,
                            long sSo, long sSi, long sDo, long sDi, int nInner) {
    int zo = blockIdx.z / nInner, zi = blockIdx.z - zo * nInner;
    src += (long)zo * sSo + (long)zi * sSi;
    dst += (long)zo * sDo + (long)zi * sDi;
    __shared__ float tile[32][33];
    int r0 = blockIdx.y * 32, c0 = blockIdx.x * 32;
    int tx = threadIdx.x & 31, ty = threadIdx.x >> 5;
#pragma unroll
    for (int k = 0; k < 4; k++) {
        int r = r0 + ty + 8 * k;
        if (r < R && c0 + tx < C) tile[ty + 8 * k][tx] = (float)src[(long)r * srcRS + c0 + tx];
    }
    __syncthreads();
#pragma unroll
    for (int k = 0; k < 4; k++) {
        int c = c0 + ty + 8 * k;
        if (c < C && r0 + tx < R) dst[(long)c * R + r0 + tx] = __float2half(tile[tx][ty + 8 * k]);
    }
}

// ---------------- fused flash attention -------------------------------------
// grid (4 q-blocks, B*NH). 8 warps, each owns 16 q-rows. 64-key chunks, online
// softmax, O accumulated fp32, written half to ctx16 (interleaved [T, D]).
__global__ void __launch_bounds__(256) flash_k(
    const __half* __restrict__ qkv, const __half* __restrict__ vt,
    __half* __restrict__ ctx) {
    int bh = blockIdx.y;
    int b = bh >> 4, hh = bh & 15;
    int qb = blockIdx.x;
    const __half* Qb = qkv + ((long)b * S_ + qb * 128) * (3 * D_) + hh * DH_;
    const __half* Kb = qkv + (long)b * S_ * (3 * D_) + D_ + hh * DH_;
    const __half* Vb = vt + (long)bh * DH_ * S_;

    __shared__ __align__(16) __half Qs[128 * 64];
    __shared__ __align__(16) __half Ks[2][64 * 64];
    __shared__ __align__(16) __half Vs[2][64 * 64];
    uint32_t qB = smem_u32(Qs), kB = smem_u32(Ks), vB = smem_u32(Vs);

    int tid = threadIdx.x, lane = tid & 31, warp = tid >> 5;
    int wm = warp * 16;
    int g = lane >> 2, tq = lane & 3;
    int q2 = lane >> 3, r7 = lane & 7;
    const float L2E = 1.44269504088896f;

    // Q tile: 1024 slots of 16B
#pragma unroll
    for (int j = 0; j < 4; j++) {
        int s = tid + 256 * j;
        int r = s >> 3, cu = s & 7;
        CP_ASYNC16(qB + qoff(r, cu), Qb + (long)r * (3 * D_) + cu * 8);
    }
    CP_COMMIT();
    // KV chunk 0
#pragma unroll
    for (int j = 0; j < 2; j++) {
        int s = tid + 256 * j;
        int r = s >> 3, cu = s & 7;
        CP_ASYNC16(kB + qoff(r, cu), Kb + (long)r * (3 * D_) + cu * 8);
        CP_ASYNC16(vB + qoff(r, cu), Vb + (long)r * S_ + cu * 8);
    }
    CP_COMMIT();
    CP_WAIT0();
    __syncthreads();
    // scale Q by 1/8 (exact in fp16)
    {
        __half2 sc = __floats2half2_rn(0.125f, 0.125f);
        __half2* qh = (__half2*)Qs;
#pragma unroll
        for (int i = 0; i < 16; i++) qh[tid + 256 * i] = __hmul2(qh[tid + 256 * i], sc);
    }
    __syncthreads();

    float o[8][4];
#pragma unroll
    for (int ni = 0; ni < 8; ni++)
#pragma unroll
        for (int r = 0; r < 4; r++) o[ni][r] = 0.f;
    float m0 = -1e30f, m1 = -1e30f, l0 = 0.f, l1 = 0.f;

    for (int c = 0; c < 8; c++) {
        int buf = c & 1;
        if (c + 1 < 8) {
            int nb = 1 - buf;
#pragma unroll
            for (int j = 0; j < 2; j++) {
                int s = tid + 256 * j;
                int r = s >> 3, cu = s & 7;
                CP_ASYNC16(kB + nb * 8192 + qoff(r, cu),
                           Kb + (long)((c + 1) * 64 + r) * (3 * D_) + cu * 8);
                CP_ASYNC16(vB + nb * 8192 + qoff(r, cu),
                           Vb + (long)r * S_ + (c + 1) * 64 + cu * 8);
            }
            CP_COMMIT();
            CP_WAIT1();
        } else {
            CP_WAIT0();
        }
        __syncthreads();

        uint32_t kBuf = kB + buf * 8192, vBuf = vB + buf * 8192;
        // S = Qw @ Kc^T
        float sv[8][4];
#pragma unroll
        for (int ni = 0; ni < 8; ni++)
#pragma unroll
            for (int r = 0; r < 4; r++) sv[ni][r] = 0.f;
#pragma unroll
        for (int ks = 0; ks < 4; ks++) {
            uint32_t af[4], bf[8][2];
            int am = wm + (q2 & 1) * 8 + r7;
            LDSM_X4(af[0], af[1], af[2], af[3], qB + qoff(am, 2 * ks + (q2 >> 1)));
#pragma unroll
            for (int nj = 0; nj < 4; nj++) {
                int bn = nj * 16 + (q2 >> 1) * 8 + r7;
                LDSM_X4(bf[2 * nj][0], bf[2 * nj][1], bf[2 * nj + 1][0], bf[2 * nj + 1][1],
                        kBuf + qoff(bn, 2 * ks + (q2 & 1)));
            }
#pragma unroll
            for (int ni = 0; ni < 8; ni++) mma16(sv[ni], af, bf[ni]);
        }

        // online softmax update
        float cm0 = -1e30f, cm1 = -1e30f;
#pragma unroll
        for (int ni = 0; ni < 8; ni++) {
            cm0 = fmaxf(cm0, fmaxf(sv[ni][0], sv[ni][1]));
            cm1 = fmaxf(cm1, fmaxf(sv[ni][2], sv[ni][3]));
        }
        cm0 = fmaxf(cm0, __shfl_xor_sync(0xffffffffu, cm0, 1));
        cm0 = fmaxf(cm0, __shfl_xor_sync(0xffffffffu, cm0, 2));
        cm1 = fmaxf(cm1, __shfl_xor_sync(0xffffffffu, cm1, 1));
        cm1 = fmaxf(cm1, __shfl_xor_sync(0xffffffffu, cm1, 2));
        float mn0 = fmaxf(m0, cm0), mn1 = fmaxf(m1, cm1);
        float sc0 = exp2f((m0 - mn0) * L2E), sc1 = exp2f((m1 - mn1) * L2E);
        m0 = mn0; m1 = mn1;
        l0 *= sc0; l1 *= sc1;
#pragma unroll
        for (int ni = 0; ni < 8; ni++) {
            o[ni][0] *= sc0; o[ni][1] *= sc0;
            o[ni][2] *= sc1; o[ni][3] *= sc1;
        }
        uint32_t pa[4][4];
        float rs0 = 0.f, rs1 = 0.f;
#pragma unroll
        for (int ni = 0; ni < 8; ni++) {
            float p0 = exp2f((sv[ni][0] - mn0) * L2E);
            float p1 = exp2f((sv[ni][1] - mn0) * L2E);
            float p2 = exp2f((sv[ni][2] - mn1) * L2E);
            float p3 = exp2f((sv[ni][3] - mn1) * L2E);
            rs0 += p0 + p1; rs1 += p2 + p3;
            int kk = ni >> 1, hi = ni & 1;
            pa[kk][hi * 2]     = h2_as_u32(__floats2half2_rn(p0, p1));
            pa[kk][hi * 2 + 1] = h2_as_u32(__floats2half2_rn(p2, p3));
        }
        rs0 += __shfl_xor_sync(0xffffffffu, rs0, 1);
        rs0 += __shfl_xor_sync(0xffffffffu, rs0, 2);
        rs1 += __shfl_xor_sync(0xffffffffu, rs1, 1);
        rs1 += __shfl_xor_sync(0xffffffffu, rs1, 2);
        l0 += rs0; l1 += rs1;

        // O += P @ Vc
#pragma unroll
        for (int ks = 0; ks < 4; ks++) {
            uint32_t bf[8][2];
#pragma unroll
            for (int nj = 0; nj < 4; nj++) {
                int bn = nj * 16 + (q2 >> 1) * 8 + r7;
                LDSM_X4(bf[2 * nj][0], bf[2 * nj][1], bf[2 * nj + 1][0], bf[2 * nj + 1][1],
                        vBuf + qoff(bn, 2 * ks + (q2 & 1)));
            }
#pragma unroll
            for (int ni = 0; ni < 8; ni++) mma16(o[ni], pa[ks], bf[ni]);
        }
        __syncthreads();
    }

    float li0 = 1.f / l0, li1 = 1.f / l1;
    long row0 = (long)b * S_ + qb * 128 + wm + g;
    __half* c0p = ctx + (row0)     * D_ + hh * DH_;
    __half* c1p = ctx + (row0 + 8) * D_ + hh * DH_;
#pragma unroll
    for (int ni = 0; ni < 8; ni++) {
        int nc = ni * 8 + tq * 2;
        *(__half2*)(c0p + nc) = __floats2half2_rn(o[ni][0] * li0, o[ni][1] * li0);
        *(__half2*)(c1p + nc) = __floats2half2_rn(o[ni][2] * li1, o[ni][3] * li1);
    }
}

// ---------------- fp16 tensor-core GEMM, 128 x 256 tile, BK=32 --------------
template <bool BI, bool GE, bool GA, bool RE, bool HOUT>
__global__ void __launch_bounds__(512) gemm_h(
    const __half* __restrict__ A, const __half* __restrict__ Bm, void* __restrict__ C,
    const float* __restrict__ bias, const float* __restrict__ gate,
    const float* __restrict__ resid,
    int Kd, int lda, int ldb, int ldc,
    long sAo, long sAi, long sBo, long sBi, long sCo, long sCi,
    int nInner, long sBias, long sGate, int gateStride, float alpha) {
    constexpr int NT = 256;
    constexpr int MI = 2, NI = 8;

    __shared__ __align__(16) __half As[2][128 * 32];
    __shared__ __align__(16) __half Bs[2][NT * 32];

    int tid = threadIdx.x, lane = tid & 31, warp = tid >> 5;
    int zo = blockIdx.z / nInner, zi = blockIdx.z - zo * nInner;
    const __half* Ap = A + (long)zo * sAo + (long)zi * sAi;
    const __half* Bp = Bm + (long)zo * sBo + (long)zi * sBi;
    long coff = (long)zo * sCo + (long)zi * sCi;
    int bm = blockIdx.y * 128, bn = blockIdx.x * NT;
    int wm = (warp % 4) * 32, wn = (warp / 4) * 64;
    int g = lane >> 2, tq = lane & 3;

    uint32_t aB = smem_u32(As), bB = smem_u32(Bs);

    float acc[MI][NI][4];
#pragma unroll
    for (int mi = 0; mi < MI; mi++)
#pragma unroll
        for (int ni = 0; ni < NI; ni++)
#pragma unroll
            for (int r = 0; r < 4; r++) acc[mi][ni][r] = 0.f;

    int ar = tid >> 2, ac = tid & 3;
    int NC = Kd >> 5;

    {
        CP_ASYNC16(aB + swoff(ar, ac), Ap + (long)(bm + ar) * lda + ac * 8);
#pragma unroll
        for (int j = 0; j < 2; j++) {
            int s = tid + 512 * j;
            int r = s >> 2, c = s & 3;
            CP_ASYNC16(bB + swoff(r, c), Bp + (long)(bn + r) * ldb + c * 8);
        }
        CP_COMMIT();
    }

    for (int ck = 0; ck < NC; ck++) {
        int buf = ck & 1;
        if (ck + 1 < NC) {
            int k0 = (ck + 1) << 5;
            uint32_t ao = aB + (1 - buf) * (128 * 64);
            uint32_t bo = bB + (1 - buf) * (NT * 64);
            CP_ASYNC16(ao + swoff(ar, ac), Ap + (long)(bm + ar) * lda + k0 + ac * 8);
#pragma unroll
            for (int j = 0; j < 2; j++) {
                int s = tid + 512 * j;
                int r = s >> 2, c = s & 3;
                CP_ASYNC16(bo + swoff(r, c), Bp + (long)(bn + r) * ldb + k0 + c * 8);
            }
            CP_COMMIT();
            CP_WAIT1();
        } else {
            CP_WAIT0();
        }
        __syncthreads();

        uint32_t aBase = aB + buf * (128 * 64);
        uint32_t bBase = bB + buf * (NT * 64);
#pragma unroll
        for (int s = 0; s < 2; s++) {
            uint32_t af[MI][4], bf[NI][2];
            int q = lane >> 3, r7 = lane & 7;
#pragma unroll
            for (int mi = 0; mi < MI; mi++) {
                int m = wm + mi * 16 + (q & 1) * 8 + r7;
                LDSM_X4(af[mi][0], af[mi][1], af[mi][2], af[mi][3],
                        aBase + swoff(m, 2 * s + (q >> 1)));
            }
#pragma unroll
            for (int nj = 0; nj < NI / 2; nj++) {
                int n = wn + nj * 16 + (q >> 1) * 8 + r7;
                LDSM_X4(bf[2 * nj][0], bf[2 * nj][1], bf[2 * nj + 1][0], bf[2 * nj + 1][1],
                        bBase + swoff(n, 2 * s + (q & 1)));
            }
#pragma unroll
            for (int mi = 0; mi < MI; mi++)
#pragma unroll
                for (int ni = 0; ni < NI; ni++)
                    mma16(acc[mi][ni], af[mi], bf[ni]);
        }
        __syncthreads();
    }

    const float* biasz = BI ? bias + (long)blockIdx.z * sBias : nullptr;
    const float* gatez = GA ? gate + (long)blockIdx.z * sGate : nullptr;
    __half* Ch = (__half*)C + coff;
    float*  Cf = (float*)C + coff;
    const float* Rz = RE ? resid + coff : nullptr;
#pragma unroll
    for (int mi = 0; mi < MI; mi++) {
#pragma unroll
        for (int rh = 0; rh < 2; rh++) {
            int row = bm + wm + mi * 16 + g + rh * 8;
            float gv = GA ? gatez[(long)row * gateStride] : 0.f;
#pragma unroll
            for (int ni = 0; ni < NI; ni++) {
                int n = bn + wn + ni * 8 + tq * 2;
                float v0 = acc[mi][ni][rh * 2]     * alpha;
                float v1 = acc[mi][ni][rh * 2 + 1] * alpha;
                if (BI) { v0 += biasz[n]; v1 += biasz[n + 1]; }
                if (GE) {
                    v0 = 0.5f * v0 * (1.f + erff(v0 * 0.70710678118654752f));
                    v1 = 0.5f * v1 * (1.f + erff(v1 * 0.70710678118654752f));
                }
                if (GA) { v0 *= gv; v1 *= gv; }
                if (HOUT) {
                    *(__half2*)(Ch + (long)row * ldc + n) = __floats2half2_rn(v0, v1);
                } else {
                    if (RE) {
                        float2 rv = *(const float2*)(Rz + (long)row * ldc + n);
                        v0 += rv.x; v1 += rv.y;
                    }
                    float2 ov; ov.x = v0; ov.y = v1;
                    *(float2*)(Cf + (long)row * ldc + n) = ov;
                }
            }
        }
    }
}

// ---------------- gate: logits, softmax, probs, top-8 gates ----------------
__global__ void gate_kernel(const __half* __restrict__ h3, const float* __restrict__ gate_w,
                            const int* __restrict__ task_id,
                            float* __restrict__ probs, float* __restrict__ gate_dense) {
    long t = blockIdx.x;
    const float* gw = gate_w + (long)(*task_id) * (D_ * E_);
    const __half* row = h3 + t * D_;
    int tid = threadIdx.x;
    float acc[16];
#pragma unroll
    for (int e = 0; e < 16; e++) acc[e] = 0.f;
    for (int d = tid; d < D_; d += 128) {
        float hv = __half2float(row[d]);
        const float* g = gw + (long)d * 16;
#pragma unroll
        for (int e = 0; e < 16; e++) acc[e] += hv * g[e];
    }
    __shared__ float red[128][17];
#pragma unroll
    for (int e = 0; e < 16; e++) red[tid][e] = acc[e];
    __syncthreads();
    for (int s = 64; s; s >>= 1) {
        if (tid < s) {
#pragma unroll
            for (int e = 0; e < 16; e++) red[tid][e] += red[tid + s][e];
        }
        __syncthreads();
    }
    if (tid == 0) {
        float lg[16], mx = -1e30f;
#pragma unroll
        for (int e = 0; e < 16; e++) { lg[e] = red[0][e]; mx = fmaxf(mx, lg[e]); }
        float sum = 0.f;
#pragma unroll
        for (int e = 0; e < 16; e++) { lg[e] = expf(lg[e] - mx); sum += lg[e]; }
        float inv = 1.f / sum;
        float p[16];
#pragma unroll
        for (int e = 0; e < 16; e++) { p[e] = lg[e] * inv; probs[t * 16 + e] = p[e]; }
        bool used[16];
#pragma unroll
        for (int e = 0; e < 16; e++) used[e] = false;
        int tidx[8]; float tval[8]; float gsum = 0.f;
        for (int kk = 0; kk < 8; kk++) {
            float best = -1.f; int bi = 0;
            for (int e = 0; e < 16; e++)
                if (!used[e] && p[e] > best) { best = p[e]; bi = e; }
            used[bi] = true; tidx[kk] = bi; tval[kk] = best; gsum += best;
        }
        float ginv = 1.f / (gsum + 1e-6f);
        float gd[16];
#pragma unroll
        for (int e = 0; e < 16; e++) gd[e] = 0.f;
        for (int kk = 0; kk < 8; kk++) gd[tidx[kk]] = tval[kk] * ginv;
#pragma unroll
        for (int e = 0; e < 16; e++) gate_dense[t * 16 + e] = gd[e];
    }
}

// ---------------- aux loss ---------------------------------------------------
__global__ void aux_kernel(const float* __restrict__ probs, float* __restrict__ outv) {
    int tid = threadIdx.x;
    float acc[16];
#pragma unroll
    for (int e = 0; e < 16; e++) acc[e] = 0.f;
    for (int t = tid; t < T_; t += 256) {
        const float* p = probs + (long)t * 16;
#pragma unroll
        for (int e = 0; e < 16; e++) acc[e] += p[e];
    }
    __shared__ float red[256][17];
#pragma unroll
    for (int e = 0; e < 16; e++) red[tid][e] = acc[e];
    __syncthreads();
    for (int s = 128; s; s >>= 1) {
        if (tid < s) {
#pragma unroll
            for (int e = 0; e < 16; e++) red[tid][e] += red[tid + s][e];
        }
        __syncthreads();
    }
    if (tid == 0) {
        float aux = 0.f;
#pragma unroll
        for (int e = 0; e < 16; e++) {
            float mp = red[0][e] * (1.f / T_);
            aux += mp * logf(mp + 1e-6f);
        }
        outv[0] = 5e-4f * aux;
    }
}

// ---------------- + gate_dense @ b2 -----------------------------------------
__global__ void b2add_kernel(const float* __restrict__ gd, const float* __restrict__ b2,
                             float* __restrict__ xo) {
    long t = blockIdx.x;
    __shared__ float g[16];
    if (threadIdx.x < 16) g[threadIdx.x] = gd[t * 16 + threadIdx.x];
    __syncthreads();
    float* row = xo + t * D_;
    for (int d = threadIdx.x; d < D_; d += 256) {
        float s = 0.f;
#pragma unroll
        for (int e = 0; e < 16; e++) s += g[e] * b2[(long)e * D_ + d];
        row[d] += s;
    }
}

// ---------------- launch -----------------------------------------------------
extern "C" void kernel_launch(void* const* d_in, const int* in_sizes, int n_in,
                              void* d_out, int out_size) {
    const float* tgt        = (const float*)d_in[0];
    const float* ln1_g      = (const float*)d_in[2];
    const float* ln1_b      = (const float*)d_in[3];
    const float* ln3_g      = (const float*)d_in[4];
    const float* ln3_b      = (const float*)d_in[5];
    const float* in_proj_w  = (const float*)d_in[6];
    const float* in_proj_b  = (const float*)d_in[7];
    const float* out_proj_w = (const float*)d_in[8];
    const float* out_proj_b = (const float*)d_in[9];
    const float* gate_w     = (const float*)d_in[10];
    const float* w1         = (const float*)d_in[11];
    const float* b1         = (const float*)d_in[12];
    const float* w2         = (const float*)d_in[13];
    const float* b2         = (const float*)d_in[14];
    const int*   task_id    = (const int*)d_in[15];

    float* out       = (float*)d_out;
    float* out_x     = out;
    float* out_aux   = out + (size_t)T_ * D_;
    float* out_probs = out_aux + 1;

    __half *h16, *qkv16, *vt16, *ctx16, *uw16, *wi16, *wo16, *w1t16, *w2t16;
    float *x, *gd;
    cudaGetSymbolAddress((void**)&h16,   g_h16);
    cudaGetSymbolAddress((void**)&qkv16, g_qkv16);
    cudaGetSymbolAddress((void**)&vt16,  g_vt16);
    cudaGetSymbolAddress((void**)&ctx16, g_ctx16);
    cudaGetSymbolAddress((void**)&x,     g_x);
    cudaGetSymbolAddress((void**)&uw16,  g_uw16);
    cudaGetSymbolAddress((void**)&gd,    g_gate);
    cudaGetSymbolAddress((void**)&wi16,  g_wi16);
    cudaGetSymbolAddress((void**)&wo16,  g_wo16);
    cudaGetSymbolAddress((void**)&w1t16, g_w1t16);
    cudaGetSymbolAddress((void**)&w2t16, g_w2t16);

    // 0. weight preprocessing
    conv_f2h<<<(unsigned)(3L * D_ * D_ / 1024), 256>>>(in_proj_w, wi16, 3L * D_ * D_);
    conv_f2h<<<(unsigned)(1L * D_ * D_ / 1024), 256>>>(out_proj_w, wo16, 1L * D_ * D_);
    transpose_h<float><<<dim3(8, 32, E_), 256>>>(
        w1, w1t16, D_, H_, H_, (long)D_ * H_, 0, (long)H_ * D_, 0, 1);
    transpose_h<float><<<dim3(32, 128, 1), 256>>>(
        w2, w2t16, E_ * H_, D_, D_, 0, 0, 0, 0, 1);

    // 1. h = LN1(tgt)
    ln_kernel<<<T_, 256>>>(tgt, ln1_g, ln1_b, h16);

    // 2. qkv = h @ in_proj_w^T + b (half out)
    gemm_h<true, false, false, false, true><<<dim3(12, 128, 1), 512>>>(
        h16, wi16, qkv16, in_proj_b, nullptr, nullptr,
        D_, D_, D_, 3 * D_,
        0, 0, 0, 0, 0, 0, 1, 0, 0, 0, 1.f);

    // 3. Vt = V^T per (b,h)
    transpose_h<__half><<<dim3(2, 16, B_ * NH_), 256>>>(
        qkv16 + 2 * D_, vt16, S_, DH_, 3 * D_,
        (long)S_ * 3 * D_, DH_, (long)NH_ * DH_ * S_, (long)DH_ * S_, NH_);

    // 4. fused flash attention -> ctx16
    flash_k<<<dim3(4, B_ * NH_), 256>>>(qkv16, vt16, ctx16);

    // 5. x = tgt + ctx @ out_proj_w^T + b (fp32 out)
    gemm_h<true, false, false, true, false><<<dim3(4, 128, 1), 512>>>(
        ctx16, wo16, x, out_proj_b, nullptr, tgt,
        D_, D_, D_, D_,
        0, 0, 0, 0, 0, 0, 1, 0, 0, 0, 1.f);

    // 6. h3 = LN3(x)
    ln_kernel<<<T_, 256>>>(x, ln3_g, ln3_b, h16);

    // 7. gate / aux
    gate_kernel<<<T_, 128>>>(h16, gate_w, task_id, out_probs, gd);
    aux_kernel<<<1, 256>>>(out_probs, out_aux);

    // 8. uw = gelu(h3 @ w1 + b1) * gate (half out), z = expert
    gemm_h<true, true, true, false, true><<<dim3(1, 128, E_), 512>>>(
        h16, w1t16, uw16, b1, gd, nullptr,
        D_, D_, D_, E_ * H_,
        0, 0, (long)H_ * D_, 0, (long)H_, 0,
        1, (long)H_, 1, E_, 1.f);

    // 9. out_x = x + uw @ w2 (fp32 out)
    gemm_h<false, false, false, true, false><<<dim3(4, 128, 1), 512>>>(
        uw16, w2t16, out_x, nullptr, nullptr, x,
        E_ * H_, E_ * H_, E_ * H_, D_,
        0, 0, 0, 0, 0, 0, 1, 0, 0, 0, 1.f);

    // 10. out_x += gate_dense @ b2
    b2add_kernel<<<T_, 256>>>(gd, b2, out_x);

    (void)in_sizes; (void)n_in; (void)out_size;
}

// round 7
// speedup vs baseline: 6.9876x; 1.1107x over previous
#include <cuda_runtime.h>
#include <cuda_fp16.h>
#include <math.h>
#include <stdint.h>

#define B_   32
#define S_   512
#define D_   1024
#define NH_  16
#define E_   16
#define H_   256
#define DH_  64
#define T_   (B_ * S_)          // 16384

// ---------------- scratch (static device memory) ---------------------------
__device__ __half g_h16[(size_t)T_ * D_];
__device__ __half g_qkv16[(size_t)T_ * 3 * D_];
__device__ __half g_vt16[(size_t)B_ * NH_ * DH_ * S_];
__device__ __half g_ctx16[(size_t)T_ * D_];
__device__ float  g_x[(size_t)T_ * D_];
__device__ __half g_uw16[(size_t)T_ * E_ * H_];
__device__ float  g_gate[(size_t)T_ * E_];
__device__ __half g_wi16[(size_t)3 * D_ * D_];
__device__ __half g_wo16[(size_t)D_ * D_];
__device__ __half g_w1t16[(size_t)E_ * H_ * D_];
__device__ __half g_w2t16[(size_t)D_ * E_ * H_];

// ---------------- helpers ---------------------------------------------------
__device__ __forceinline__ uint32_t smem_u32(const void* p) {
    uint32_t a;
    asm("{ .reg .u64 t; cvta.to.shared.u64 t, %1; cvt.u32.u64 %0, t; }" : "=r"(a) : "l"(p));
    return a;
}
__device__ __forceinline__ uint32_t h2_as_u32(__half2 h) {
    return *reinterpret_cast<uint32_t*>(&h);
}
#define CP_ASYNC16(dst, src) \
    asm volatile("cp.async.ca.shared.global [%0], [%1], 16;" :: "r"(dst), "l"(src) : "memory")
#define CP_COMMIT() asm volatile("cp.async.commit_group;" ::: "memory")
#define CP_WAIT2()  asm volatile("cp.async.wait_group 2;" ::: "memory")
#define CP_WAIT1()  asm volatile("cp.async.wait_group 1;" ::: "memory")
#define CP_WAIT0()  asm volatile("cp.async.wait_group 0;" ::: "memory")

#define LDSM_X4(r0, r1, r2, r3, addr) \
    asm volatile("ldmatrix.sync.aligned.m8n8.x4.shared.b16 {%0,%1,%2,%3}, [%4];" \
        : "=r"(r0), "=r"(r1), "=r"(r2), "=r"(r3) : "r"(addr))

__device__ __forceinline__ void mma16(float* d, const uint32_t* a, const uint32_t* b) {
    asm volatile(
        "mma.sync.aligned.m16n8k16.row.col.f32.f16.f16.f32 "
        "{%0,%1,%2,%3},{%4,%5,%6,%7},{%8,%9},{%0,%1,%2,%3};"
        : "+f"(d[0]), "+f"(d[1]), "+f"(d[2]), "+f"(d[3])
        : "r"(a[0]), "r"(a[1]), "r"(a[2]), "r"(a[3]), "r"(b[0]), "r"(b[1]));
}

// smem tile: 64 halfs (128B) per row, SW128 (validated in flash kernel)
__device__ __forceinline__ uint32_t qoff(int m, int c) {
    return (uint32_t)(m * 128 + ((c ^ (m & 7)) << 4));
}

// ---------------- LayerNorm (fp32 in -> half out) ---------------------------
__global__ void ln_kernel(const float* __restrict__ x, const float* __restrict__ g,
                          const float* __restrict__ b, __half* __restrict__ y16) {
    long t = blockIdx.x;
    const float* row = x + t * D_;
    int tid = threadIdx.x;
    float v[4];
    float s = 0.f, sq = 0.f;
#pragma unroll
    for (int i = 0; i < 4; i++) {
        v[i] = row[tid + i * 256];
        s += v[i]; sq += v[i] * v[i];
    }
#pragma unroll
    for (int o = 16; o; o >>= 1) {
        s  += __shfl_xor_sync(0xffffffffu, s, o);
        sq += __shfl_xor_sync(0xffffffffu, sq, o);
    }
    __shared__ float ws[8], wq[8];
    int w = tid >> 5, l = tid & 31;
    if (l == 0) { ws[w] = s; wq[w] = sq; }
    __syncthreads();
    if (tid == 0) {
        float a = 0.f, c = 0.f;
        for (int i = 0; i < 8; i++) { a += ws[i]; c += wq[i]; }
        ws[0] = a; wq[0] = c;
    }
    __syncthreads();
    float mean = ws[0] * (1.f / D_);
    float var  = wq[0] * (1.f / D_) - mean * mean;
    float inv  = rsqrtf(var + 1e-5f);
#pragma unroll
    for (int i = 0; i < 4; i++) {
        int d = tid + i * 256;
        y16[t * D_ + d] = __float2half((v[i] - mean) * inv * g[d] + b[d]);
    }
}

// ---------------- fp32 -> fp16 convert --------------------------------------
__global__ void conv_f2h(const float* __restrict__ in, __half* __restrict__ out, long n) {
    long i = (long)blockIdx.x * 1024 + threadIdx.x * 4;
    if (i < n) {
        float4 v = *(const float4*)(in + i);
        *(__half2*)(out + i)     = __floats2half2_rn(v.x, v.y);
        *(__half2*)(out + i + 2) = __floats2half2_rn(v.z, v.w);
    }
}

// ---------------- batched tiled transpose -> half ---------------------------
template <typename TI>
__global__ void transpose_h(const TI* __restrict__ src, __half* __restrict__ dst,
                            int R, int C, long srcRS,
                            long sSo, long sSi, long sDo, long sDi, int nInner) {
    int zo = blockIdx.z / nInner, zi = blockIdx.z - zo * nInner;
    src += (long)zo * sSo + (long)zi * sSi;
    dst += (long)zo * sDo + (long)zi * sDi;
    __shared__ float tile[32][33];
    int r0 = blockIdx.y * 32, c0 = blockIdx.x * 32;
    int tx = threadIdx.x & 31, ty = threadIdx.x >> 5;
#pragma unroll
    for (int k = 0; k < 4; k++) {
        int r = r0 + ty + 8 * k;
        if (r < R && c0 + tx < C) tile[ty + 8 * k][tx] = (float)src[(long)r * srcRS + c0 + tx];
    }
    __syncthreads();
#pragma unroll
    for (int k = 0; k < 4; k++) {
        int c = c0 + ty + 8 * k;
        if (c < C && r0 + tx < R) dst[(long)c * R + r0 + tx] = __float2half(tile[tx][ty + 8 * k]);
    }
}

// ---------------- fused flash attention (unchanged, passing) ----------------
__global__ void __launch_bounds__(256) flash_k(
    const __half* __restrict__ qkv, const __half* __restrict__ vt,
    __half* __restrict__ ctx) {
    int bh = blockIdx.y;
    int b = bh >> 4, hh = bh & 15;
    int qb = blockIdx.x;
    const __half* Qb = qkv + ((long)b * S_ + qb * 128) * (3 * D_) + hh * DH_;
    const __half* Kb = qkv + (long)b * S_ * (3 * D_) + D_ + hh * DH_;
    const __half* Vb = vt + (long)bh * DH_ * S_;

    __shared__ __align__(16) __half Qs[128 * 64];
    __shared__ __align__(16) __half Ks[2][64 * 64];
    __shared__ __align__(16) __half Vs[2][64 * 64];
    uint32_t qB = smem_u32(Qs), kB = smem_u32(Ks), vB = smem_u32(Vs);

    int tid = threadIdx.x, lane = tid & 31, warp = tid >> 5;
    int wm = warp * 16;
    int g = lane >> 2, tq = lane & 3;
    int q2 = lane >> 3, r7 = lane & 7;
    const float L2E = 1.44269504088896f;

#pragma unroll
    for (int j = 0; j < 4; j++) {
        int s = tid + 256 * j;
        int r = s >> 3, cu = s & 7;
        CP_ASYNC16(qB + qoff(r, cu), Qb + (long)r * (3 * D_) + cu * 8);
    }
    CP_COMMIT();
#pragma unroll
    for (int j = 0; j < 2; j++) {
        int s = tid + 256 * j;
        int r = s >> 3, cu = s & 7;
        CP_ASYNC16(kB + qoff(r, cu), Kb + (long)r * (3 * D_) + cu * 8);
        CP_ASYNC16(vB + qoff(r, cu), Vb + (long)r * S_ + cu * 8);
    }
    CP_COMMIT();
    CP_WAIT0();
    __syncthreads();
    {
        __half2 sc = __floats2half2_rn(0.125f, 0.125f);
        __half2* qh = (__half2*)Qs;
#pragma unroll
        for (int i = 0; i < 16; i++) qh[tid + 256 * i] = __hmul2(qh[tid + 256 * i], sc);
    }
    __syncthreads();

    float o[8][4];
#pragma unroll
    for (int ni = 0; ni < 8; ni++)
#pragma unroll
        for (int r = 0; r < 4; r++) o[ni][r] = 0.f;
    float m0 = -1e30f, m1 = -1e30f, l0 = 0.f, l1 = 0.f;

    for (int c = 0; c < 8; c++) {
        int buf = c & 1;
        if (c + 1 < 8) {
            int nb = 1 - buf;
#pragma unroll
            for (int j = 0; j < 2; j++) {
                int s = tid + 256 * j;
                int r = s >> 3, cu = s & 7;
                CP_ASYNC16(kB + nb * 8192 + qoff(r, cu),
                           Kb + (long)((c + 1) * 64 + r) * (3 * D_) + cu * 8);
                CP_ASYNC16(vB + nb * 8192 + qoff(r, cu),
                           Vb + (long)r * S_ + (c + 1) * 64 + cu * 8);
            }
            CP_COMMIT();
            CP_WAIT1();
        } else {
            CP_WAIT0();
        }
        __syncthreads();

        uint32_t kBuf = kB + buf * 8192, vBuf = vB + buf * 8192;
        float sv[8][4];
#pragma unroll
        for (int ni = 0; ni < 8; ni++)
#pragma unroll
            for (int r = 0; r < 4; r++) sv[ni][r] = 0.f;
#pragma unroll
        for (int ks = 0; ks < 4; ks++) {
            uint32_t af[4], bf[8][2];
            int am = wm + (q2 & 1) * 8 + r7;
            LDSM_X4(af[0], af[1], af[2], af[3], qB + qoff(am, 2 * ks + (q2 >> 1)));
#pragma unroll
            for (int nj = 0; nj < 4; nj++) {
                int bn = nj * 16 + (q2 >> 1) * 8 + r7;
                LDSM_X4(bf[2 * nj][0], bf[2 * nj][1], bf[2 * nj + 1][0], bf[2 * nj + 1][1],
                        kBuf + qoff(bn, 2 * ks + (q2 & 1)));
            }
#pragma unroll
            for (int ni = 0; ni < 8; ni++) mma16(sv[ni], af, bf[ni]);
        }

        float cm0 = -1e30f, cm1 = -1e30f;
#pragma unroll
        for (int ni = 0; ni < 8; ni++) {
            cm0 = fmaxf(cm0, fmaxf(sv[ni][0], sv[ni][1]));
            cm1 = fmaxf(cm1, fmaxf(sv[ni][2], sv[ni][3]));
        }
        cm0 = fmaxf(cm0, __shfl_xor_sync(0xffffffffu, cm0, 1));
        cm0 = fmaxf(cm0, __shfl_xor_sync(0xffffffffu, cm0, 2));
        cm1 = fmaxf(cm1, __shfl_xor_sync(0xffffffffu, cm1, 1));
        cm1 = fmaxf(cm1, __shfl_xor_sync(0xffffffffu, cm1, 2));
        float mn0 = fmaxf(m0, cm0), mn1 = fmaxf(m1, cm1);
        float sc0 = exp2f((m0 - mn0) * L2E), sc1 = exp2f((m1 - mn1) * L2E);
        m0 = mn0; m1 = mn1;
        l0 *= sc0; l1 *= sc1;
#pragma unroll
        for (int ni = 0; ni < 8; ni++) {
            o[ni][0] *= sc0; o[ni][1] *= sc0;
            o[ni][2] *= sc1; o[ni][3] *= sc1;
        }
        uint32_t pa[4][4];
        float rs0 = 0.f, rs1 = 0.f;
#pragma unroll
        for (int ni = 0; ni < 8; ni++) {
            float p0 = exp2f((sv[ni][0] - mn0) * L2E);
            float p1 = exp2f((sv[ni][1] - mn0) * L2E);
            float p2 = exp2f((sv[ni][2] - mn1) * L2E);
            float p3 = exp2f((sv[ni][3] - mn1) * L2E);
            rs0 += p0 + p1; rs1 += p2 + p3;
            int kk = ni >> 1, hi = ni & 1;
            pa[kk][hi * 2]     = h2_as_u32(__floats2half2_rn(p0, p1));
            pa[kk][hi * 2 + 1] = h2_as_u32(__floats2half2_rn(p2, p3));
        }
        rs0 += __shfl_xor_sync(0xffffffffu, rs0, 1);
        rs0 += __shfl_xor_sync(0xffffffffu, rs0, 2);
        rs1 += __shfl_xor_sync(0xffffffffu, rs1, 1);
        rs1 += __shfl_xor_sync(0xffffffffu, rs1, 2);
        l0 += rs0; l1 += rs1;

#pragma unroll
        for (int ks = 0; ks < 4; ks++) {
            uint32_t bf[8][2];
#pragma unroll
            for (int nj = 0; nj < 4; nj++) {
                int bn = nj * 16 + (q2 >> 1) * 8 + r7;
                LDSM_X4(bf[2 * nj][0], bf[2 * nj][1], bf[2 * nj + 1][0], bf[2 * nj + 1][1],
                        vBuf + qoff(bn, 2 * ks + (q2 & 1)));
            }
#pragma unroll
            for (int ni = 0; ni < 8; ni++) mma16(o[ni], pa[ks], bf[ni]);
        }
        __syncthreads();
    }

    float li0 = 1.f / l0, li1 = 1.f / l1;
    long row0 = (long)b * S_ + qb * 128 + wm + g;
    __half* c0p = ctx + (row0)     * D_ + hh * DH_;
    __half* c1p = ctx + (row0 + 8) * D_ + hh * DH_;
#pragma unroll
    for (int ni = 0; ni < 8; ni++) {
        int nc = ni * 8 + tq * 2;
        *(__half2*)(c0p + nc) = __floats2half2_rn(o[ni][0] * li0, o[ni][1] * li0);
        *(__half2*)(c1p + nc) = __floats2half2_rn(o[ni][2] * li1, o[ni][3] * li1);
    }
}

// ---------------- fp16 GEMM: 128x256 tile, BK=64, 3-stage pipeline ----------
// C = epilogue(A @ B^T); A:[M,K] half, B:[N,K] half, both row-major (K-major).
// One __syncthreads per 64-wide K chunk. Dynamic smem = 3 * 48KB.
template <bool BI, bool GE, bool GA, bool RE, bool HOUT>
__global__ void __launch_bounds__(512) gemm_h(
    const __half* __restrict__ A, const __half* __restrict__ Bm, void* __restrict__ C,
    const float* __restrict__ bias, const float* __restrict__ gate,
    const float* __restrict__ resid,
    int Kd, int lda, int ldb, int ldc,
    long sAo, long sAi, long sBo, long sBi, long sCo, long sCi,
    int nInner, long sBias, long sGate, int gateStride, float alpha) {
    constexpr int NT = 256, MI = 2, NI = 8;
    constexpr int STAGE = 49152;          // (128 + 256) * 64 * 2 bytes
    constexpr int BOFF  = 16384;          // A = 128*64*2

    extern __shared__ __align__(16) char smdyn[];
    uint32_t sb = smem_u32(smdyn);

    int tid = threadIdx.x, lane = tid & 31, warp = tid >> 5;
    int zo = blockIdx.z / nInner, zi = blockIdx.z - zo * nInner;
    const __half* Ap = A + (long)zo * sAo + (long)zi * sAi;
    const __half* Bp = Bm + (long)zo * sBo + (long)zi * sBi;
    long coff = (long)zo * sCo + (long)zi * sCi;
    int bm = blockIdx.y * 128, bn = blockIdx.x * NT;
    int wm = (warp % 4) * 32, wn = (warp / 4) * 64;
    int g = lane >> 2, tq = lane & 3;
    int q2 = lane >> 3, r7 = lane & 7;

    float acc[MI][NI][4];
#pragma unroll
    for (int mi = 0; mi < MI; mi++)
#pragma unroll
        for (int ni = 0; ni < NI; ni++)
#pragma unroll
            for (int r = 0; r < 4; r++) acc[mi][ni][r] = 0.f;

    int NC = Kd >> 6;

    // stage fill: A 1024 16B-slots (2/thread), B 2048 slots (4/thread)
#define GH_ISSUE(st, k0)                                                          \
    do {                                                                          \
        uint32_t _as = sb + (st) * STAGE;                                         \
        uint32_t _bs = _as + BOFF;                                                \
        _Pragma("unroll")                                                         \
        for (int j = 0; j < 2; j++) {                                             \
            int s = tid + 512 * j;                                                \
            int r = s >> 3, cu = s & 7;                                           \
            CP_ASYNC16(_as + qoff(r, cu), Ap + (long)(bm + r) * lda + (k0) + cu * 8); \
        }                                                                         \
        _Pragma("unroll")                                                         \
        for (int j = 0; j < 4; j++) {                                             \
            int s = tid + 512 * j;                                                \
            int r = s >> 3, cu = s & 7;                                           \
            CP_ASYNC16(_bs + qoff(r, cu), Bp + (long)(bn + r) * ldb + (k0) + cu * 8); \
        }                                                                         \
    } while (0)

    GH_ISSUE(0, 0);
    CP_COMMIT();
    GH_ISSUE(1, 64);
    CP_COMMIT();

    for (int ck = 0; ck < NC; ck++) {
        CP_WAIT1();
        __syncthreads();
        // refill the stage consumed 3 chunks ago (safe: all warps past its compute)
        if (ck + 2 < NC) {
            int st = (ck + 2) % 3;
            GH_ISSUE(st, (ck + 2) << 6);
        }
        CP_COMMIT();   // empty group near the tail keeps wait counting uniform

        uint32_t aBase = sb + (ck % 3) * STAGE;
        uint32_t bBase = aBase + BOFF;
#pragma unroll
        for (int s = 0; s < 4; s++) {
            uint32_t af[MI][4], bf[NI][2];
#pragma unroll
            for (int mi = 0; mi < MI; mi++) {
                int m = wm + mi * 16 + (q2 & 1) * 8 + r7;
                LDSM_X4(af[mi][0], af[mi][1], af[mi][2], af[mi][3],
                        aBase + qoff(m, 2 * s + (q2 >> 1)));
            }
#pragma unroll
            for (int nj = 0; nj < NI / 2; nj++) {
                int n = wn + nj * 16 + (q2 >> 1) * 8 + r7;
                LDSM_X4(bf[2 * nj][0], bf[2 * nj][1], bf[2 * nj + 1][0], bf[2 * nj + 1][1],
                        bBase + qoff(n, 2 * s + (q2 & 1)));
            }
#pragma unroll
            for (int mi = 0; mi < MI; mi++)
#pragma unroll
                for (int ni = 0; ni < NI; ni++)
                    mma16(acc[mi][ni], af[mi], bf[ni]);
        }
        __syncthreads();   // all warps done with this stage before it is refilled
    }
#undef GH_ISSUE

    const float* biasz = BI ? bias + (long)blockIdx.z * sBias : nullptr;
    const float* gatez = GA ? gate + (long)blockIdx.z * sGate : nullptr;
    __half* Ch = (__half*)C + coff;
    float*  Cf = (float*)C + coff;
    const float* Rz = RE ? resid + coff : nullptr;
#pragma unroll
    for (int mi = 0; mi < MI; mi++) {
#pragma unroll
        for (int rh = 0; rh < 2; rh++) {
            int row = bm + wm + mi * 16 + g + rh * 8;
            float gv = GA ? gatez[(long)row * gateStride] : 0.f;
#pragma unroll
            for (int ni = 0; ni < NI; ni++) {
                int n = bn + wn + ni * 8 + tq * 2;
                float v0 = acc[mi][ni][rh * 2]     * alpha;
                float v1 = acc[mi][ni][rh * 2 + 1] * alpha;
                if (BI) { v0 += biasz[n]; v1 += biasz[n + 1]; }
                if (GE) {
                    v0 = 0.5f * v0 * (1.f + erff(v0 * 0.70710678118654752f));
                    v1 = 0.5f * v1 * (1.f + erff(v1 * 0.70710678118654752f));
                }
                if (GA) { v0 *= gv; v1 *= gv; }
                if (HOUT) {
                    *(__half2*)(Ch + (long)row * ldc + n) = __floats2half2_rn(v0, v1);
                } else {
                    if (RE) {
                        float2 rv = *(const float2*)(Rz + (long)row * ldc + n);
                        v0 += rv.x; v1 += rv.y;
                    }
                    float2 ov; ov.x = v0; ov.y = v1;
                    *(float2*)(Cf + (long)row * ldc + n) = ov;
                }
            }
        }
    }
}

// ---------------- gate: logits, softmax, probs, top-8 gates ----------------
__global__ void gate_kernel(const __half* __restrict__ h3, const float* __restrict__ gate_w,
                            const int* __restrict__ task_id,
                            float* __restrict__ probs, float* __restrict__ gate_dense) {
    long t = blockIdx.x;
    const float* gw = gate_w + (long)(*task_id) * (D_ * E_);
    const __half* row = h3 + t * D_;
    int tid = threadIdx.x;
    float acc[16];
#pragma unroll
    for (int e = 0; e < 16; e++) acc[e] = 0.f;
    for (int d = tid; d < D_; d += 128) {
        float hv = __half2float(row[d]);
        const float* g = gw + (long)d * 16;
#pragma unroll
        for (int e = 0; e < 16; e++) acc[e] += hv * g[e];
    }
    __shared__ float red[128][17];
#pragma unroll
    for (int e = 0; e < 16; e++) red[tid][e] = acc[e];
    __syncthreads();
    for (int s = 64; s; s >>= 1) {
        if (tid < s) {
#pragma unroll
            for (int e = 0; e < 16; e++) red[tid][e] += red[tid + s][e];
        }
        __syncthreads();
    }
    if (tid == 0) {
        float lg[16], mx = -1e30f;
#pragma unroll
        for (int e = 0; e < 16; e++) { lg[e] = red[0][e]; mx = fmaxf(mx, lg[e]); }
        float sum = 0.f;
#pragma unroll
        for (int e = 0; e < 16; e++) { lg[e] = expf(lg[e] - mx); sum += lg[e]; }
        float inv = 1.f / sum;
        float p[16];
#pragma unroll
        for (int e = 0; e < 16; e++) { p[e] = lg[e] * inv; probs[t * 16 + e] = p[e]; }
        bool used[16];
#pragma unroll
        for (int e = 0; e < 16; e++) used[e] = false;
        int tidx[8]; float tval[8]; float gsum = 0.f;
        for (int kk = 0; kk < 8; kk++) {
            float best = -1.f; int bi = 0;
            for (int e = 0; e < 16; e++)
                if (!used[e] && p[e] > best) { best = p[e]; bi = e; }
            used[bi] = true; tidx[kk] = bi; tval[kk] = best; gsum += best;
        }
        float ginv = 1.f / (gsum + 1e-6f);
        float gd[16];
#pragma unroll
        for (int e = 0; e < 16; e++) gd[e] = 0.f;
        for (int kk = 0; kk < 8; kk++) gd[tidx[kk]] = tval[kk] * ginv;
#pragma unroll
        for (int e = 0; e < 16; e++) gate_dense[t * 16 + e] = gd[e];
    }
}

// ---------------- aux loss ---------------------------------------------------
__global__ void aux_kernel(const float* __restrict__ probs, float* __restrict__ outv) {
    int tid = threadIdx.x;
    float acc[16];
#pragma unroll
    for (int e = 0; e < 16; e++) acc[e] = 0.f;
    for (int t = tid; t < T_; t += 256) {
        const float* p = probs + (long)t * 16;
#pragma unroll
        for (int e = 0; e < 16; e++) acc[e] += p[e];
    }
    __shared__ float red[256][17];
#pragma unroll
    for (int e = 0; e < 16; e++) red[tid][e] = acc[e];
    __syncthreads();
    for (int s = 128; s; s >>= 1) {
        if (tid < s) {
#pragma unroll
            for (int e = 0; e < 16; e++) red[tid][e] += red[tid + s][e];
        }
        __syncthreads();
    }
    if (tid == 0) {
        float aux = 0.f;
#pragma unroll
        for (int e = 0; e < 16; e++) {
            float mp = red[0][e] * (1.f / T_);
            aux += mp * logf(mp + 1e-6f);
        }
        outv[0] = 5e-4f * aux;
    }
}

// ---------------- + gate_dense @ b2 -----------------------------------------
__global__ void b2add_kernel(const float* __restrict__ gd, const float* __restrict__ b2,
                             float* __restrict__ xo) {
    long t = blockIdx.x;
    __shared__ float g[16];
    if (threadIdx.x < 16) g[threadIdx.x] = gd[t * 16 + threadIdx.x];
    __syncthreads();
    float* row = xo + t * D_;
    for (int d = threadIdx.x; d < D_; d += 256) {
        float s = 0.f;
#pragma unroll
        for (int e = 0; e < 16; e++) s += g[e] * b2[(long)e * D_ + d];
        row[d] += s;
    }
}

// ---------------- launch -----------------------------------------------------
extern "C" void kernel_launch(void* const* d_in, const int* in_sizes, int n_in,
                              void* d_out, int out_size) {
    const float* tgt        = (const float*)d_in[0];
    const float* ln1_g      = (const float*)d_in[2];
    const float* ln1_b      = (const float*)d_in[3];
    const float* ln3_g      = (const float*)d_in[4];
    const float* ln3_b      = (const float*)d_in[5];
    const float* in_proj_w  = (const float*)d_in[6];
    const float* in_proj_b  = (const float*)d_in[7];
    const float* out_proj_w = (const float*)d_in[8];
    const float* out_proj_b = (const float*)d_in[9];
    const float* gate_w     = (const float*)d_in[10];
    const float* w1         = (const float*)d_in[11];
    const float* b1         = (const float*)d_in[12];
    const float* w2         = (const float*)d_in[13];
    const float* b2         = (const float*)d_in[14];
    const int*   task_id    = (const int*)d_in[15];

    float* out       = (float*)d_out;
    float* out_x     = out;
    float* out_aux   = out + (size_t)T_ * D_;
    float* out_probs = out_aux + 1;

    __half *h16, *qkv16, *vt16, *ctx16, *uw16, *wi16, *wo16, *w1t16, *w2t16;
    float *x, *gd;
    cudaGetSymbolAddress((void**)&h16,   g_h16);
    cudaGetSymbolAddress((void**)&qkv16, g_qkv16);
    cudaGetSymbolAddress((void**)&vt16,  g_vt16);
    cudaGetSymbolAddress((void**)&ctx16, g_ctx16);
    cudaGetSymbolAddress((void**)&x,     g_x);
    cudaGetSymbolAddress((void**)&uw16,  g_uw16);
    cudaGetSymbolAddress((void**)&gd,    g_gate);
    cudaGetSymbolAddress((void**)&wi16,  g_wi16);
    cudaGetSymbolAddress((void**)&wo16,  g_wo16);
    cudaGetSymbolAddress((void**)&w1t16, g_w1t16);
    cudaGetSymbolAddress((void**)&w2t16, g_w2t16);

    const int GSM = 3 * 49152;   // 147456 bytes dynamic smem
    cudaFuncSetAttribute(gemm_h<true,  false, false, false, true >, cudaFuncAttributeMaxDynamicSharedMemorySize, GSM);
    cudaFuncSetAttribute(gemm_h<true,  false, false, true,  false>, cudaFuncAttributeMaxDynamicSharedMemorySize, GSM);
    cudaFuncSetAttribute(gemm_h<true,  true,  true,  false, true >, cudaFuncAttributeMaxDynamicSharedMemorySize, GSM);
    cudaFuncSetAttribute(gemm_h<false, false, false, true,  false>, cudaFuncAttributeMaxDynamicSharedMemorySize, GSM);

    // 0. weight preprocessing
    conv_f2h<<<(unsigned)(3L * D_ * D_ / 1024), 256>>>(in_proj_w, wi16, 3L * D_ * D_);
    conv_f2h<<<(unsigned)(1L * D_ * D_ / 1024), 256>>>(out_proj_w, wo16, 1L * D_ * D_);
    transpose_h<float><<<dim3(8, 32, E_), 256>>>(
        w1, w1t16, D_, H_, H_, (long)D_ * H_, 0, (long)H_ * D_, 0, 1);
    transpose_h<float><<<dim3(32, 128, 1), 256>>>(
        w2, w2t16, E_ * H_, D_, D_, 0, 0, 0, 0, 1);

    // 1. h = LN1(tgt)
    ln_kernel<<<T_, 256>>>(tgt, ln1_g, ln1_b, h16);

    // 2. qkv = h @ in_proj_w^T + b (half out)
    gemm_h<true, false, false, false, true><<<dim3(12, 128, 1), 512, GSM>>>(
        h16, wi16, qkv16, in_proj_b, nullptr, nullptr,
        D_, D_, D_, 3 * D_,
        0, 0, 0, 0, 0, 0, 1, 0, 0, 0, 1.f);

    // 3. Vt = V^T per (b,h)
    transpose_h<__half><<<dim3(2, 16, B_ * NH_), 256>>>(
        qkv16 + 2 * D_, vt16, S_, DH_, 3 * D_,
        (long)S_ * 3 * D_, DH_, (long)NH_ * DH_ * S_, (long)DH_ * S_, NH_);

    // 4. fused flash attention -> ctx16
    flash_k<<<dim3(4, B_ * NH_), 256>>>(qkv16, vt16, ctx16);

    // 5. x = tgt + ctx @ out_proj_w^T + b (fp32 out)
    gemm_h<true, false, false, true, false><<<dim3(4, 128, 1), 512, GSM>>>(
        ctx16, wo16, x, out_proj_b, nullptr, tgt,
        D_, D_, D_, D_,
        0, 0, 0, 0, 0, 0, 1, 0, 0, 0, 1.f);

    // 6. h3 = LN3(x)
    ln_kernel<<<T_, 256>>>(x, ln3_g, ln3_b, h16);

    // 7. gate / aux
    gate_kernel<<<T_, 128>>>(h16, gate_w, task_id, out_probs, gd);
    aux_kernel<<<1, 256>>>(out_probs, out_aux);

    // 8. uw = gelu(h3 @ w1 + b1) * gate (half out), z = expert
    gemm_h<true, true, true, false, true><<<dim3(1, 128, E_), 512, GSM>>>(
        h16, w1t16, uw16, b1, gd, nullptr,
        D_, D_, D_, E_ * H_,
        0, 0, (long)H_ * D_, 0, (long)H_, 0,
        1, (long)H_, 1, E_, 1.f);

    // 9. out_x = x + uw @ w2 (fp32 out)
    gemm_h<false, false, false, true, false><<<dim3(4, 128, 1), 512, GSM>>>(
        uw16, w2t16, out_x, nullptr, nullptr, x,
        E_ * H_, E_ * H_, E_ * H_, D_,
        0, 0, 0, 0, 0, 0, 1, 0, 0, 0, 1.f);

    // 10. out_x += gate_dense @ b2
    b2add_kernel<<<T_, 256>>>(gd, b2, out_x);

    (void)in_sizes; (void)n_in; (void)out_size;
}

// round 8
// speedup vs baseline: 8.4844x; 1.2142x over previous
#include <cuda_runtime.h>
#include <cuda_fp16.h>
#include <math.h>
#include <stdint.h>

#define B_   32
#define S_   512
#define D_   1024
#define NH_  16
#define E_   16
#define H_   256
#define DH_  64
#define T_   (B_ * S_)          // 16384
#define CAP_ 16384

// ---------------- scratch (static device memory) ---------------------------
__device__ __half g_h16[(size_t)T_ * D_];
__device__ __half g_qkv16[(size_t)T_ * 3 * D_];
__device__ __half g_vt16[(size_t)B_ * NH_ * DH_ * S_];
__device__ __half g_ctx16[(size_t)T_ * D_];
__device__ float  g_x[(size_t)T_ * D_];
__device__ float  g_gate[(size_t)T_ * E_];
__device__ __half g_wi16[(size_t)3 * D_ * D_];
__device__ __half g_wo16[(size_t)D_ * D_];
__device__ __half g_w1t16[(size_t)E_ * H_ * D_];
__device__ __half g_w2te16[(size_t)E_ * D_ * H_];
__device__ __half g_uws[(size_t)E_ * CAP_ * H_];
__device__ __half g_outs[(size_t)E_ * CAP_ * D_];
__device__ int    g_cnt[E_];
__device__ int    g_rowidx[(size_t)E_ * CAP_];
__device__ int    g_pairpos[(size_t)T_ * 8];

// ---------------- helpers ---------------------------------------------------
__device__ __forceinline__ uint32_t smem_u32(const void* p) {
    uint32_t a;
    asm("{ .reg .u64 t; cvta.to.shared.u64 t, %1; cvt.u32.u64 %0, t; }" : "=r"(a) : "l"(p));
    return a;
}
__device__ __forceinline__ uint32_t h2_as_u32(__half2 h) {
    return *reinterpret_cast<uint32_t*>(&h);
}
#define CP_ASYNC16(dst, src) \
    asm volatile("cp.async.ca.shared.global [%0], [%1], 16;" :: "r"(dst), "l"(src) : "memory")
#define CP_COMMIT() asm volatile("cp.async.commit_group;" ::: "memory")
#define CP_WAIT1()  asm volatile("cp.async.wait_group 1;" ::: "memory")
#define CP_WAIT0()  asm volatile("cp.async.wait_group 0;" ::: "memory")

#define LDSM_X4(r0, r1, r2, r3, addr) \
    asm volatile("ldmatrix.sync.aligned.m8n8.x4.shared.b16 {%0,%1,%2,%3}, [%4];" \
        : "=r"(r0), "=r"(r1), "=r"(r2), "=r"(r3) : "r"(addr))

__device__ __forceinline__ void mma16(float* d, const uint32_t* a, const uint32_t* b) {
    asm volatile(
        "mma.sync.aligned.m16n8k16.row.col.f32.f16.f16.f32 "
        "{%0,%1,%2,%3},{%4,%5,%6,%7},{%8,%9},{%0,%1,%2,%3};"
        : "+f"(d[0]), "+f"(d[1]), "+f"(d[2]), "+f"(d[3])
        : "r"(a[0]), "r"(a[1]), "r"(a[2]), "r"(a[3]), "r"(b[0]), "r"(b[1]));
}

// smem tile: 64 halfs (128B) per row, SW128
__device__ __forceinline__ uint32_t qoff(int m, int c) {
    return (uint32_t)(m * 128 + ((c ^ (m & 7)) << 4));
}
__device__ __forceinline__ float gelu_f(float v) {
    return 0.5f * v * (1.f + erff(v * 0.70710678118654752f));
}

// ---------------- LayerNorm (fp32 in -> half out) ---------------------------
__global__ void ln_kernel(const float* __restrict__ x, const float* __restrict__ g,
                          const float* __restrict__ b, __half* __restrict__ y16) {
    long t = blockIdx.x;
    const float* row = x + t * D_;
    int tid = threadIdx.x;
    float v[4];
    float s = 0.f, sq = 0.f;
#pragma unroll
    for (int i = 0; i < 4; i++) {
        v[i] = row[tid + i * 256];
        s += v[i]; sq += v[i] * v[i];
    }
#pragma unroll
    for (int o = 16; o; o >>= 1) {
        s  += __shfl_xor_sync(0xffffffffu, s, o);
        sq += __shfl_xor_sync(0xffffffffu, sq, o);
    }
    __shared__ float ws[8], wq[8];
    int w = tid >> 5, l = tid & 31;
    if (l == 0) { ws[w] = s; wq[w] = sq; }
    __syncthreads();
    if (tid == 0) {
        float a = 0.f, c = 0.f;
        for (int i = 0; i < 8; i++) { a += ws[i]; c += wq[i]; }
        ws[0] = a; wq[0] = c;
    }
    __syncthreads();
    float mean = ws[0] * (1.f / D_);
    float var  = wq[0] * (1.f / D_) - mean * mean;
    float inv  = rsqrtf(var + 1e-5f);
#pragma unroll
    for (int i = 0; i < 4; i++) {
        int d = tid + i * 256;
        y16[t * D_ + d] = __float2half((v[i] - mean) * inv * g[d] + b[d]);
    }
}

// ---------------- fp32 -> fp16 convert --------------------------------------
__global__ void conv_f2h(const float* __restrict__ in, __half* __restrict__ out, long n) {
    long i = (long)blockIdx.x * 1024 + threadIdx.x * 4;
    if (i < n) {
        float4 v = *(const float4*)(in + i);
        *(__half2*)(out + i)     = __floats2half2_rn(v.x, v.y);
        *(__half2*)(out + i + 2) = __floats2half2_rn(v.z, v.w);
    }
}

// ---------------- batched tiled transpose -> half ---------------------------
template <typename TI>
__global__ void transpose_h(const TI* __restrict__ src, __half* __restrict__ dst,
                            int R, int C, long srcRS,
                            long sSo, long sSi, long sDo, long sDi, int nInner) {
    int zo = blockIdx.z / nInner, zi = blockIdx.z - zo * nInner;
    src += (long)zo * sSo + (long)zi * sSi;
    dst += (long)zo * sDo + (long)zi * sDi;
    __shared__ float tile[32][33];
    int r0 = blockIdx.y * 32, c0 = blockIdx.x * 32;
    int tx = threadIdx.x & 31, ty = threadIdx.x >> 5;
#pragma unroll
    for (int k = 0; k < 4; k++) {
        int r = r0 + ty + 8 * k;
        if (r < R && c0 + tx < C) tile[ty + 8 * k][tx] = (float)src[(long)r * srcRS + c0 + tx];
    }
    __syncthreads();
#pragma unroll
    for (int k = 0; k < 4; k++) {
        int c = c0 + ty + 8 * k;
        if (c < C && r0 + tx < R) dst[(long)c * R + r0 + tx] = __float2half(tile[tx][ty + 8 * k]);
    }
}

// ---------------- fused flash attention (unchanged, validated) --------------
__global__ void __launch_bounds__(256) flash_k(
    const __half* __restrict__ qkv, const __half* __restrict__ vt,
    __half* __restrict__ ctx) {
    int bh = blockIdx.y;
    int b = bh >> 4, hh = bh & 15;
    int qb = blockIdx.x;
    const __half* Qb = qkv + ((long)b * S_ + qb * 128) * (3 * D_) + hh * DH_;
    const __half* Kb = qkv + (long)b * S_ * (3 * D_) + D_ + hh * DH_;
    const __half* Vb = vt + (long)bh * DH_ * S_;

    __shared__ __align__(16) __half Qs[128 * 64];
    __shared__ __align__(16) __half Ks[2][64 * 64];
    __shared__ __align__(16) __half Vs[2][64 * 64];
    uint32_t qB = smem_u32(Qs), kB = smem_u32(Ks), vB = smem_u32(Vs);

    int tid = threadIdx.x, lane = tid & 31, warp = tid >> 5;
    int wm = warp * 16;
    int g = lane >> 2, tq = lane & 3;
    int q2 = lane >> 3, r7 = lane & 7;
    const float L2E = 1.44269504088896f;

#pragma unroll
    for (int j = 0; j < 4; j++) {
        int s = tid + 256 * j;
        int r = s >> 3, cu = s & 7;
        CP_ASYNC16(qB + qoff(r, cu), Qb + (long)r * (3 * D_) + cu * 8);
    }
    CP_COMMIT();
#pragma unroll
    for (int j = 0; j < 2; j++) {
        int s = tid + 256 * j;
        int r = s >> 3, cu = s & 7;
        CP_ASYNC16(kB + qoff(r, cu), Kb + (long)r * (3 * D_) + cu * 8);
        CP_ASYNC16(vB + qoff(r, cu), Vb + (long)r * S_ + cu * 8);
    }
    CP_COMMIT();
    CP_WAIT0();
    __syncthreads();
    {
        __half2 sc = __floats2half2_rn(0.125f, 0.125f);
        __half2* qh = (__half2*)Qs;
#pragma unroll
        for (int i = 0; i < 16; i++) qh[tid + 256 * i] = __hmul2(qh[tid + 256 * i], sc);
    }
    __syncthreads();

    float o[8][4];
#pragma unroll
    for (int ni = 0; ni < 8; ni++)
#pragma unroll
        for (int r = 0; r < 4; r++) o[ni][r] = 0.f;
    float m0 = -1e30f, m1 = -1e30f, l0 = 0.f, l1 = 0.f;

    for (int c = 0; c < 8; c++) {
        int buf = c & 1;
        if (c + 1 < 8) {
            int nb = 1 - buf;
#pragma unroll
            for (int j = 0; j < 2; j++) {
                int s = tid + 256 * j;
                int r = s >> 3, cu = s & 7;
                CP_ASYNC16(kB + nb * 8192 + qoff(r, cu),
                           Kb + (long)((c + 1) * 64 + r) * (3 * D_) + cu * 8);
                CP_ASYNC16(vB + nb * 8192 + qoff(r, cu),
                           Vb + (long)r * S_ + (c + 1) * 64 + cu * 8);
            }
            CP_COMMIT();
            CP_WAIT1();
        } else {
            CP_WAIT0();
        }
        __syncthreads();

        uint32_t kBuf = kB + buf * 8192, vBuf = vB + buf * 8192;
        float sv[8][4];
#pragma unroll
        for (int ni = 0; ni < 8; ni++)
#pragma unroll
            for (int r = 0; r < 4; r++) sv[ni][r] = 0.f;
#pragma unroll
        for (int ks = 0; ks < 4; ks++) {
            uint32_t af[4], bf[8][2];
            int am = wm + (q2 & 1) * 8 + r7;
            LDSM_X4(af[0], af[1], af[2], af[3], qB + qoff(am, 2 * ks + (q2 >> 1)));
#pragma unroll
            for (int nj = 0; nj < 4; nj++) {
                int bn = nj * 16 + (q2 >> 1) * 8 + r7;
                LDSM_X4(bf[2 * nj][0], bf[2 * nj][1], bf[2 * nj + 1][0], bf[2 * nj + 1][1],
                        kBuf + qoff(bn, 2 * ks + (q2 & 1)));
            }
#pragma unroll
            for (int ni = 0; ni < 8; ni++) mma16(sv[ni], af, bf[ni]);
        }

        float cm0 = -1e30f, cm1 = -1e30f;
#pragma unroll
        for (int ni = 0; ni < 8; ni++) {
            cm0 = fmaxf(cm0, fmaxf(sv[ni][0], sv[ni][1]));
            cm1 = fmaxf(cm1, fmaxf(sv[ni][2], sv[ni][3]));
        }
        cm0 = fmaxf(cm0, __shfl_xor_sync(0xffffffffu, cm0, 1));
        cm0 = fmaxf(cm0, __shfl_xor_sync(0xffffffffu, cm0, 2));
        cm1 = fmaxf(cm1, __shfl_xor_sync(0xffffffffu, cm1, 1));
        cm1 = fmaxf(cm1, __shfl_xor_sync(0xffffffffu, cm1, 2));
        float mn0 = fmaxf(m0, cm0), mn1 = fmaxf(m1, cm1);
        float sc0 = exp2f((m0 - mn0) * L2E), sc1 = exp2f((m1 - mn1) * L2E);
        m0 = mn0; m1 = mn1;
        l0 *= sc0; l1 *= sc1;
#pragma unroll
        for (int ni = 0; ni < 8; ni++) {
            o[ni][0] *= sc0; o[ni][1] *= sc0;
            o[ni][2] *= sc1; o[ni][3] *= sc1;
        }
        uint32_t pa[4][4];
        float rs0 = 0.f, rs1 = 0.f;
#pragma unroll
        for (int ni = 0; ni < 8; ni++) {
            float p0 = exp2f((sv[ni][0] - mn0) * L2E);
            float p1 = exp2f((sv[ni][1] - mn0) * L2E);
            float p2 = exp2f((sv[ni][2] - mn1) * L2E);
            float p3 = exp2f((sv[ni][3] - mn1) * L2E);
            rs0 += p0 + p1; rs1 += p2 + p3;
            int kk = ni >> 1, hi = ni & 1;
            pa[kk][hi * 2]     = h2_as_u32(__floats2half2_rn(p0, p1));
            pa[kk][hi * 2 + 1] = h2_as_u32(__floats2half2_rn(p2, p3));
        }
        rs0 += __shfl_xor_sync(0xffffffffu, rs0, 1);
        rs0 += __shfl_xor_sync(0xffffffffu, rs0, 2);
        rs1 += __shfl_xor_sync(0xffffffffu, rs1, 1);
        rs1 += __shfl_xor_sync(0xffffffffu, rs1, 2);
        l0 += rs0; l1 += rs1;

#pragma unroll
        for (int ks = 0; ks < 4; ks++) {
            uint32_t bf[8][2];
#pragma unroll
            for (int nj = 0; nj < 4; nj++) {
                int bn = nj * 16 + (q2 >> 1) * 8 + r7;
                LDSM_X4(bf[2 * nj][0], bf[2 * nj][1], bf[2 * nj + 1][0], bf[2 * nj + 1][1],
                        vBuf + qoff(bn, 2 * ks + (q2 & 1)));
            }
#pragma unroll
            for (int ni = 0; ni < 8; ni++) mma16(o[ni], pa[ks], bf[ni]);
        }
        __syncthreads();
    }

    float li0 = 1.f / l0, li1 = 1.f / l1;
    long row0 = (long)b * S_ + qb * 128 + wm + g;
    __half* c0p = ctx + (row0)     * D_ + hh * DH_;
    __half* c1p = ctx + (row0 + 8) * D_ + hh * DH_;
#pragma unroll
    for (int ni = 0; ni < 8; ni++) {
        int nc = ni * 8 + tq * 2;
        *(__half2*)(c0p + nc) = __floats2half2_rn(o[ni][0] * li0, o[ni][1] * li0);
        *(__half2*)(c1p + nc) = __floats2half2_rn(o[ni][2] * li1, o[ni][3] * li1);
    }
}

// ---------------- generic fp16 GEMM (128x256, BK=64, 3 stages) --------------
template <bool BI, bool RE, bool HOUT>
__global__ void __launch_bounds__(512) gemm_h(
    const __half* __restrict__ A, const __half* __restrict__ Bm, void* __restrict__ C,
    const float* __restrict__ bias, const float* __restrict__ resid,
    int Kd, int lda, int ldb, int ldc) {
    constexpr int STAGE = 49152, BOFF = 16384;
    extern __shared__ __align__(16) char smdyn[];
    uint32_t sb = smem_u32(smdyn);

    int tid = threadIdx.x, lane = tid & 31, warp = tid >> 5;
    int bm = blockIdx.y * 128, bn = blockIdx.x * 256;
    int wm = (warp % 4) * 32, wn = (warp / 4) * 64;
    int g = lane >> 2, tq = lane & 3;
    int q2 = lane >> 3, r7 = lane & 7;

    float acc[2][8][4];
#pragma unroll
    for (int mi = 0; mi < 2; mi++)
#pragma unroll
        for (int ni = 0; ni < 8; ni++)
#pragma unroll
            for (int r = 0; r < 4; r++) acc[mi][ni][r] = 0.f;

    int NC = Kd >> 6;
#define GH_ISSUE(st, k0)                                                              \
    do {                                                                              \
        uint32_t _as = sb + (st) * STAGE, _bs = _as + BOFF;                           \
        _Pragma("unroll")                                                             \
        for (int j = 0; j < 2; j++) {                                                 \
            int s = tid + 512 * j; int r = s >> 3, cu = s & 7;                        \
            CP_ASYNC16(_as + qoff(r, cu), A + (long)(bm + r) * lda + (k0) + cu * 8);  \
        }                                                                             \
        _Pragma("unroll")                                                             \
        for (int j = 0; j < 4; j++) {                                                 \
            int s = tid + 512 * j; int r = s >> 3, cu = s & 7;                        \
            CP_ASYNC16(_bs + qoff(r, cu), Bm + (long)(bn + r) * ldb + (k0) + cu * 8); \
        }                                                                             \
    } while (0)

    GH_ISSUE(0, 0); CP_COMMIT();
    GH_ISSUE(1, 64); CP_COMMIT();

    for (int ck = 0; ck < NC; ck++) {
        CP_WAIT1();
        __syncthreads();
        if (ck + 2 < NC) { int st = (ck + 2) % 3; GH_ISSUE(st, (ck + 2) << 6); }
        CP_COMMIT();
        uint32_t aBase = sb + (ck % 3) * STAGE, bBase = aBase + BOFF;
#pragma unroll
        for (int s = 0; s < 4; s++) {
            uint32_t af[2][4], bf[8][2];
#pragma unroll
            for (int mi = 0; mi < 2; mi++) {
                int m = wm + mi * 16 + (q2 & 1) * 8 + r7;
                LDSM_X4(af[mi][0], af[mi][1], af[mi][2], af[mi][3],
                        aBase + qoff(m, 2 * s + (q2 >> 1)));
            }
#pragma unroll
            for (int nj = 0; nj < 4; nj++) {
                int n = wn + nj * 16 + (q2 >> 1) * 8 + r7;
                LDSM_X4(bf[2 * nj][0], bf[2 * nj][1], bf[2 * nj + 1][0], bf[2 * nj + 1][1],
                        bBase + qoff(n, 2 * s + (q2 & 1)));
            }
#pragma unroll
            for (int mi = 0; mi < 2; mi++)
#pragma unroll
                for (int ni = 0; ni < 8; ni++)
                    mma16(acc[mi][ni], af[mi], bf[ni]);
        }
        __syncthreads();
    }
#undef GH_ISSUE

    __half* Ch = (__half*)C;
    float*  Cf = (float*)C;
#pragma unroll
    for (int mi = 0; mi < 2; mi++) {
#pragma unroll
        for (int rh = 0; rh < 2; rh++) {
            int row = bm + wm + mi * 16 + g + rh * 8;
#pragma unroll
            for (int ni = 0; ni < 8; ni++) {
                int n = bn + wn + ni * 8 + tq * 2;
                float v0 = acc[mi][ni][rh * 2], v1 = acc[mi][ni][rh * 2 + 1];
                if (BI) { v0 += bias[n]; v1 += bias[n + 1]; }
                if (HOUT) {
                    *(__half2*)(Ch + (long)row * ldc + n) = __floats2half2_rn(v0, v1);
                } else {
                    if (RE) {
                        float2 rv = *(const float2*)(resid + (long)row * ldc + n);
                        v0 += rv.x; v1 += rv.y;
                    }
                    float2 ov; ov.x = v0; ov.y = v1;
                    *(float2*)(Cf + (long)row * ldc + n) = ov;
                }
            }
        }
    }
}

// ---------------- MoE up: indexed-A grouped GEMM, GELU*gate epilogue --------
// grid (1, 128, E). A rows gathered via rowidx. N = H = 256, K = D = 1024.
__global__ void __launch_bounds__(512) gemm_up(
    const __half* __restrict__ Ah, const __half* __restrict__ w1t,
    __half* __restrict__ uws, const float* __restrict__ b1,
    const float* __restrict__ gd, const int* __restrict__ rowidx,
    const int* __restrict__ cnt) {
    constexpr int STAGE = 49152, BOFF = 16384;
    extern __shared__ __align__(16) char smdyn[];
    uint32_t sb = smem_u32(smdyn);

    int e = blockIdx.z;
    int c = cnt[e];
    int cp = (c + 127) & ~127;
    int bm = blockIdx.y * 128;
    if (bm >= cp) return;

    int tid = threadIdx.x, lane = tid & 31, warp = tid >> 5;
    int wm = (warp % 4) * 32, wn = (warp / 4) * 64;
    int g = lane >> 2, tq = lane & 3;
    int q2 = lane >> 3, r7 = lane & 7;
    const __half* Bp = w1t + (long)e * (H_ * D_);
    const int* ridx = rowidx + (long)e * CAP_;

    int tokA[2];
#pragma unroll
    for (int j = 0; j < 2; j++) {
        int r = (tid + 512 * j) >> 3;
        tokA[j] = ridx[bm + r];
    }

    float acc[2][8][4];
#pragma unroll
    for (int mi = 0; mi < 2; mi++)
#pragma unroll
        for (int ni = 0; ni < 8; ni++)
#pragma unroll
            for (int r = 0; r < 4; r++) acc[mi][ni][r] = 0.f;

#define UP_ISSUE(st, k0)                                                              \
    do {                                                                              \
        uint32_t _as = sb + (st) * STAGE, _bs = _as + BOFF;                           \
        _Pragma("unroll")                                                             \
        for (int j = 0; j < 2; j++) {                                                 \
            int s = tid + 512 * j; int r = s >> 3, cu = s & 7;                        \
            CP_ASYNC16(_as + qoff(r, cu), Ah + (long)tokA[j] * D_ + (k0) + cu * 8);   \
        }                                                                             \
        _Pragma("unroll")                                                             \
        for (int j = 0; j < 4; j++) {                                                 \
            int s = tid + 512 * j; int r = s >> 3, cu = s & 7;                        \
            CP_ASYNC16(_bs + qoff(r, cu), Bp + (long)r * D_ + (k0) + cu * 8);         \
        }                                                                             \
    } while (0)

    UP_ISSUE(0, 0); CP_COMMIT();
    UP_ISSUE(1, 64); CP_COMMIT();

    for (int ck = 0; ck < 16; ck++) {
        CP_WAIT1();
        __syncthreads();
        if (ck + 2 < 16) { int st = (ck + 2) % 3; UP_ISSUE(st, (ck + 2) << 6); }
        CP_COMMIT();
        uint32_t aBase = sb + (ck % 3) * STAGE, bBase = aBase + BOFF;
#pragma unroll
        for (int s = 0; s < 4; s++) {
            uint32_t af[2][4], bf[8][2];
#pragma unroll
            for (int mi = 0; mi < 2; mi++) {
                int m = wm + mi * 16 + (q2 & 1) * 8 + r7;
                LDSM_X4(af[mi][0], af[mi][1], af[mi][2], af[mi][3],
                        aBase + qoff(m, 2 * s + (q2 >> 1)));
            }
#pragma unroll
            for (int nj = 0; nj < 4; nj++) {
                int n = wn + nj * 16 + (q2 >> 1) * 8 + r7;
                LDSM_X4(bf[2 * nj][0], bf[2 * nj][1], bf[2 * nj + 1][0], bf[2 * nj + 1][1],
                        bBase + qoff(n, 2 * s + (q2 & 1)));
            }
#pragma unroll
            for (int mi = 0; mi < 2; mi++)
#pragma unroll
                for (int ni = 0; ni < 8; ni++)
                    mma16(acc[mi][ni], af[mi], bf[ni]);
        }
        __syncthreads();
    }
#undef UP_ISSUE

    const float* b1e = b1 + (long)e * H_;
#pragma unroll
    for (int mi = 0; mi < 2; mi++) {
#pragma unroll
        for (int rh = 0; rh < 2; rh++) {
            int row = bm + wm + mi * 16 + g + rh * 8;
            int tok = ridx[row];
            float gv = gd[(long)tok * 16 + e];
            __half* orow = uws + ((long)e * CAP_ + row) * H_;
#pragma unroll
            for (int ni = 0; ni < 8; ni++) {
                int n = wn + ni * 8 + tq * 2;
                float v0 = gelu_f(acc[mi][ni][rh * 2]     + b1e[n])     * gv;
                float v1 = gelu_f(acc[mi][ni][rh * 2 + 1] + b1e[n + 1]) * gv;
                *(__half2*)(orow + n) = __floats2half2_rn(v0, v1);
            }
        }
    }
}

// ---------------- MoE down: grouped GEMM, K=256 -----------------------------
// grid (4, 128, E). A = uws segment, B = w2te[e] ([D rows, H] K-major).
__global__ void __launch_bounds__(512) gemm_dn(
    const __half* __restrict__ uws, const __half* __restrict__ w2te,
    __half* __restrict__ outs, const int* __restrict__ cnt) {
    constexpr int STAGE = 49152, BOFF = 16384;
    extern __shared__ __align__(16) char smdyn[];
    uint32_t sb = smem_u32(smdyn);

    int e = blockIdx.z;
    int c = cnt[e];
    int cp = (c + 127) & ~127;
    int bm = blockIdx.y * 128;
    if (bm >= cp) return;
    int bn = blockIdx.x * 256;

    int tid = threadIdx.x, lane = tid & 31, warp = tid >> 5;
    int wm = (warp % 4) * 32, wn = (warp / 4) * 64;
    int g = lane >> 2, tq = lane & 3;
    int q2 = lane >> 3, r7 = lane & 7;
    const __half* Ap = uws + (long)e * CAP_ * H_;
    const __half* Bp = w2te + (long)e * (D_ * H_);

    float acc[2][8][4];
#pragma unroll
    for (int mi = 0; mi < 2; mi++)
#pragma unroll
        for (int ni = 0; ni < 8; ni++)
#pragma unroll
            for (int r = 0; r < 4; r++) acc[mi][ni][r] = 0.f;

#define DN_ISSUE(st, k0)                                                              \
    do {                                                                              \
        uint32_t _as = sb + (st) * STAGE, _bs = _as + BOFF;                           \
        _Pragma("unroll")                                                             \
        for (int j = 0; j < 2; j++) {                                                 \
            int s = tid + 512 * j; int r = s >> 3, cu = s & 7;                        \
            CP_ASYNC16(_as + qoff(r, cu), Ap + (long)(bm + r) * H_ + (k0) + cu * 8);  \
        }                                                                             \
        _Pragma("unroll")                                                             \
        for (int j = 0; j < 4; j++) {                                                 \
            int s = tid + 512 * j; int r = s >> 3, cu = s & 7;                        \
            CP_ASYNC16(_bs + qoff(r, cu), Bp + (long)(bn + r) * H_ + (k0) + cu * 8);  \
        }                                                                             \
    } while (0)

    DN_ISSUE(0, 0); CP_COMMIT();
    DN_ISSUE(1, 64); CP_COMMIT();

    for (int ck = 0; ck < 4; ck++) {
        CP_WAIT1();
        __syncthreads();
        if (ck + 2 < 4) { int st = (ck + 2) % 3; DN_ISSUE(st, (ck + 2) << 6); }
        CP_COMMIT();
        uint32_t aBase = sb + (ck % 3) * STAGE, bBase = aBase + BOFF;
#pragma unroll
        for (int s = 0; s < 4; s++) {
            uint32_t af[2][4], bf[8][2];
#pragma unroll
            for (int mi = 0; mi < 2; mi++) {
                int m = wm + mi * 16 + (q2 & 1) * 8 + r7;
                LDSM_X4(af[mi][0], af[mi][1], af[mi][2], af[mi][3],
                        aBase + qoff(m, 2 * s + (q2 >> 1)));
            }
#pragma unroll
            for (int nj = 0; nj < 4; nj++) {
                int n = wn + nj * 16 + (q2 >> 1) * 8 + r7;
                LDSM_X4(bf[2 * nj][0], bf[2 * nj][1], bf[2 * nj + 1][0], bf[2 * nj + 1][1],
                        bBase + qoff(n, 2 * s + (q2 & 1)));
            }
#pragma unroll
            for (int mi = 0; mi < 2; mi++)
#pragma unroll
                for (int ni = 0; ni < 8; ni++)
                    mma16(acc[mi][ni], af[mi], bf[ni]);
        }
        __syncthreads();
    }
#undef DN_ISSUE

#pragma unroll
    for (int mi = 0; mi < 2; mi++) {
#pragma unroll
        for (int rh = 0; rh < 2; rh++) {
            int row = bm + wm + mi * 16 + g + rh * 8;
            __half* orow = outs + ((long)e * CAP_ + row) * D_;
#pragma unroll
            for (int ni = 0; ni < 8; ni++) {
                int n = bn + wn + ni * 8 + tq * 2;
                *(__half2*)(orow + n) =
                    __floats2half2_rn(acc[mi][ni][rh * 2], acc[mi][ni][rh * 2 + 1]);
            }
        }
    }
}

// ---------------- gate: logits, softmax, probs, top-8 gates ----------------
__global__ void gate_kernel(const __half* __restrict__ h3, const float* __restrict__ gate_w,
                            const int* __restrict__ task_id,
                            float* __restrict__ probs, float* __restrict__ gate_dense) {
    long t = blockIdx.x;
    const float* gw = gate_w + (long)(*task_id) * (D_ * E_);
    const __half* row = h3 + t * D_;
    int tid = threadIdx.x;
    float acc[16];
#pragma unroll
    for (int e = 0; e < 16; e++) acc[e] = 0.f;
    for (int d = tid; d < D_; d += 128) {
        float hv = __half2float(row[d]);
        const float* g = gw + (long)d * 16;
#pragma unroll
        for (int e = 0; e < 16; e++) acc[e] += hv * g[e];
    }
    __shared__ float red[128][17];
#pragma unroll
    for (int e = 0; e < 16; e++) red[tid][e] = acc[e];
    __syncthreads();
    for (int s = 64; s; s >>= 1) {
        if (tid < s) {
#pragma unroll
            for (int e = 0; e < 16; e++) red[tid][e] += red[tid + s][e];
        }
        __syncthreads();
    }
    if (tid == 0) {
        float lg[16], mx = -1e30f;
#pragma unroll
        for (int e = 0; e < 16; e++) { lg[e] = red[0][e]; mx = fmaxf(mx, lg[e]); }
        float sum = 0.f;
#pragma unroll
        for (int e = 0; e < 16; e++) { lg[e] = expf(lg[e] - mx); sum += lg[e]; }
        float inv = 1.f / sum;
        float p[16];
#pragma unroll
        for (int e = 0; e < 16; e++) { p[e] = lg[e] * inv; probs[t * 16 + e] = p[e]; }
        bool used[16];
#pragma unroll
        for (int e = 0; e < 16; e++) used[e] = false;
        int tidx[8]; float tval[8]; float gsum = 0.f;
        for (int kk = 0; kk < 8; kk++) {
            float best = -1.f; int bi = 0;
            for (int e = 0; e < 16; e++)
                if (!used[e] && p[e] > best) { best = p[e]; bi = e; }
            used[bi] = true; tidx[kk] = bi; tval[kk] = best; gsum += best;
        }
        float ginv = 1.f / (gsum + 1e-6f);
        float gd[16];
#pragma unroll
        for (int e = 0; e < 16; e++) gd[e] = 0.f;
        for (int kk = 0; kk < 8; kk++) gd[tidx[kk]] = tval[kk] * ginv;
#pragma unroll
        for (int e = 0; e < 16; e++) gate_dense[t * 16 + e] = gd[e];
    }
}

// ---------------- routing ----------------------------------------------------
__global__ void zero_cnt(int* cnt) {
    if (threadIdx.x < E_) cnt[threadIdx.x] = 0;
}
__global__ void route_k(const float* __restrict__ gd, int* __restrict__ cnt,
                        int* __restrict__ rowidx, int* __restrict__ pairpos) {
    int t = blockIdx.x * 128 + threadIdx.x;
    int k = 0;
#pragma unroll
    for (int e = 0; e < E_; e++) {
        float v = gd[(long)t * 16 + e];
        if (v > 0.f && k < 8) {
            int pos = atomicAdd(&cnt[e], 1);
            rowidx[(long)e * CAP_ + pos] = t;
            pairpos[(long)t * 8 + k] = e * CAP_ + pos;
            k++;
        }
    }
}

// ---------------- gather: out = x + sum_k outs[pp[k]] + gd @ b2 --------------
__global__ void gather_k(const float* __restrict__ x, const __half* __restrict__ outs,
                         const int* __restrict__ pairpos, const float* __restrict__ gd,
                         const float* __restrict__ b2, float* __restrict__ out) {
    long t = blockIdx.x;
    __shared__ int pp[8];
    __shared__ float gdv[16];
    int tid = threadIdx.x;
    if (tid < 8) pp[tid] = pairpos[t * 8 + tid];
    if (tid < 16) gdv[tid] = gd[t * 16 + tid];
    __syncthreads();
    int d = tid * 4;
    float4 a = *(const float4*)(x + t * D_ + d);
#pragma unroll
    for (int k = 0; k < 8; k++) {
        const __half2* o2 = (const __half2*)(outs + (long)pp[k] * D_ + d);
        float2 f0 = __half22float2(o2[0]), f1 = __half22float2(o2[1]);
        a.x += f0.x; a.y += f0.y; a.z += f1.x; a.w += f1.y;
    }
#pragma unroll
    for (int e = 0; e < 16; e++) {
        float4 bv = *(const float4*)(b2 + (long)e * D_ + d);
        float gv = gdv[e];
        a.x += gv * bv.x; a.y += gv * bv.y; a.z += gv * bv.z; a.w += gv * bv.w;
    }
    *(float4*)(out + t * D_ + d) = a;
}

// ---------------- aux loss ---------------------------------------------------
__global__ void aux_kernel(const float* __restrict__ probs, float* __restrict__ outv) {
    int tid = threadIdx.x;
    float acc[16];
#pragma unroll
    for (int e = 0; e < 16; e++) acc[e] = 0.f;
    for (int t = tid; t < T_; t += 256) {
        const float* p = probs + (long)t * 16;
#pragma unroll
        for (int e = 0; e < 16; e++) acc[e] += p[e];
    }
    __shared__ float red[256][17];
#pragma unroll
    for (int e = 0; e < 16; e++) red[tid][e] = acc[e];
    __syncthreads();
    for (int s = 128; s; s >>= 1) {
        if (tid < s) {
#pragma unroll
            for (int e = 0; e < 16; e++) red[tid][e] += red[tid + s][e];
        }
        __syncthreads();
    }
    if (tid == 0) {
        float aux = 0.f;
#pragma unroll
        for (int e = 0; e < 16; e++) {
            float mp = red[0][e] * (1.f / T_);
            aux += mp * logf(mp + 1e-6f);
        }
        outv[0] = 5e-4f * aux;
    }
}

// ---------------- launch -----------------------------------------------------
extern "C" void kernel_launch(void* const* d_in, const int* in_sizes, int n_in,
                              void* d_out, int out_size) {
    const float* tgt        = (const float*)d_in[0];
    const float* ln1_g      = (const float*)d_in[2];
    const float* ln1_b      = (const float*)d_in[3];
    const float* ln3_g      = (const float*)d_in[4];
    const float* ln3_b      = (const float*)d_in[5];
    const float* in_proj_w  = (const float*)d_in[6];
    const float* in_proj_b  = (const float*)d_in[7];
    const float* out_proj_w = (const float*)d_in[8];
    const float* out_proj_b = (const float*)d_in[9];
    const float* gate_w     = (const float*)d_in[10];
    const float* w1         = (const float*)d_in[11];
    const float* b1         = (const float*)d_in[12];
    const float* w2         = (const float*)d_in[13];
    const float* b2         = (const float*)d_in[14];
    const int*   task_id    = (const int*)d_in[15];

    float* out       = (float*)d_out;
    float* out_x     = out;
    float* out_aux   = out + (size_t)T_ * D_;
    float* out_probs = out_aux + 1;

    __half *h16, *qkv16, *vt16, *ctx16, *wi16, *wo16, *w1t16, *w2te16, *uws, *outs;
    float *x, *gd;
    int *cnt, *rowidx, *pairpos;
    cudaGetSymbolAddress((void**)&h16,    g_h16);
    cudaGetSymbolAddress((void**)&qkv16,  g_qkv16);
    cudaGetSymbolAddress((void**)&vt16,   g_vt16);
    cudaGetSymbolAddress((void**)&ctx16,  g_ctx16);
    cudaGetSymbolAddress((void**)&x,      g_x);
    cudaGetSymbolAddress((void**)&gd,     g_gate);
    cudaGetSymbolAddress((void**)&wi16,   g_wi16);
    cudaGetSymbolAddress((void**)&wo16,   g_wo16);
    cudaGetSymbolAddress((void**)&w1t16,  g_w1t16);
    cudaGetSymbolAddress((void**)&w2te16, g_w2te16);
    cudaGetSymbolAddress((void**)&uws,    g_uws);
    cudaGetSymbolAddress((void**)&outs,   g_outs);
    cudaGetSymbolAddress((void**)&cnt,    g_cnt);
    cudaGetSymbolAddress((void**)&rowidx, g_rowidx);
    cudaGetSymbolAddress((void**)&pairpos,g_pairpos);

    const int GSM = 3 * 49152;
    cudaFuncSetAttribute(gemm_h<true, false, true >, cudaFuncAttributeMaxDynamicSharedMemorySize, GSM);
    cudaFuncSetAttribute(gemm_h<true, true,  false>, cudaFuncAttributeMaxDynamicSharedMemorySize, GSM);
    cudaFuncSetAttribute(gemm_up, cudaFuncAttributeMaxDynamicSharedMemorySize, GSM);
    cudaFuncSetAttribute(gemm_dn, cudaFuncAttributeMaxDynamicSharedMemorySize, GSM);

    // 0. weight preprocessing
    conv_f2h<<<(unsigned)(3L * D_ * D_ / 1024), 256>>>(in_proj_w, wi16, 3L * D_ * D_);
    conv_f2h<<<(unsigned)(1L * D_ * D_ / 1024), 256>>>(out_proj_w, wo16, 1L * D_ * D_);
    transpose_h<float><<<dim3(8, 32, E_), 256>>>(
        w1, w1t16, D_, H_, H_, (long)D_ * H_, 0, (long)H_ * D_, 0, 1);
    transpose_h<float><<<dim3(32, 8, E_), 256>>>(
        w2, w2te16, H_, D_, D_, (long)H_ * D_, 0, (long)D_ * H_, 0, 1);

    // 1. h = LN1(tgt)
    ln_kernel<<<T_, 256>>>(tgt, ln1_g, ln1_b, h16);

    // 2. qkv = h @ in_proj_w^T + b (half out)
    gemm_h<true, false, true><<<dim3(12, 128), 512, GSM>>>(
        h16, wi16, qkv16, in_proj_b, nullptr, D_, D_, D_, 3 * D_);

    // 3. Vt = V^T per (b,h)
    transpose_h<__half><<<dim3(2, 16, B_ * NH_), 256>>>(
        qkv16 + 2 * D_, vt16, S_, DH_, 3 * D_,
        (long)S_ * 3 * D_, DH_, (long)NH_ * DH_ * S_, (long)DH_ * S_, NH_);

    // 4. fused flash attention -> ctx16
    flash_k<<<dim3(4, B_ * NH_), 256>>>(qkv16, vt16, ctx16);

    // 5. x = tgt + ctx @ out_proj_w^T + b (fp32 out)
    gemm_h<true, true, false><<<dim3(4, 128), 512, GSM>>>(
        ctx16, wo16, x, out_proj_b, tgt, D_, D_, D_, D_);

    // 6. h3 = LN3(x)
    ln_kernel<<<T_, 256>>>(x, ln3_g, ln3_b, h16);

    // 7. gate / aux
    gate_kernel<<<T_, 128>>>(h16, gate_w, task_id, out_probs, gd);
    aux_kernel<<<1, 256>>>(out_probs, out_aux);

    // 8. routing
    zero_cnt<<<1, 32>>>(cnt);
    route_k<<<T_ / 128, 128>>>(gd, cnt, rowidx, pairpos);

    // 9. sparse MoE up: uws = gelu(h3[gathered] @ w1[e] + b1[e]) * gate
    gemm_up<<<dim3(1, 128, E_), 512, GSM>>>(h16, w1t16, uws, b1, gd, rowidx, cnt);

    // 10. sparse MoE down: outs = uws @ w2[e]
    gemm_dn<<<dim3(4, 128, E_), 512, GSM>>>(uws, w2te16, outs, cnt);

    // 11. gather: out = x + sum_k outs + gd @ b2
    gather_k<<<T_, 256>>>(x, outs, pairpos, gd, b2, out_x);

    (void)in_sizes; (void)n_in; (void)out_size;
}

// round 9
// speedup vs baseline: 11.3029x; 1.3322x over previous
#include <cuda_runtime.h>
#include <cuda_fp16.h>
#include <math.h>
#include <stdint.h>

#define B_   32
#define S_   512
#define D_   1024
#define NH_  16
#define E_   16
#define H_   256
#define DH_  64
#define T_   (B_ * S_)          // 16384
#define CAP_ 16384

// ---------------- scratch (static device memory) ---------------------------
__device__ __half g_h16[(size_t)T_ * D_];
__device__ __half g_qkv16[(size_t)T_ * 3 * D_];
__device__ __half g_vt16[(size_t)B_ * NH_ * DH_ * S_];
__device__ __half g_ctx16[(size_t)T_ * D_];
__device__ float  g_x[(size_t)T_ * D_];
__device__ float  g_gate[(size_t)T_ * E_];
__device__ __half g_wi16[(size_t)3 * D_ * D_];
__device__ __half g_wo16[(size_t)D_ * D_];
__device__ __half g_w1t16[(size_t)E_ * H_ * D_];
__device__ __half g_w2te16[(size_t)E_ * D_ * H_];
__device__ __half g_uws[(size_t)E_ * CAP_ * H_];
__device__ __half g_outs[(size_t)E_ * CAP_ * D_];
__device__ int    g_cnt[E_];
__device__ int    g_rowidx[(size_t)E_ * CAP_];
__device__ int    g_pairpos[(size_t)T_ * 8];
__device__ float  g_auxp[64 * E_];

// ---------------- helpers ---------------------------------------------------
__device__ __forceinline__ uint32_t smem_u32(const void* p) {
    uint32_t a;
    asm("{ .reg .u64 t; cvta.to.shared.u64 t, %1; cvt.u32.u64 %0, t; }" : "=r"(a) : "l"(p));
    return a;
}
__device__ __forceinline__ uint32_t h2_as_u32(__half2 h) {
    return *reinterpret_cast<uint32_t*>(&h);
}
#define CP_ASYNC16(dst, src) \
    asm volatile("cp.async.ca.shared.global [%0], [%1], 16;" :: "r"(dst), "l"(src) : "memory")
#define CP_COMMIT() asm volatile("cp.async.commit_group;" ::: "memory")
#define CP_WAIT1()  asm volatile("cp.async.wait_group 1;" ::: "memory")
#define CP_WAIT0()  asm volatile("cp.async.wait_group 0;" ::: "memory")

#define LDSM_X4(r0, r1, r2, r3, addr) \
    asm volatile("ldmatrix.sync.aligned.m8n8.x4.shared.b16 {%0,%1,%2,%3}, [%4];" \
        : "=r"(r0), "=r"(r1), "=r"(r2), "=r"(r3) : "r"(addr))

__device__ __forceinline__ void mma16(float* d, const uint32_t* a, const uint32_t* b) {
    asm volatile(
        "mma.sync.aligned.m16n8k16.row.col.f32.f16.f16.f32 "
        "{%0,%1,%2,%3},{%4,%5,%6,%7},{%8,%9},{%0,%1,%2,%3};"
        : "+f"(d[0]), "+f"(d[1]), "+f"(d[2]), "+f"(d[3])
        : "r"(a[0]), "r"(a[1]), "r"(a[2]), "r"(a[3]), "r"(b[0]), "r"(b[1]));
}

// smem tile: 64 halfs (128B) per row, SW128
__device__ __forceinline__ uint32_t qoff(int m, int c) {
    return (uint32_t)(m * 128 + ((c ^ (m & 7)) << 4));
}
__device__ __forceinline__ float gelu_f(float v) {
    return 0.5f * v * (1.f + erff(v * 0.70710678118654752f));
}

// ---------------- LayerNorm (fp32 in -> half out) ---------------------------
__global__ void ln_kernel(const float* __restrict__ x, const float* __restrict__ g,
                          const float* __restrict__ b, __half* __restrict__ y16) {
    long t = blockIdx.x;
    const float* row = x + t * D_;
    int tid = threadIdx.x;
    float v[4];
    float s = 0.f, sq = 0.f;
#pragma unroll
    for (int i = 0; i < 4; i++) {
        v[i] = row[tid + i * 256];
        s += v[i]; sq += v[i] * v[i];
    }
#pragma unroll
    for (int o = 16; o; o >>= 1) {
        s  += __shfl_xor_sync(0xffffffffu, s, o);
        sq += __shfl_xor_sync(0xffffffffu, sq, o);
    }
    __shared__ float ws[8], wq[8];
    int w = tid >> 5, l = tid & 31;
    if (l == 0) { ws[w] = s; wq[w] = sq; }
    __syncthreads();
    if (tid == 0) {
        float a = 0.f, c = 0.f;
        for (int i = 0; i < 8; i++) { a += ws[i]; c += wq[i]; }
        ws[0] = a; wq[0] = c;
    }
    __syncthreads();
    float mean = ws[0] * (1.f / D_);
    float var  = wq[0] * (1.f / D_) - mean * mean;
    float inv  = rsqrtf(var + 1e-5f);
#pragma unroll
    for (int i = 0; i < 4; i++) {
        int d = tid + i * 256;
        y16[t * D_ + d] = __float2half((v[i] - mean) * inv * g[d] + b[d]);
    }
}

// ---------------- fp32 -> fp16 convert --------------------------------------
__global__ void conv_f2h(const float* __restrict__ in, __half* __restrict__ out, long n) {
    long i = (long)blockIdx.x * 1024 + threadIdx.x * 4;
    if (i < n) {
        float4 v = *(const float4*)(in + i);
        *(__half2*)(out + i)     = __floats2half2_rn(v.x, v.y);
        *(__half2*)(out + i + 2) = __floats2half2_rn(v.z, v.w);
    }
}

// ---------------- batched tiled transpose -> half ---------------------------
template <typename TI>
__global__ void transpose_h(const TI* __restrict__ src, __half* __restrict__ dst,
                            int R, int C, long srcRS,
                            long sSo, long sSi, long sDo, long sDi, int nInner) {
    int zo = blockIdx.z / nInner, zi = blockIdx.z - zo * nInner;
    src += (long)zo * sSo + (long)zi * sSi;
    dst += (long)zo * sDo + (long)zi * sDi;
    __shared__ float tile[32][33];
    int r0 = blockIdx.y * 32, c0 = blockIdx.x * 32;
    int tx = threadIdx.x & 31, ty = threadIdx.x >> 5;
#pragma unroll
    for (int k = 0; k < 4; k++) {
        int r = r0 + ty + 8 * k;
        if (r < R && c0 + tx < C) tile[ty + 8 * k][tx] = (float)src[(long)r * srcRS + c0 + tx];
    }
    __syncthreads();
#pragma unroll
    for (int k = 0; k < 4; k++) {
        int c = c0 + ty + 8 * k;
        if (c < C && r0 + tx < R) dst[(long)c * R + r0 + tx] = __float2half(tile[tx][ty + 8 * k]);
    }
}

// ---------------- fused flash attention (unchanged, validated) --------------
__global__ void __launch_bounds__(256) flash_k(
    const __half* __restrict__ qkv, const __half* __restrict__ vt,
    __half* __restrict__ ctx) {
    int bh = blockIdx.y;
    int b = bh >> 4, hh = bh & 15;
    int qb = blockIdx.x;
    const __half* Qb = qkv + ((long)b * S_ + qb * 128) * (3 * D_) + hh * DH_;
    const __half* Kb = qkv + (long)b * S_ * (3 * D_) + D_ + hh * DH_;
    const __half* Vb = vt + (long)bh * DH_ * S_;

    __shared__ __align__(16) __half Qs[128 * 64];
    __shared__ __align__(16) __half Ks[2][64 * 64];
    __shared__ __align__(16) __half Vs[2][64 * 64];
    uint32_t qB = smem_u32(Qs), kB = smem_u32(Ks), vB = smem_u32(Vs);

    int tid = threadIdx.x, lane = tid & 31, warp = tid >> 5;
    int wm = warp * 16;
    int g = lane >> 2, tq = lane & 3;
    int q2 = lane >> 3, r7 = lane & 7;
    const float L2E = 1.44269504088896f;

#pragma unroll
    for (int j = 0; j < 4; j++) {
        int s = tid + 256 * j;
        int r = s >> 3, cu = s & 7;
        CP_ASYNC16(qB + qoff(r, cu), Qb + (long)r * (3 * D_) + cu * 8);
    }
    CP_COMMIT();
#pragma unroll
    for (int j = 0; j < 2; j++) {
        int s = tid + 256 * j;
        int r = s >> 3, cu = s & 7;
        CP_ASYNC16(kB + qoff(r, cu), Kb + (long)r * (3 * D_) + cu * 8);
        CP_ASYNC16(vB + qoff(r, cu), Vb + (long)r * S_ + cu * 8);
    }
    CP_COMMIT();
    CP_WAIT0();
    __syncthreads();
    {
        __half2 sc = __floats2half2_rn(0.125f, 0.125f);
        __half2* qh = (__half2*)Qs;
#pragma unroll
        for (int i = 0; i < 16; i++) qh[tid + 256 * i] = __hmul2(qh[tid + 256 * i], sc);
    }
    __syncthreads();

    float o[8][4];
#pragma unroll
    for (int ni = 0; ni < 8; ni++)
#pragma unroll
        for (int r = 0; r < 4; r++) o[ni][r] = 0.f;
    float m0 = -1e30f, m1 = -1e30f, l0 = 0.f, l1 = 0.f;

    for (int c = 0; c < 8; c++) {
        int buf = c & 1;
        if (c + 1 < 8) {
            int nb = 1 - buf;
#pragma unroll
            for (int j = 0; j < 2; j++) {
                int s = tid + 256 * j;
                int r = s >> 3, cu = s & 7;
                CP_ASYNC16(kB + nb * 8192 + qoff(r, cu),
                           Kb + (long)((c + 1) * 64 + r) * (3 * D_) + cu * 8);
                CP_ASYNC16(vB + nb * 8192 + qoff(r, cu),
                           Vb + (long)r * S_ + (c + 1) * 64 + cu * 8);
            }
            CP_COMMIT();
            CP_WAIT1();
        } else {
            CP_WAIT0();
        }
        __syncthreads();

        uint32_t kBuf = kB + buf * 8192, vBuf = vB + buf * 8192;
        float sv[8][4];
#pragma unroll
        for (int ni = 0; ni < 8; ni++)
#pragma unroll
            for (int r = 0; r < 4; r++) sv[ni][r] = 0.f;
#pragma unroll
        for (int ks = 0; ks < 4; ks++) {
            uint32_t af[4], bf[8][2];
            int am = wm + (q2 & 1) * 8 + r7;
            LDSM_X4(af[0], af[1], af[2], af[3], qB + qoff(am, 2 * ks + (q2 >> 1)));
#pragma unroll
            for (int nj = 0; nj < 4; nj++) {
                int bn = nj * 16 + (q2 >> 1) * 8 + r7;
                LDSM_X4(bf[2 * nj][0], bf[2 * nj][1], bf[2 * nj + 1][0], bf[2 * nj + 1][1],
                        kBuf + qoff(bn, 2 * ks + (q2 & 1)));
            }
#pragma unroll
            for (int ni = 0; ni < 8; ni++) mma16(sv[ni], af, bf[ni]);
        }

        float cm0 = -1e30f, cm1 = -1e30f;
#pragma unroll
        for (int ni = 0; ni < 8; ni++) {
            cm0 = fmaxf(cm0, fmaxf(sv[ni][0], sv[ni][1]));
            cm1 = fmaxf(cm1, fmaxf(sv[ni][2], sv[ni][3]));
        }
        cm0 = fmaxf(cm0, __shfl_xor_sync(0xffffffffu, cm0, 1));
        cm0 = fmaxf(cm0, __shfl_xor_sync(0xffffffffu, cm0, 2));
        cm1 = fmaxf(cm1, __shfl_xor_sync(0xffffffffu, cm1, 1));
        cm1 = fmaxf(cm1, __shfl_xor_sync(0xffffffffu, cm1, 2));
        float mn0 = fmaxf(m0, cm0), mn1 = fmaxf(m1, cm1);
        float sc0 = exp2f((m0 - mn0) * L2E), sc1 = exp2f((m1 - mn1) * L2E);
        m0 = mn0; m1 = mn1;
        l0 *= sc0; l1 *= sc1;
#pragma unroll
        for (int ni = 0; ni < 8; ni++) {
            o[ni][0] *= sc0; o[ni][1] *= sc0;
            o[ni][2] *= sc1; o[ni][3] *= sc1;
        }
        uint32_t pa[4][4];
        float rs0 = 0.f, rs1 = 0.f;
#pragma unroll
        for (int ni = 0; ni < 8; ni++) {
            float p0 = exp2f((sv[ni][0] - mn0) * L2E);
            float p1 = exp2f((sv[ni][1] - mn0) * L2E);
            float p2 = exp2f((sv[ni][2] - mn1) * L2E);
            float p3 = exp2f((sv[ni][3] - mn1) * L2E);
            rs0 += p0 + p1; rs1 += p2 + p3;
            int kk = ni >> 1, hi = ni & 1;
            pa[kk][hi * 2]     = h2_as_u32(__floats2half2_rn(p0, p1));
            pa[kk][hi * 2 + 1] = h2_as_u32(__floats2half2_rn(p2, p3));
        }
        rs0 += __shfl_xor_sync(0xffffffffu, rs0, 1);
        rs0 += __shfl_xor_sync(0xffffffffu, rs0, 2);
        rs1 += __shfl_xor_sync(0xffffffffu, rs1, 1);
        rs1 += __shfl_xor_sync(0xffffffffu, rs1, 2);
        l0 += rs0; l1 += rs1;

#pragma unroll
        for (int ks = 0; ks < 4; ks++) {
            uint32_t bf[8][2];
#pragma unroll
            for (int nj = 0; nj < 4; nj++) {
                int bn = nj * 16 + (q2 >> 1) * 8 + r7;
                LDSM_X4(bf[2 * nj][0], bf[2 * nj][1], bf[2 * nj + 1][0], bf[2 * nj + 1][1],
                        vBuf + qoff(bn, 2 * ks + (q2 & 1)));
            }
#pragma unroll
            for (int ni = 0; ni < 8; ni++) mma16(o[ni], pa[ks], bf[ni]);
        }
        __syncthreads();
    }

    float li0 = 1.f / l0, li1 = 1.f / l1;
    long row0 = (long)b * S_ + qb * 128 + wm + g;
    __half* c0p = ctx + (row0)     * D_ + hh * DH_;
    __half* c1p = ctx + (row0 + 8) * D_ + hh * DH_;
#pragma unroll
    for (int ni = 0; ni < 8; ni++) {
        int nc = ni * 8 + tq * 2;
        *(__half2*)(c0p + nc) = __floats2half2_rn(o[ni][0] * li0, o[ni][1] * li0);
        *(__half2*)(c1p + nc) = __floats2half2_rn(o[ni][2] * li1, o[ni][3] * li1);
    }
}

// ---------------- fp16 GEMM: 128x128 tile, BK=64, 3 stages, 2 CTAs/SM -------
template <bool BI, bool RE, bool HOUT>
__global__ void __launch_bounds__(256, 2) gemm_h(
    const __half* __restrict__ A, const __half* __restrict__ Bm, void* __restrict__ C,
    const float* __restrict__ bias, const float* __restrict__ resid,
    int Kd, int lda, int ldb, int ldc) {
    constexpr int STAGE = 32768, BOFF = 16384;
    extern __shared__ __align__(16) char smdyn[];
    uint32_t sb = smem_u32(smdyn);

    int tid = threadIdx.x, lane = tid & 31, warp = tid >> 5;
    int bm = blockIdx.y * 128, bn = blockIdx.x * 128;
    int wm = (warp % 4) * 32, wn = (warp / 4) * 64;
    int g = lane >> 2, tq = lane & 3;
    int q2 = lane >> 3, r7 = lane & 7;

    float acc[2][8][4];
#pragma unroll
    for (int mi = 0; mi < 2; mi++)
#pragma unroll
        for (int ni = 0; ni < 8; ni++)
#pragma unroll
            for (int r = 0; r < 4; r++) acc[mi][ni][r] = 0.f;

    int NC = Kd >> 6;
#define GH_ISSUE(st, k0)                                                              \
    do {                                                                              \
        uint32_t _as = sb + (st) * STAGE, _bs = _as + BOFF;                           \
        _Pragma("unroll")                                                             \
        for (int j = 0; j < 4; j++) {                                                 \
            int s = tid + 256 * j; int r = s >> 3, cu = s & 7;                        \
            CP_ASYNC16(_as + qoff(r, cu), A + (long)(bm + r) * lda + (k0) + cu * 8);  \
            CP_ASYNC16(_bs + qoff(r, cu), Bm + (long)(bn + r) * ldb + (k0) + cu * 8); \
        }                                                                             \
    } while (0)

    GH_ISSUE(0, 0); CP_COMMIT();
    GH_ISSUE(1, 64); CP_COMMIT();

    for (int ck = 0; ck < NC; ck++) {
        CP_WAIT1();
        __syncthreads();
        if (ck + 2 < NC) { int st = (ck + 2) % 3; GH_ISSUE(st, (ck + 2) << 6); }
        CP_COMMIT();
        uint32_t aBase = sb + (ck % 3) * STAGE, bBase = aBase + BOFF;
#pragma unroll
        for (int s = 0; s < 4; s++) {
            uint32_t af[2][4], bf[8][2];
#pragma unroll
            for (int mi = 0; mi < 2; mi++) {
                int m = wm + mi * 16 + (q2 & 1) * 8 + r7;
                LDSM_X4(af[mi][0], af[mi][1], af[mi][2], af[mi][3],
                        aBase + qoff(m, 2 * s + (q2 >> 1)));
            }
#pragma unroll
            for (int nj = 0; nj < 4; nj++) {
                int n = wn + nj * 16 + (q2 >> 1) * 8 + r7;
                LDSM_X4(bf[2 * nj][0], bf[2 * nj][1], bf[2 * nj + 1][0], bf[2 * nj + 1][1],
                        bBase + qoff(n, 2 * s + (q2 & 1)));
            }
#pragma unroll
            for (int mi = 0; mi < 2; mi++)
#pragma unroll
                for (int ni = 0; ni < 8; ni++)
                    mma16(acc[mi][ni], af[mi], bf[ni]);
        }
        __syncthreads();
    }
#undef GH_ISSUE

    __half* Ch = (__half*)C;
    float*  Cf = (float*)C;
#pragma unroll
    for (int mi = 0; mi < 2; mi++) {
#pragma unroll
        for (int rh = 0; rh < 2; rh++) {
            int row = bm + wm + mi * 16 + g + rh * 8;
#pragma unroll
            for (int ni = 0; ni < 8; ni++) {
                int n = bn + wn + ni * 8 + tq * 2;
                float v0 = acc[mi][ni][rh * 2], v1 = acc[mi][ni][rh * 2 + 1];
                if (BI) { v0 += bias[n]; v1 += bias[n + 1]; }
                if (HOUT) {
                    *(__half2*)(Ch + (long)row * ldc + n) = __floats2half2_rn(v0, v1);
                } else {
                    if (RE) {
                        float2 rv = *(const float2*)(resid + (long)row * ldc + n);
                        v0 += rv.x; v1 += rv.y;
                    }
                    float2 ov; ov.x = v0; ov.y = v1;
                    *(float2*)(Cf + (long)row * ldc + n) = ov;
                }
            }
        }
    }
}

// ---------------- MoE up: indexed-A grouped GEMM, GELU*gate epilogue --------
// grid (2, 128, E). 128x128 tile. N = H = 256, K = D = 1024.
__global__ void __launch_bounds__(256, 2) gemm_up(
    const __half* __restrict__ Ah, const __half* __restrict__ w1t,
    __half* __restrict__ uws, const float* __restrict__ b1,
    const float* __restrict__ gd, const int* __restrict__ rowidx,
    const int* __restrict__ cnt) {
    constexpr int STAGE = 32768, BOFF = 16384;
    extern __shared__ __align__(16) char smdyn[];
    uint32_t sb = smem_u32(smdyn);

    int e = blockIdx.z;
    int c = cnt[e];
    int cp = (c + 127) & ~127;
    int bm = blockIdx.y * 128;
    if (bm >= cp) return;
    int bn = blockIdx.x * 128;

    int tid = threadIdx.x, lane = tid & 31, warp = tid >> 5;
    int wm = (warp % 4) * 32, wn = (warp / 4) * 64;
    int g = lane >> 2, tq = lane & 3;
    int q2 = lane >> 3, r7 = lane & 7;
    const __half* Bp = w1t + (long)e * (H_ * D_);
    const int* ridx = rowidx + (long)e * CAP_;

    int tokA[4];
#pragma unroll
    for (int j = 0; j < 4; j++) {
        int r = (tid + 256 * j) >> 3;
        tokA[j] = ridx[bm + r];
    }

    float acc[2][8][4];
#pragma unroll
    for (int mi = 0; mi < 2; mi++)
#pragma unroll
        for (int ni = 0; ni < 8; ni++)
#pragma unroll
            for (int r = 0; r < 4; r++) acc[mi][ni][r] = 0.f;

#define UP_ISSUE(st, k0)                                                              \
    do {                                                                              \
        uint32_t _as = sb + (st) * STAGE, _bs = _as + BOFF;                           \
        _Pragma("unroll")                                                             \
        for (int j = 0; j < 4; j++) {                                                 \
            int s = tid + 256 * j; int r = s >> 3, cu = s & 7;                        \
            CP_ASYNC16(_as + qoff(r, cu), Ah + (long)tokA[j] * D_ + (k0) + cu * 8);   \
            CP_ASYNC16(_bs + qoff(r, cu), Bp + (long)(bn + r) * D_ + (k0) + cu * 8);  \
        }                                                                             \
    } while (0)

    UP_ISSUE(0, 0); CP_COMMIT();
    UP_ISSUE(1, 64); CP_COMMIT();

    for (int ck = 0; ck < 16; ck++) {
        CP_WAIT1();
        __syncthreads();
        if (ck + 2 < 16) { int st = (ck + 2) % 3; UP_ISSUE(st, (ck + 2) << 6); }
        CP_COMMIT();
        uint32_t aBase = sb + (ck % 3) * STAGE, bBase = aBase + BOFF;
#pragma unroll
        for (int s = 0; s < 4; s++) {
            uint32_t af[2][4], bf[8][2];
#pragma unroll
            for (int mi = 0; mi < 2; mi++) {
                int m = wm + mi * 16 + (q2 & 1) * 8 + r7;
                LDSM_X4(af[mi][0], af[mi][1], af[mi][2], af[mi][3],
                        aBase + qoff(m, 2 * s + (q2 >> 1)));
            }
#pragma unroll
            for (int nj = 0; nj < 4; nj++) {
                int n = wn + nj * 16 + (q2 >> 1) * 8 + r7;
                LDSM_X4(bf[2 * nj][0], bf[2 * nj][1], bf[2 * nj + 1][0], bf[2 * nj + 1][1],
                        bBase + qoff(n, 2 * s + (q2 & 1)));
            }
#pragma unroll
            for (int mi = 0; mi < 2; mi++)
#pragma unroll
                for (int ni = 0; ni < 8; ni++)
                    mma16(acc[mi][ni], af[mi], bf[ni]);
        }
        __syncthreads();
    }
#undef UP_ISSUE

    const float* b1e = b1 + (long)e * H_;
#pragma unroll
    for (int mi = 0; mi < 2; mi++) {
#pragma unroll
        for (int rh = 0; rh < 2; rh++) {
            int row = bm + wm + mi * 16 + g + rh * 8;
            int tok = ridx[row];
            float gv = gd[(long)tok * 16 + e];
            __half* orow = uws + ((long)e * CAP_ + row) * H_;
#pragma unroll
            for (int ni = 0; ni < 8; ni++) {
                int n = bn + wn + ni * 8 + tq * 2;
                float v0 = gelu_f(acc[mi][ni][rh * 2]     + b1e[n])     * gv;
                float v1 = gelu_f(acc[mi][ni][rh * 2 + 1] + b1e[n + 1]) * gv;
                *(__half2*)(orow + n) = __floats2half2_rn(v0, v1);
            }
        }
    }
}

// ---------------- MoE down: grouped GEMM, K=256 -----------------------------
// grid (8, 128, E). 128x128 tile.
__global__ void __launch_bounds__(256, 2) gemm_dn(
    const __half* __restrict__ uws, const __half* __restrict__ w2te,
    __half* __restrict__ outs, const int* __restrict__ cnt) {
    constexpr int STAGE = 32768, BOFF = 16384;
    extern __shared__ __align__(16) char smdyn[];
    uint32_t sb = smem_u32(smdyn);

    int e = blockIdx.z;
    int c = cnt[e];
    int cp = (c + 127) & ~127;
    int bm = blockIdx.y * 128;
    if (bm >= cp) return;
    int bn = blockIdx.x * 128;

    int tid = threadIdx.x, lane = tid & 31, warp = tid >> 5;
    int wm = (warp % 4) * 32, wn = (warp / 4) * 64;
    int g = lane >> 2, tq = lane & 3;
    int q2 = lane >> 3, r7 = lane & 7;
    const __half* Ap = uws + (long)e * CAP_ * H_;
    const __half* Bp = w2te + (long)e * (D_ * H_);

    float acc[2][8][4];
#pragma unroll
    for (int mi = 0; mi < 2; mi++)
#pragma unroll
        for (int ni = 0; ni < 8; ni++)
#pragma unroll
            for (int r = 0; r < 4; r++) acc[mi][ni][r] = 0.f;

#define DN_ISSUE(st, k0)                                                              \
    do {                                                                              \
        uint32_t _as = sb + (st) * STAGE, _bs = _as + BOFF;                           \
        _Pragma("unroll")                                                             \
        for (int j = 0; j < 4; j++) {                                                 \
            int s = tid + 256 * j; int r = s >> 3, cu = s & 7;                        \
            CP_ASYNC16(_as + qoff(r, cu), Ap + (long)(bm + r) * H_ + (k0) + cu * 8);  \
            CP_ASYNC16(_bs + qoff(r, cu), Bp + (long)(bn + r) * H_ + (k0) + cu * 8);  \
        }                                                                             \
    } while (0)

    DN_ISSUE(0, 0); CP_COMMIT();
    DN_ISSUE(1, 64); CP_COMMIT();

    for (int ck = 0; ck < 4; ck++) {
        CP_WAIT1();
        __syncthreads();
        if (ck + 2 < 4) { int st = (ck + 2) % 3; DN_ISSUE(st, (ck + 2) << 6); }
        CP_COMMIT();
        uint32_t aBase = sb + (ck % 3) * STAGE, bBase = aBase + BOFF;
#pragma unroll
        for (int s = 0; s < 4; s++) {
            uint32_t af[2][4], bf[8][2];
#pragma unroll
            for (int mi = 0; mi < 2; mi++) {
                int m = wm + mi * 16 + (q2 & 1) * 8 + r7;
                LDSM_X4(af[mi][0], af[mi][1], af[mi][2], af[mi][3],
                        aBase + qoff(m, 2 * s + (q2 >> 1)));
            }
#pragma unroll
            for (int nj = 0; nj < 4; nj++) {
                int n = wn + nj * 16 + (q2 >> 1) * 8 + r7;
                LDSM_X4(bf[2 * nj][0], bf[2 * nj][1], bf[2 * nj + 1][0], bf[2 * nj + 1][1],
                        bBase + qoff(n, 2 * s + (q2 & 1)));
            }
#pragma unroll
            for (int mi = 0; mi < 2; mi++)
#pragma unroll
                for (int ni = 0; ni < 8; ni++)
                    mma16(acc[mi][ni], af[mi], bf[ni]);
        }
        __syncthreads();
    }
#undef DN_ISSUE

#pragma unroll
    for (int mi = 0; mi < 2; mi++) {
#pragma unroll
        for (int rh = 0; rh < 2; rh++) {
            int row = bm + wm + mi * 16 + g + rh * 8;
            __half* orow = outs + ((long)e * CAP_ + row) * D_;
#pragma unroll
            for (int ni = 0; ni < 8; ni++) {
                int n = bn + wn + ni * 8 + tq * 2;
                *(__half2*)(orow + n) =
                    __floats2half2_rn(acc[mi][ni][rh * 2], acc[mi][ni][rh * 2 + 1]);
            }
        }
    }
}

// ---------------- gate v2: smem-cached gate matrix, 128 tokens/block --------
__global__ void __launch_bounds__(256) gate_v2(
    const __half* __restrict__ h3, const float* __restrict__ gate_w,
    const int* __restrict__ task_id,
    float* __restrict__ probs, float* __restrict__ gate_dense) {
    extern __shared__ float gwT[];   // [16][1024]
    const float* gw = gate_w + (long)(*task_id) * (D_ * E_);
    int tid = threadIdx.x;
#pragma unroll 8
    for (int j = 0; j < 64; j++) {
        int idx = tid + 256 * j;
        int d = idx >> 4, e = idx & 15;
        gwT[e * 1024 + d] = gw[idx];
    }
    __syncthreads();
    int warp = tid >> 5, lane = tid & 31;
    for (int i = 0; i < 16; i++) {
        long tok = (long)blockIdx.x * 128 + i * 8 + warp;
        const __half* hrow = h3 + tok * D_;
        float acc[16];
#pragma unroll
        for (int e = 0; e < 16; e++) acc[e] = 0.f;
#pragma unroll
        for (int j = 0; j < 8; j++) {
            int d0 = (j * 32 + lane) * 4;
            __half2 a = *(const __half2*)(hrow + d0);
            __half2 b = *(const __half2*)(hrow + d0 + 2);
            float2 fa = __half22float2(a), fb = __half22float2(b);
#pragma unroll
            for (int e = 0; e < 16; e++) {
                float4 g4 = *(const float4*)&gwT[e * 1024 + d0];
                acc[e] += fa.x * g4.x + fa.y * g4.y + fb.x * g4.z + fb.y * g4.w;
            }
        }
#pragma unroll
        for (int e = 0; e < 16; e++) {
#pragma unroll
            for (int o = 16; o; o >>= 1)
                acc[e] += __shfl_xor_sync(0xffffffffu, acc[e], o);
        }
        if (lane == 0) {
            float mx = -1e30f;
#pragma unroll
            for (int e = 0; e < 16; e++) mx = fmaxf(mx, acc[e]);
            float sum = 0.f;
#pragma unroll
            for (int e = 0; e < 16; e++) { acc[e] = expf(acc[e] - mx); sum += acc[e]; }
            float inv = 1.f / sum;
            float p[16];
#pragma unroll
            for (int e = 0; e < 16; e++) { p[e] = acc[e] * inv; probs[tok * 16 + e] = p[e]; }
            bool used[16];
#pragma unroll
            for (int e = 0; e < 16; e++) used[e] = false;
            int tix[8]; float tvl[8]; float gsum = 0.f;
            for (int kk = 0; kk < 8; kk++) {
                float best = -1.f; int bi = 0;
                for (int e = 0; e < 16; e++)
                    if (!used[e] && p[e] > best) { best = p[e]; bi = e; }
                used[bi] = true; tix[kk] = bi; tvl[kk] = best; gsum += best;
            }
            float ginv = 1.f / (gsum + 1e-6f);
            float gdv[16];
#pragma unroll
            for (int e = 0; e < 16; e++) gdv[e] = 0.f;
            for (int kk = 0; kk < 8; kk++) gdv[tix[kk]] = tvl[kk] * ginv;
#pragma unroll
            for (int e = 0; e < 16; e++) gate_dense[tok * 16 + e] = gdv[e];
        }
    }
}

// ---------------- routing ----------------------------------------------------
__global__ void zero_cnt(int* cnt) {
    if (threadIdx.x < E_) cnt[threadIdx.x] = 0;
}
__global__ void route_k(const float* __restrict__ gd, int* __restrict__ cnt,
                        int* __restrict__ rowidx, int* __restrict__ pairpos) {
    int t = blockIdx.x * 128 + threadIdx.x;
    int k = 0;
#pragma unroll
    for (int e = 0; e < E_; e++) {
        float v = gd[(long)t * 16 + e];
        if (v > 0.f && k < 8) {
            int pos = atomicAdd(&cnt[e], 1);
            rowidx[(long)e * CAP_ + pos] = t;
            pairpos[(long)t * 8 + k] = e * CAP_ + pos;
            k++;
        }
    }
}

// ---------------- gather: out = x + sum_k outs[pp[k]] + gd @ b2 --------------
__global__ void gather_k(const float* __restrict__ x, const __half* __restrict__ outs,
                         const int* __restrict__ pairpos, const float* __restrict__ gd,
                         const float* __restrict__ b2, float* __restrict__ out) {
    long t = blockIdx.x;
    __shared__ int pp[8];
    __shared__ float gdv[16];
    int tid = threadIdx.x;
    if (tid < 8) pp[tid] = pairpos[t * 8 + tid];
    if (tid < 16) gdv[tid] = gd[t * 16 + tid];
    __syncthreads();
    int d = tid * 4;
    float4 a = *(const float4*)(x + t * D_ + d);
#pragma unroll
    for (int k = 0; k < 8; k++) {
        const __half2* o2 = (const __half2*)(outs + (long)pp[k] * D_ + d);
        float2 f0 = __half22float2(o2[0]), f1 = __half22float2(o2[1]);
        a.x += f0.x; a.y += f0.y; a.z += f1.x; a.w += f1.y;
    }
#pragma unroll
    for (int e = 0; e < 16; e++) {
        float4 bv = *(const float4*)(b2 + (long)e * D_ + d);
        float gv = gdv[e];
        a.x += gv * bv.x; a.y += gv * bv.y; a.z += gv * bv.z; a.w += gv * bv.w;
    }
    *(float4*)(out + t * D_ + d) = a;
}

// ---------------- aux loss: 64 deterministic partials + final ----------------
__global__ void aux_part(const float* __restrict__ probs, float* __restrict__ part) {
    int b = blockIdx.x, tid = threadIdx.x;
    const float* p = probs + ((long)b * 256 + tid) * 16;
    float v[16];
#pragma unroll
    for (int e = 0; e < 16; e++) v[e] = p[e];
    __shared__ float red[256][17];
#pragma unroll
    for (int e = 0; e < 16; e++) red[tid][e] = v[e];
    __syncthreads();
    for (int s = 128; s; s >>= 1) {
        if (tid < s) {
#pragma unroll
            for (int e = 0; e < 16; e++) red[tid][e] += red[tid + s][e];
        }
        __syncthreads();
    }
    if (tid == 0) {
#pragma unroll
        for (int e = 0; e < 16; e++) part[b * 16 + e] = red[0][e];
    }
}
__global__ void aux_fin(const float* __restrict__ part, float* __restrict__ outv) {
    if (threadIdx.x == 0) {
        float aux = 0.f;
        for (int e = 0; e < 16; e++) {
            float s = 0.f;
            for (int b = 0; b < 64; b++) s += part[b * 16 + e];
            float mp = s * (1.f / T_);
            aux += mp * logf(mp + 1e-6f);
        }
        outv[0] = 5e-4f * aux;
    }
}

// ---------------- launch -----------------------------------------------------
extern "C" void kernel_launch(void* const* d_in, const int* in_sizes, int n_in,
                              void* d_out, int out_size) {
    const float* tgt        = (const float*)d_in[0];
    const float* ln1_g      = (const float*)d_in[2];
    const float* ln1_b      = (const float*)d_in[3];
    const float* ln3_g      = (const float*)d_in[4];
    const float* ln3_b      = (const float*)d_in[5];
    const float* in_proj_w  = (const float*)d_in[6];
    const float* in_proj_b  = (const float*)d_in[7];
    const float* out_proj_w = (const float*)d_in[8];
    const float* out_proj_b = (const float*)d_in[9];
    const float* gate_w     = (const float*)d_in[10];
    const float* w1         = (const float*)d_in[11];
    const float* b1         = (const float*)d_in[12];
    const float* w2         = (const float*)d_in[13];
    const float* b2         = (const float*)d_in[14];
    const int*   task_id    = (const int*)d_in[15];

    float* out       = (float*)d_out;
    float* out_x     = out;
    float* out_aux   = out + (size_t)T_ * D_;
    float* out_probs = out_aux + 1;

    __half *h16, *qkv16, *vt16, *ctx16, *wi16, *wo16, *w1t16, *w2te16, *uws, *outs;
    float *x, *gd, *auxp;
    int *cnt, *rowidx, *pairpos;
    cudaGetSymbolAddress((void**)&h16,    g_h16);
    cudaGetSymbolAddress((void**)&qkv16,  g_qkv16);
    cudaGetSymbolAddress((void**)&vt16,   g_vt16);
    cudaGetSymbolAddress((void**)&ctx16,  g_ctx16);
    cudaGetSymbolAddress((void**)&x,      g_x);
    cudaGetSymbolAddress((void**)&gd,     g_gate);
    cudaGetSymbolAddress((void**)&wi16,   g_wi16);
    cudaGetSymbolAddress((void**)&wo16,   g_wo16);
    cudaGetSymbolAddress((void**)&w1t16,  g_w1t16);
    cudaGetSymbolAddress((void**)&w2te16, g_w2te16);
    cudaGetSymbolAddress((void**)&uws,    g_uws);
    cudaGetSymbolAddress((void**)&outs,   g_outs);
    cudaGetSymbolAddress((void**)&cnt,    g_cnt);
    cudaGetSymbolAddress((void**)&rowidx, g_rowidx);
    cudaGetSymbolAddress((void**)&pairpos,g_pairpos);
    cudaGetSymbolAddress((void**)&auxp,   g_auxp);

    const int GSM = 3 * 32768;      // 98304
    const int GATESM = 65536;
    cudaFuncSetAttribute(gemm_h<true, false, true >, cudaFuncAttributeMaxDynamicSharedMemorySize, GSM);
    cudaFuncSetAttribute(gemm_h<true, true,  false>, cudaFuncAttributeMaxDynamicSharedMemorySize, GSM);
    cudaFuncSetAttribute(gemm_up, cudaFuncAttributeMaxDynamicSharedMemorySize, GSM);
    cudaFuncSetAttribute(gemm_dn, cudaFuncAttributeMaxDynamicSharedMemorySize, GSM);
    cudaFuncSetAttribute(gate_v2, cudaFuncAttributeMaxDynamicSharedMemorySize, GATESM);

    // 0. weight preprocessing
    conv_f2h<<<(unsigned)(3L * D_ * D_ / 1024), 256>>>(in_proj_w, wi16, 3L * D_ * D_);
    conv_f2h<<<(unsigned)(1L * D_ * D_ / 1024), 256>>>(out_proj_w, wo16, 1L * D_ * D_);
    transpose_h<float><<<dim3(8, 32, E_), 256>>>(
        w1, w1t16, D_, H_, H_, (long)D_ * H_, 0, (long)H_ * D_, 0, 1);
    transpose_h<float><<<dim3(32, 8, E_), 256>>>(
        w2, w2te16, H_, D_, D_, (long)H_ * D_, 0, (long)D_ * H_, 0, 1);

    // 1. h = LN1(tgt)
    ln_kernel<<<T_, 256>>>(tgt, ln1_g, ln1_b, h16);

    // 2. qkv = h @ in_proj_w^T + b (half out)
    gemm_h<true, false, true><<<dim3(24, 128), 256, GSM>>>(
        h16, wi16, qkv16, in_proj_b, nullptr, D_, D_, D_, 3 * D_);

    // 3. Vt = V^T per (b,h)
    transpose_h<__half><<<dim3(2, 16, B_ * NH_), 256>>>(
        qkv16 + 2 * D_, vt16, S_, DH_, 3 * D_,
        (long)S_ * 3 * D_, DH_, (long)NH_ * DH_ * S_, (long)DH_ * S_, NH_);

    // 4. fused flash attention -> ctx16
    flash_k<<<dim3(4, B_ * NH_), 256>>>(qkv16, vt16, ctx16);

    // 5. x = tgt + ctx @ out_proj_w^T + b (fp32 out)
    gemm_h<true, true, false><<<dim3(8, 128), 256, GSM>>>(
        ctx16, wo16, x, out_proj_b, tgt, D_, D_, D_, D_);

    // 6. h3 = LN3(x)
    ln_kernel<<<T_, 256>>>(x, ln3_g, ln3_b, h16);

    // 7. gate / aux
    gate_v2<<<T_ / 128, 256, GATESM>>>(h16, gate_w, task_id, out_probs, gd);
    aux_part<<<64, 256>>>(out_probs, auxp);
    aux_fin<<<1, 32>>>(auxp, out_aux);

    // 8. routing
    zero_cnt<<<1, 32>>>(cnt);
    route_k<<<T_ / 128, 128>>>(gd, cnt, rowidx, pairpos);

    // 9. sparse MoE up
    gemm_up<<<dim3(2, 128, E_), 256, GSM>>>(h16, w1t16, uws, b1, gd, rowidx, cnt);

    // 10. sparse MoE down
    gemm_dn<<<dim3(8, 128, E_), 256, GSM>>>(uws, w2te16, outs, cnt);

    // 11. gather: out = x + sum_k outs + gd @ b2
    gather_k<<<T_, 256>>>(x, outs, pairpos, gd, b2, out_x);

    (void)in_sizes; (void)n_in; (void)out_size;
}